// round 11
// baseline (speedup 1.0000x reference)
#include <cuda_runtime.h>
#include <cuda_bf16.h>
#include <cstdint>

#define B_   256
#define LD_  64
#define NO_  10240
#define LO_  32
#define NM_  81920
#define LM_  16
#define EO_  81920
#define EM_  327680
#define E_   128
#define HID_ 256
#define H_   8
#define Dh_  16
#define NCHUNK 4
#define CHROWS (NM_ / NCHUNK)   // 20480

// ---------------- scratch ----------------
__device__ float g_hn[B_ * E_];
__device__ float g_stmt[NO_ * E_];
__device__ float g_q[NM_ * E_];
__device__ float g_k[NM_ * E_];
__device__ float g_v[NM_ * E_];
__device__ float g_hidden[NM_ * E_];    // skip (QKVS output); read-only in fused attn
__device__ float g_dinv[NO_];
__device__ float g_xw1[NO_ * HID_];
__device__ float g_xw2[NO_ * E_];
__device__ float g_fs[NO_ * E_];

// bf16 split operand buffers
__device__ __align__(16) __nv_bfloat16 g_mini_hi[NM_ * E_], g_mini_lo[NM_ * E_];
__device__ __align__(16) __nv_bfloat16 g_mfn_hi[NO_ * E_],  g_mfn_lo[NO_ * E_];
__device__ __align__(16) __nv_bfloat16 g_gc1_hi[NO_ * HID_], g_gc1_lo[NO_ * HID_];
__device__ __align__(16) __nv_bfloat16 g_wtq_hi[E_ * E_], g_wtq_lo[E_ * E_];
__device__ __align__(16) __nv_bfloat16 g_wtk_hi[E_ * E_], g_wtk_lo[E_ * E_];
__device__ __align__(16) __nv_bfloat16 g_wtv_hi[E_ * E_], g_wtv_lo[E_ * E_];
__device__ __align__(16) __nv_bfloat16 g_wts_hi[E_ * E_], g_wts_lo[E_ * E_];
__device__ __align__(16) __nv_bfloat16 g_w2t_hi[HID_ * E_], g_w2t_lo[HID_ * E_];
__device__ __align__(16) __nv_bfloat16 g_w3t_hi[E_ * HID_], g_w3t_lo[E_ * HID_];

__device__ int g_deg_m[NM_];
__device__ int g_off_m[NM_ + 1];
__device__ int g_pos_m[NM_];
__device__ int g_csr_m[EM_];
__device__ int g_bsum_m[256];
__device__ int g_deg_o[NO_];
__device__ int g_off_o[NO_ + 1];
__device__ int g_pos_o[NO_];
__device__ int g_csr_o[EO_];
__device__ int g_bsum_o[256];

// ---------------- helpers ----------------
__device__ __forceinline__ uint32_t smem_u32(const void* p) {
    uint32_t a;
    asm("{ .reg .u64 t; cvta.to.shared.u64 t, %1; cvt.u32.u64 %0, t; }" : "=r"(a) : "l"(p));
    return a;
}
__device__ __forceinline__ void cp16(uint32_t dst, const void* src) {
    asm volatile("cp.async.cg.shared.global [%0], [%1], 16;" :: "r"(dst), "l"(src));
}
__device__ __forceinline__ void cp_commit() {
    asm volatile("cp.async.commit_group;" ::: "memory");
}
template <int N>
__device__ __forceinline__ void cp_wait() {
    asm volatile("cp.async.wait_group %0;" :: "n"(N) : "memory");
}
__device__ __forceinline__ void mma_bf16(float* d, const uint32_t* a, const uint32_t* b) {
    asm volatile(
        "mma.sync.aligned.m16n8k16.row.col.f32.bf16.bf16.f32 "
        "{%0,%1,%2,%3}, {%4,%5,%6,%7}, {%8,%9}, {%0,%1,%2,%3};"
        : "+f"(d[0]), "+f"(d[1]), "+f"(d[2]), "+f"(d[3])
        : "r"(a[0]), "r"(a[1]), "r"(a[2]), "r"(a[3]), "r"(b[0]), "r"(b[1]));
}

__device__ __forceinline__ void split_store4(__nv_bfloat16* hi, __nv_bfloat16* lo,
                                             size_t base, float4 v) {
    __nv_bfloat162 h0 = __floats2bfloat162_rn(v.x, v.y);
    __nv_bfloat162 h1 = __floats2bfloat162_rn(v.z, v.w);
    float rx = __bfloat162float(h0.x), ry = __bfloat162float(h0.y);
    float rz = __bfloat162float(h1.x), rw = __bfloat162float(h1.y);
    __nv_bfloat162 l0 = __floats2bfloat162_rn(v.x - rx, v.y - ry);
    __nv_bfloat162 l1 = __floats2bfloat162_rn(v.z - rz, v.w - rw);
    uint2 hp = {*(uint32_t*)&h0, *(uint32_t*)&h1};
    uint2 lp = {*(uint32_t*)&l0, *(uint32_t*)&l1};
    *(uint2*)(hi + base) = hp;
    *(uint2*)(lo + base) = lp;
}

// ---------------- weight transpose + split ----------------
__global__ void wsplit_kernel(const float* __restrict__ W, __nv_bfloat16* __restrict__ hi,
                              __nv_bfloat16* __restrict__ lo, int K, int N) {
    int i = blockIdx.x * blockDim.x + threadIdx.x;
    if (i >= K * N) return;
    int n = i / K, k = i - n * K;
    float v = W[(size_t)k * N + n];
    __nv_bfloat16 h = __float2bfloat16(v);
    hi[i] = h;
    lo[i] = __float2bfloat16(v - __bfloat162float(h));
}

__global__ void wsplit4_kernel(const float* __restrict__ Wq, const float* __restrict__ Wk,
                               const float* __restrict__ Wv, const float* __restrict__ Ws) {
    const float* W; __nv_bfloat16 *hi, *lo;
    switch (blockIdx.y) {
        case 0: W = Wq; hi = g_wtq_hi; lo = g_wtq_lo; break;
        case 1: W = Wk; hi = g_wtk_hi; lo = g_wtk_lo; break;
        case 2: W = Wv; hi = g_wtv_hi; lo = g_wtv_lo; break;
        default: W = Ws; hi = g_wts_hi; lo = g_wts_lo; break;
    }
    int i = blockIdx.x * blockDim.x + threadIdx.x;
    if (i >= E_ * E_) return;
    int n = i / E_, k = i - n * E_;
    float v = W[(size_t)k * E_ + n];
    __nv_bfloat16 h = __float2bfloat16(v);
    hi[i] = h;
    lo[i] = __float2bfloat16(v - __bfloat162float(h));
}

// ---------------- bf16x3 mma.sync GEMM, cp.async double-buffered -----------------
// (round-8 scalar-LDS inner loop — measured-best configuration)
#define GSTR 40
#define GST_ELEMS (128 * GSTR)
#define STAGE_ELEMS (4 * GST_ELEMS)
#define GEMM_SMEM (2 * STAGE_ELEMS * 2)

__device__ void bf16_gemm_body(const __nv_bfloat16* __restrict__ Ahi,
                               const __nv_bfloat16* __restrict__ Alo,
                               const __nv_bfloat16* __restrict__ Bhi,
                               const __nv_bfloat16* __restrict__ Blo,
                               const float* __restrict__ bias, float* __restrict__ C,
                               int row0, int K, int Ntot, int col0) {
    extern __shared__ __align__(16) __nv_bfloat16 smb[];
    uint32_t sbase = smem_u32(smb);
    int tid = threadIdx.x;
    int wid = tid >> 5, lane = tid & 31;
    int wm = wid >> 2, wn = wid & 3, gr = lane >> 2, tg = lane & 3;

    float acc[4][4][4] = {};
    int nch = K >> 5;

    auto issue = [&](int c) {
        int kt = c << 5;
        uint32_t base = sbase + (uint32_t)(c & 1) * (STAGE_ELEMS * 2);
#pragma unroll
        for (int it = 0; it < 2; it++) {
            int idx = it * 256 + tid;
            int row = idx >> 2, g8 = (idx & 3) * 8;
            size_t goff = (size_t)(row0 + row) * K + kt + g8;
            uint32_t d = base + (uint32_t)(row * GSTR + g8) * 2;
            cp16(d, Ahi + goff);
            cp16(d + GST_ELEMS * 2, Alo + goff);
        }
#pragma unroll
        for (int it = 0; it < 2; it++) {
            int idx = it * 256 + tid;
            int n = idx >> 2, g8 = (idx & 3) * 8;
            size_t goff = (size_t)(col0 + n) * K + kt + g8;
            uint32_t d = base + (uint32_t)(2 * GST_ELEMS + n * GSTR + g8) * 2;
            cp16(d, Bhi + goff);
            cp16(d + GST_ELEMS * 2, Blo + goff);
        }
        cp_commit();
    };

    issue(0);
    for (int c = 0; c < nch; c++) {
        if (c + 1 < nch) { issue(c + 1); cp_wait<1>(); }
        else             { cp_wait<0>(); }
        __syncthreads();

        const uint32_t* S = reinterpret_cast<const uint32_t*>(smb) + (c & 1) * (STAGE_ELEMS / 2);
        const uint32_t* A32h = S;
        const uint32_t* A32l = S + GST_ELEMS / 2;
        const uint32_t* B32h = S + GST_ELEMS;
        const uint32_t* B32l = S + GST_ELEMS + GST_ELEMS / 2;

#pragma unroll
        for (int ks = 0; ks < 2; ks++) {
            int kb = ks * 8;
            uint32_t ah[4][4], al[4][4], bh[4][2], bl[4][2];
#pragma unroll
            for (int mt = 0; mt < 4; mt++) {
                int r = wm * 64 + mt * 16 + gr;
                int o = r * (GSTR / 2) + kb + tg;
                ah[mt][0] = A32h[o];
                ah[mt][1] = A32h[o + 8 * (GSTR / 2)];
                ah[mt][2] = A32h[o + 4];
                ah[mt][3] = A32h[o + 8 * (GSTR / 2) + 4];
                al[mt][0] = A32l[o];
                al[mt][1] = A32l[o + 8 * (GSTR / 2)];
                al[mt][2] = A32l[o + 4];
                al[mt][3] = A32l[o + 8 * (GSTR / 2) + 4];
            }
#pragma unroll
            for (int nt = 0; nt < 4; nt++) {
                int n = wn * 32 + nt * 8 + gr;
                int o = n * (GSTR / 2) + kb + tg;
                bh[nt][0] = B32h[o];
                bh[nt][1] = B32h[o + 4];
                bl[nt][0] = B32l[o];
                bl[nt][1] = B32l[o + 4];
            }
#pragma unroll
            for (int mt = 0; mt < 4; mt++)
#pragma unroll
                for (int nt = 0; nt < 4; nt++) {
                    mma_bf16(acc[mt][nt], ah[mt], bh[nt]);
                    mma_bf16(acc[mt][nt], ah[mt], bl[nt]);
                    mma_bf16(acc[mt][nt], al[mt], bh[nt]);
                }
        }
        __syncthreads();
    }

#pragma unroll
    for (int mt = 0; mt < 4; mt++) {
#pragma unroll
        for (int nt = 0; nt < 4; nt++) {
            int row = row0 + wm * 64 + mt * 16 + gr;
            int col = col0 + wn * 32 + nt * 8 + 2 * tg;
            float b0 = 0.f, b1 = 0.f;
            if (bias) { b0 = bias[col]; b1 = bias[col + 1]; }
            float2 o0 = {acc[mt][nt][0] + b0, acc[mt][nt][1] + b1};
            float2 o1 = {acc[mt][nt][2] + b0, acc[mt][nt][3] + b1};
            *(float2*)&C[(size_t)row * Ntot + col] = o0;
            *(float2*)&C[(size_t)(row + 8) * Ntot + col] = o1;
        }
    }
}

__global__ __launch_bounds__(256) void bf16_gemm_qkvs(
    const __nv_bfloat16* __restrict__ Ahi, const __nv_bfloat16* __restrict__ Alo,
    const float* __restrict__ bq, float* __restrict__ Cq,
    const float* __restrict__ bk, float* __restrict__ Ck,
    const float* __restrict__ bv, float* __restrict__ Cv,
    const float* __restrict__ bs, float* __restrict__ Cs, int rowbase) {
    const __nv_bfloat16 *Bh, *Bl; const float* bias; float* C;
    switch (blockIdx.y) {
        case 0: Bh = g_wtq_hi; Bl = g_wtq_lo; bias = bq; C = Cq; break;
        case 1: Bh = g_wtk_hi; Bl = g_wtk_lo; bias = bk; C = Ck; break;
        case 2: Bh = g_wtv_hi; Bl = g_wtv_lo; bias = bv; C = Cv; break;
        default: Bh = g_wts_hi; Bl = g_wts_lo; bias = bs; C = Cs; break;
    }
    bf16_gemm_body(Ahi, Alo, Bh, Bl, bias, C, rowbase + blockIdx.x * 128, E_, E_, 0);
}

__global__ __launch_bounds__(256) void bf16_gemm(
    const __nv_bfloat16* __restrict__ Ahi, const __nv_bfloat16* __restrict__ Alo,
    const __nv_bfloat16* __restrict__ Bhi, const __nv_bfloat16* __restrict__ Blo,
    float* __restrict__ C, int K, int Ntot) {
    bf16_gemm_body(Ahi, Alo, Bhi, Blo, nullptr, C, blockIdx.x * 128, K, Ntot, blockIdx.y * 128);
}

// ---------------- CSR build ----------------
__global__ void zero_deg_kernel() {
    int i = blockIdx.x * blockDim.x + threadIdx.x;
    if (i < NM_) g_deg_m[i] = 0;
    if (i < NO_) g_deg_o[i] = 0;
}
__global__ void count_kernel(const int* __restrict__ dst, int* __restrict__ deg, int ne) {
    int e = blockIdx.x * blockDim.x + threadIdx.x;
    if (e < ne) atomicAdd(&deg[dst[e]], 1);
}
__global__ void scan_local_kernel(const int* __restrict__ deg, int* __restrict__ off,
                                  int* __restrict__ bsum) {
    __shared__ int ws[8];
    int tid = threadIdx.x;
    int base = blockIdx.x * 1024 + tid * 4;
    int4 d = *(const int4*)&deg[base];
    int s = d.x + d.y + d.z + d.w;
    int lane = tid & 31, wid = tid >> 5;
    int v = s;
#pragma unroll
    for (int o = 1; o < 32; o <<= 1) {
        int t = __shfl_up_sync(0xffffffffu, v, o);
        if (lane >= o) v += t;
    }
    if (lane == 31) ws[wid] = v;
    __syncthreads();
    if (tid == 0) {
        int run = 0;
#pragma unroll
        for (int w = 0; w < 8; w++) { int t = ws[w]; ws[w] = run; run += t; }
    }
    __syncthreads();
    int excl = v - s + ws[wid];
    int4 o4;
    o4.x = excl;
    o4.y = excl + d.x;
    o4.z = o4.y + d.y;
    o4.w = o4.z + d.z;
    *(int4*)&off[base] = o4;
    if (tid == 255) bsum[blockIdx.x] = excl + s;
}
__global__ void scan_bsums_kernel(int* __restrict__ bsum, int nb, int* __restrict__ off, int n) {
    __shared__ int sh[128];
    int tid = threadIdx.x;
    int val = (tid < nb) ? bsum[tid] : 0;
    sh[tid] = val;
    __syncthreads();
    int acc = val;
    for (int o = 1; o < 128; o <<= 1) {
        int t = (tid >= o) ? sh[tid - o] : 0;
        __syncthreads();
        acc += t;
        sh[tid] = acc;
        __syncthreads();
    }
    if (tid < nb) bsum[tid] = acc - val;
    if (tid == 127) off[n] = sh[127];
}
__global__ void scan_add_kernel(int* __restrict__ off, int* __restrict__ pos,
                                const int* __restrict__ bsum, int n) {
    int i = blockIdx.x * blockDim.x + threadIdx.x;
    if (i < n) {
        int v = off[i] + bsum[i >> 10];
        off[i] = v;
        pos[i] = v;
    }
}
__global__ void scatter_kernel(const int* __restrict__ src, const int* __restrict__ dst,
                               int* __restrict__ pos, int* __restrict__ csr, int ne) {
    int e = blockIdx.x * blockDim.x + threadIdx.x;
    if (e < ne) {
        int t = dst[e];
        int slot = atomicAdd(&pos[t], 1);
        csr[slot] = src[e];
    }
}
__global__ void dinv_kernel() {
    int i = blockIdx.x * blockDim.x + threadIdx.x;
    if (i < NO_) g_dinv[i] = rsqrtf((float)(g_deg_o[i] + 1));
}

// ---------------- masked mean (fp32 out) ----------------
__global__ void masked_mean4_kernel(const int* __restrict__ tok,
                                    const float* __restrict__ table,
                                    float* __restrict__ out, int L) {
    __shared__ int ts[4][64];
    int warp = threadIdx.x >> 5, lane = threadIdx.x & 31;
    int n = blockIdx.x * 4 + warp;
    for (int j = lane; j < L; j += 32) ts[warp][j] = tok[n * L + j];
    __syncwarp();
    const float4* t4 = (const float4*)table;
    float4 acc = {0.f, 0.f, 0.f, 0.f};
    int cnt = 0;
    for (int j = 0; j < L; j++) {
        int t = ts[warp][j];
        if (t != 0) {
            float4 e = t4[(size_t)t * 32 + lane];
            acc.x += e.x; acc.y += e.y; acc.z += e.z; acc.w += e.w;
            cnt++;
        }
    }
    float inv = 1.f / (float)(cnt > 1 ? cnt : 1);
    float4 o = {acc.x * inv, acc.y * inv, acc.z * inv, acc.w * inv};
    ((float4*)out)[(size_t)n * 32 + lane] = o;
}

// ---------------- masked mean (bf16 hi/lo out, with node offset) ------------------
__global__ void masked_mean4_bf16_kernel(const int* __restrict__ tok,
                                         const float* __restrict__ table,
                                         __nv_bfloat16* __restrict__ hi,
                                         __nv_bfloat16* __restrict__ lo, int L, int n0) {
    __shared__ int ts[4][64];
    int warp = threadIdx.x >> 5, lane = threadIdx.x & 31;
    int n = n0 + blockIdx.x * 4 + warp;
    for (int j = lane; j < L; j += 32) ts[warp][j] = tok[n * L + j];
    __syncwarp();
    const float4* t4 = (const float4*)table;
    float4 acc = {0.f, 0.f, 0.f, 0.f};
    int cnt = 0;
    for (int j = 0; j < L; j++) {
        int t = ts[warp][j];
        if (t != 0) {
            float4 e = t4[(size_t)t * 32 + lane];
            acc.x += e.x; acc.y += e.y; acc.z += e.z; acc.w += e.w;
            cnt++;
        }
    }
    float inv = 1.f / (float)(cnt > 1 ? cnt : 1);
    float4 o = {acc.x * inv, acc.y * inv, acc.z * inv, acc.w * inv};
    split_store4(hi, lo, ((size_t)n * 32 + lane) * 4, o);
}

// ---------------- fused attn + global-attention-8 + (.,+stmt)*0.5 -----------------
__global__ __launch_bounds__(256) void attn_gattn8_kernel(const float* __restrict__ Wg,
                                                          const float* __restrict__ bg) {
    __shared__ float sh_rows[8][132];
    __shared__ float sh_gate[8];
    int tid = threadIdx.x;
    int warp = tid >> 5, lane = tid & 31;
    int n = blockIdx.x;
    int t = n * 8 + warp;

    const float4* q4 = (const float4*)g_q;
    const float4* k4 = (const float4*)g_k;
    const float4* v4 = (const float4*)g_v;
    float4 qv = q4[(size_t)t * 32 + lane];
    float m = -1e30f, ss = 0.f;
    float4 acc = {0.f, 0.f, 0.f, 0.f};
    int beg = g_off_m[t], end = g_off_m[t + 1];
    for (int i = beg; i < end; i++) {
        int s = g_csr_m[i];
        float4 kv = k4[(size_t)s * 32 + lane];
        float p = qv.x * kv.x + qv.y * kv.y + qv.z * kv.z + qv.w * kv.w;
        p += __shfl_xor_sync(0xffffffffu, p, 1);
        p += __shfl_xor_sync(0xffffffffu, p, 2);
        float sc = p * 0.25f;
        float mn = fmaxf(m, sc);
        float scale = __expf(m - mn);
        float w = __expf(sc - mn);
        float4 vv = v4[(size_t)s * 32 + lane];
        ss = ss * scale + w;
        acc.x = acc.x * scale + w * vv.x;
        acc.y = acc.y * scale + w * vv.y;
        acc.z = acc.z * scale + w * vv.z;
        acc.w = acc.w * scale + w * vv.w;
        m = mn;
    }
    float inv = 1.f / (ss + 1e-16f);
    float4 h = ((const float4*)g_hidden)[(size_t)t * 32 + lane];
    h.x += acc.x * inv; h.y += acc.y * inv;
    h.z += acc.z * inv; h.w += acc.w * inv;

    float4 wg = ((const float4*)Wg)[lane];
    float p = h.x * wg.x + h.y * wg.y + h.z * wg.z + h.w * wg.w;
#pragma unroll
    for (int off = 16; off; off >>= 1) p += __shfl_xor_sync(0xffffffffu, p, off);

    *(float4*)&sh_rows[warp][lane * 4] = h;
    if (lane == 0) sh_gate[warp] = p + bg[0];
    __syncthreads();

    if (tid < E_) {
        float gm = sh_gate[0];
#pragma unroll
        for (int j = 1; j < 8; j++) gm = fmaxf(gm, sh_gate[j]);
        float e[8], s = 0.f;
#pragma unroll
        for (int j = 0; j < 8; j++) { e[j] = __expf(sh_gate[j] - gm); s += e[j]; }
        float is = 1.f / (s + 1e-16f);
        float o = 0.f;
#pragma unroll
        for (int j = 0; j < 8; j++) o += e[j] * is * sh_rows[j][tid];
        float res = (o + g_stmt[(size_t)n * E_ + tid]) * 0.5f;
        __nv_bfloat16 hb = __float2bfloat16(res);
        g_mfn_hi[(size_t)n * E_ + tid] = hb;
        g_mfn_lo[(size_t)n * E_ + tid] = __float2bfloat16(res - __bfloat162float(hb));
    }
}

// ---------------- GCN gather -> relu + bf16 split ----------------
__global__ void gcn_gather_split_kernel(const float* __restrict__ xw,
                                        const float* __restrict__ bias,
                                        __nv_bfloat16* __restrict__ hi,
                                        __nv_bfloat16* __restrict__ lo, int Mv4) {
    int warp = threadIdx.x >> 5, lane = threadIdx.x & 31;
    int t = blockIdx.x * 8 + warp;
    float di = g_dinv[t];
    int beg = g_off_o[t], end = g_off_o[t + 1];
    const float4* x4 = (const float4*)xw;
    for (int c = lane; c < Mv4; c += 32) {
        float4 a = x4[(size_t)t * Mv4 + c];
        float4 bv = ((const float4*)bias)[c];
        float d2 = di * di;
        float4 acc = {a.x * d2 + bv.x, a.y * d2 + bv.y, a.z * d2 + bv.z, a.w * d2 + bv.w};
        for (int i = beg; i < end; i++) {
            int s = g_csr_o[i];
            float nr = g_dinv[s] * di;
            float4 x = x4[(size_t)s * Mv4 + c];
            acc.x += nr * x.x; acc.y += nr * x.y;
            acc.z += nr * x.z; acc.w += nr * x.w;
        }
        acc.x = fmaxf(acc.x, 0.f); acc.y = fmaxf(acc.y, 0.f);
        acc.z = fmaxf(acc.z, 0.f); acc.w = fmaxf(acc.w, 0.f);
        split_store4(hi, lo, ((size_t)t * Mv4 + c) * 4, acc);
    }
}

// ---------------- GCN gather -> fp32 ----------------
__global__ void gcn_gather_kernel(const float* __restrict__ xw, const float* __restrict__ bias,
                                  float* __restrict__ out, int Mv4) {
    int warp = threadIdx.x >> 5, lane = threadIdx.x & 31;
    int t = blockIdx.x * 8 + warp;
    float di = g_dinv[t];
    int beg = g_off_o[t], end = g_off_o[t + 1];
    const float4* x4 = (const float4*)xw;
    for (int c = lane; c < Mv4; c += 32) {
        float4 a = x4[(size_t)t * Mv4 + c];
        float4 bv = ((const float4*)bias)[c];
        float d2 = di * di;
        float4 acc = {a.x * d2 + bv.x, a.y * d2 + bv.y, a.z * d2 + bv.z, a.w * d2 + bv.w};
        for (int i = beg; i < end; i++) {
            int s = g_csr_o[i];
            float nr = g_dinv[s] * di;
            float4 x = x4[(size_t)s * Mv4 + c];
            acc.x += nr * x.x; acc.y += nr * x.y;
            acc.z += nr * x.z; acc.w += nr * x.w;
        }
        ((float4*)out)[(size_t)t * Mv4 + c] = acc;
    }
}

// ---------------- fused global attention (segments of 40) + cosine ----------------
__global__ void gattn40_cos_kernel(const float* __restrict__ Wg, const float* __restrict__ bg,
                                   float* __restrict__ out) {
    __shared__ float gate[40];
    __shared__ float alpha[40];
    __shared__ float ms[2];
    __shared__ float red[3][4];
    int b = blockIdx.x;
    int tid = threadIdx.x;  // 128
    int warp = tid >> 5, lane = tid & 31;
    float4 wg = ((const float4*)Wg)[lane];
    for (int j = warp; j < 40; j += 4) {
        float4 xv = ((const float4*)g_fs)[(size_t)(b * 40 + j) * 32 + lane];
        float p = xv.x * wg.x + xv.y * wg.y + xv.z * wg.z + xv.w * wg.w;
#pragma unroll
        for (int off = 16; off; off >>= 1) p += __shfl_xor_sync(0xffffffffu, p, off);
        if (lane == 0) gate[j] = p + bg[0];
    }
    __syncthreads();
    if (tid == 0) {
        float m = gate[0];
        for (int j = 1; j < 40; j++) m = fmaxf(m, gate[j]);
        float s = 0.f;
        for (int j = 0; j < 40; j++) s += __expf(gate[j] - m);
        ms[0] = m; ms[1] = s;
    }
    __syncthreads();
    if (tid < 40) alpha[tid] = __expf(gate[tid] - ms[0]) / (ms[1] + 1e-16f);
    __syncthreads();
    float f = 0.f;
    for (int j = 0; j < 40; j++)
        f += alpha[j] * g_fs[(size_t)(b * 40 + j) * E_ + tid];
    float hh = g_hn[(size_t)b * E_ + tid];
    float dt = f * hh, na = f * f, nb = hh * hh;
#pragma unroll
    for (int off = 16; off; off >>= 1) {
        dt += __shfl_xor_sync(0xffffffffu, dt, off);
        na += __shfl_xor_sync(0xffffffffu, na, off);
        nb += __shfl_xor_sync(0xffffffffu, nb, off);
    }
    if (lane == 0) { red[0][warp] = dt; red[1][warp] = na; red[2][warp] = nb; }
    __syncthreads();
    if (tid == 0) {
        float d = red[0][0] + red[0][1] + red[0][2] + red[0][3];
        float a = red[1][0] + red[1][1] + red[1][2] + red[1][3];
        float c = red[2][0] + red[2][1] + red[2][2] + red[2][3];
        out[b] = d / (fmaxf(sqrtf(a), 1e-8f) * fmaxf(sqrtf(c), 1e-8f));
    }
}

// ---------------- launch (stream DAG inside graph capture) ----------------
extern "C" void kernel_launch(void* const* d_in, const int* in_sizes, int n_in,
                              void* d_out, int out_size) {
    const int* desc_tokens = (const int*)d_in[0];
    const int* x_tokens    = (const int*)d_in[1];
    const int* mini_tokens = (const int*)d_in[2];
    const int* src         = (const int*)d_in[3];
    const int* dst         = (const int*)d_in[4];
    const int* mini_src    = (const int*)d_in[5];
    const int* mini_dst    = (const int*)d_in[6];
    const float* desc_table  = (const float*)d_in[9];
    const float* code_table  = (const float*)d_in[10];
    const float* code_table2 = (const float*)d_in[11];
    const float* Wq = (const float*)d_in[12]; const float* bq = (const float*)d_in[13];
    const float* Wk = (const float*)d_in[14]; const float* bk = (const float*)d_in[15];
    const float* Wv = (const float*)d_in[16]; const float* bv = (const float*)d_in[17];
    const float* Wskip = (const float*)d_in[18]; const float* bskip = (const float*)d_in[19];
    const float* W2 = (const float*)d_in[20]; const float* b2 = (const float*)d_in[21];
    const float* W3 = (const float*)d_in[22]; const float* b3 = (const float*)d_in[23];
    const float* Wg = (const float*)d_in[24]; const float* bg = (const float*)d_in[25];
    float* out = (float*)d_out;

    float *p_q, *p_k, *p_v, *p_hidden, *p_hn, *p_stmt, *p_xw1, *p_xw2, *p_fs;
    cudaGetSymbolAddress((void**)&p_q, g_q);
    cudaGetSymbolAddress((void**)&p_k, g_k);
    cudaGetSymbolAddress((void**)&p_v, g_v);
    cudaGetSymbolAddress((void**)&p_hidden, g_hidden);
    cudaGetSymbolAddress((void**)&p_hn, g_hn);
    cudaGetSymbolAddress((void**)&p_stmt, g_stmt);
    cudaGetSymbolAddress((void**)&p_xw1, g_xw1);
    cudaGetSymbolAddress((void**)&p_xw2, g_xw2);
    cudaGetSymbolAddress((void**)&p_fs, g_fs);

    __nv_bfloat16 *p_mini_hi, *p_mini_lo, *p_mfn_hi, *p_mfn_lo, *p_gc1_hi, *p_gc1_lo;
    __nv_bfloat16 *p_w2t_hi, *p_w2t_lo, *p_w3t_hi, *p_w3t_lo;
    cudaGetSymbolAddress((void**)&p_mini_hi, g_mini_hi);
    cudaGetSymbolAddress((void**)&p_mini_lo, g_mini_lo);
    cudaGetSymbolAddress((void**)&p_mfn_hi, g_mfn_hi);
    cudaGetSymbolAddress((void**)&p_mfn_lo, g_mfn_lo);
    cudaGetSymbolAddress((void**)&p_gc1_hi, g_gc1_hi);
    cudaGetSymbolAddress((void**)&p_gc1_lo, g_gc1_lo);
    cudaGetSymbolAddress((void**)&p_w2t_hi, g_w2t_hi);
    cudaGetSymbolAddress((void**)&p_w2t_lo, g_w2t_lo);
    cudaGetSymbolAddress((void**)&p_w3t_hi, g_w3t_hi);
    cudaGetSymbolAddress((void**)&p_w3t_lo, g_w3t_lo);

    int *p_deg_m, *p_off_m, *p_pos_m, *p_csr_m, *p_bsum_m;
    int *p_deg_o, *p_off_o, *p_pos_o, *p_csr_o, *p_bsum_o;
    cudaGetSymbolAddress((void**)&p_deg_m, g_deg_m);
    cudaGetSymbolAddress((void**)&p_off_m, g_off_m);
    cudaGetSymbolAddress((void**)&p_pos_m, g_pos_m);
    cudaGetSymbolAddress((void**)&p_csr_m, g_csr_m);
    cudaGetSymbolAddress((void**)&p_bsum_m, g_bsum_m);
    cudaGetSymbolAddress((void**)&p_deg_o, g_deg_o);
    cudaGetSymbolAddress((void**)&p_off_o, g_off_o);
    cudaGetSymbolAddress((void**)&p_pos_o, g_pos_o);
    cudaGetSymbolAddress((void**)&p_csr_o, g_csr_o);
    cudaGetSymbolAddress((void**)&p_bsum_o, g_bsum_o);

    cudaFuncSetAttribute(bf16_gemm_qkvs, cudaFuncAttributeMaxDynamicSharedMemorySize, GEMM_SMEM);
    cudaFuncSetAttribute(bf16_gemm, cudaFuncAttributeMaxDynamicSharedMemorySize, GEMM_SMEM);

    static cudaStream_t s1 = nullptr, s2 = nullptr, s3 = nullptr;
    static cudaEvent_t e_root = nullptr, e_csrm = nullptr, e_csro = nullptr,
                       e_ws = nullptr, e_emb2 = nullptr, e_qkvs = nullptr;
    static cudaEvent_t e_mb[NCHUNK] = {};
    if (!s1) {
        cudaStreamCreateWithFlags(&s1, cudaStreamNonBlocking);
        cudaStreamCreateWithFlags(&s2, cudaStreamNonBlocking);
        cudaStreamCreateWithFlags(&s3, cudaStreamNonBlocking);
        cudaEventCreateWithFlags(&e_root, cudaEventDisableTiming);
        cudaEventCreateWithFlags(&e_csrm, cudaEventDisableTiming);
        cudaEventCreateWithFlags(&e_csro, cudaEventDisableTiming);
        cudaEventCreateWithFlags(&e_ws, cudaEventDisableTiming);
        cudaEventCreateWithFlags(&e_emb2, cudaEventDisableTiming);
        cudaEventCreateWithFlags(&e_qkvs, cudaEventDisableTiming);
        for (int c = 0; c < NCHUNK; c++)
            cudaEventCreateWithFlags(&e_mb[c], cudaEventDisableTiming);
    }

    cudaEventRecord(e_root, 0);
    cudaStreamWaitEvent(s1, e_root, 0);
    cudaStreamWaitEvent(s2, e_root, 0);
    cudaStreamWaitEvent(s3, e_root, 0);

    // ---- s1: CSR builds ----
    zero_deg_kernel<<<(NM_ + 255) / 256, 256, 0, s1>>>();
    count_kernel<<<(EM_ + 255) / 256, 256, 0, s1>>>(mini_dst, p_deg_m, EM_);
    count_kernel<<<(EO_ + 255) / 256, 256, 0, s1>>>(dst, p_deg_o, EO_);
    scan_local_kernel<<<NM_ / 1024, 256, 0, s1>>>(p_deg_m, p_off_m, p_bsum_m);
    scan_bsums_kernel<<<1, 128, 0, s1>>>(p_bsum_m, NM_ / 1024, p_off_m, NM_);
    scan_add_kernel<<<NM_ / 256, 256, 0, s1>>>(p_off_m, p_pos_m, p_bsum_m, NM_);
    scatter_kernel<<<(EM_ + 255) / 256, 256, 0, s1>>>(mini_src, mini_dst, p_pos_m, p_csr_m, EM_);
    cudaEventRecord(e_csrm, s1);
    scan_local_kernel<<<NO_ / 1024, 256, 0, s1>>>(p_deg_o, p_off_o, p_bsum_o);
    scan_bsums_kernel<<<1, 128, 0, s1>>>(p_bsum_o, NO_ / 1024, p_off_o, NO_);
    scan_add_kernel<<<NO_ / 256, 256, 0, s1>>>(p_off_o, p_pos_o, p_bsum_o, NO_);
    dinv_kernel<<<(NO_ + 255) / 256, 256, 0, s1>>>();
    scatter_kernel<<<(EO_ + 255) / 256, 256, 0, s1>>>(src, dst, p_pos_o, p_csr_o, EO_);
    cudaEventRecord(e_csro, s1);

    // ---- s2: weight splits + secondary embeddings ----
    {
        dim3 g((E_ * E_ + 255) / 256, 4);
        wsplit4_kernel<<<g, 256, 0, s2>>>(Wq, Wk, Wv, Wskip);
    }
    wsplit_kernel<<<(E_ * HID_ + 255) / 256, 256, 0, s2>>>(W2, p_w2t_hi, p_w2t_lo, E_, HID_);
    wsplit_kernel<<<(HID_ * E_ + 255) / 256, 256, 0, s2>>>(W3, p_w3t_hi, p_w3t_lo, HID_, E_);
    cudaEventRecord(e_ws, s2);
    masked_mean4_kernel<<<NO_ / 4, 128, 0, s2>>>(x_tokens, code_table2, p_stmt, LO_);
    masked_mean4_kernel<<<B_ / 4, 128, 0, s2>>>(desc_tokens, desc_table, p_hn, LD_);
    cudaEventRecord(e_emb2, s2);

    // ---- main stream: mini embedding in 4 chunks ----
    for (int c = 0; c < NCHUNK; c++) {
        masked_mean4_bf16_kernel<<<CHROWS / 4, 128>>>(mini_tokens, code_table,
                                                      p_mini_hi, p_mini_lo, LM_, c * CHROWS);
        cudaEventRecord(e_mb[c], 0);
    }

    // ---- s3: QKVS GEMM chunks, pipelined against embedding chunks ----
    cudaStreamWaitEvent(s3, e_ws, 0);
    for (int c = 0; c < NCHUNK; c++) {
        cudaStreamWaitEvent(s3, e_mb[c], 0);
        dim3 grid(CHROWS / 128, 4);
        bf16_gemm_qkvs<<<grid, 256, GEMM_SMEM, s3>>>(p_mini_hi, p_mini_lo,
                                                     bq, p_q, bk, p_k, bv, p_v,
                                                     bskip, p_hidden, c * CHROWS);
    }
    cudaEventRecord(e_qkvs, s3);

    // ---- main stream: remainder of critical path ----
    cudaStreamWaitEvent(0, e_qkvs, 0);
    cudaStreamWaitEvent(0, e_csrm, 0);
    cudaStreamWaitEvent(0, e_emb2, 0);
    attn_gattn8_kernel<<<NO_, 256>>>(Wg, bg);

    {
        dim3 grid(NO_ / 128, HID_ / 128);
        bf16_gemm<<<grid, 256, GEMM_SMEM>>>(p_mfn_hi, p_mfn_lo, p_w2t_hi, p_w2t_lo,
                                            p_xw1, E_, HID_);
    }
    cudaStreamWaitEvent(0, e_csro, 0);
    gcn_gather_split_kernel<<<NO_ / 8, 256>>>(p_xw1, b2, p_gc1_hi, p_gc1_lo, HID_ / 4);

    {
        dim3 grid(NO_ / 128, E_ / 128);
        bf16_gemm<<<grid, 256, GEMM_SMEM>>>(p_gc1_hi, p_gc1_lo, p_w3t_hi, p_w3t_lo,
                                            p_xw2, HID_, E_);
    }
    gcn_gather_kernel<<<NO_ / 8, 256>>>(p_xw2, b3, p_fs, E_ / 4);

    gattn40_cos_kernel<<<B_, E_>>>(Wg, bg, out);
    (void)in_sizes; (void)n_in; (void)out_size;
}

// round 12
// speedup vs baseline: 1.0161x; 1.0161x over previous
#include <cuda_runtime.h>
#include <cuda_bf16.h>
#include <cstdint>

#define B_   256
#define LD_  64
#define NO_  10240
#define LO_  32
#define NM_  81920
#define LM_  16
#define EO_  81920
#define EM_  327680
#define E_   128
#define HID_ 256
#define H_   8
#define Dh_  16

// ---------------- scratch ----------------
__device__ float g_hn[B_ * E_];
__device__ float g_stmt[NO_ * E_];
__device__ float g_q[NM_ * E_];
__device__ float g_k[NM_ * E_];
__device__ float g_v[NM_ * E_];
__device__ float g_hidden[NM_ * E_];    // skip (QKVS output); read-only in fused attn
__device__ float g_dinv[NO_];
__device__ float g_xw1[NO_ * HID_];
__device__ float g_xw2[NO_ * E_];
__device__ float g_fs[NO_ * E_];

// bf16 split operand buffers
__device__ __align__(16) __nv_bfloat16 g_mini_hi[NM_ * E_], g_mini_lo[NM_ * E_];
__device__ __align__(16) __nv_bfloat16 g_mfn_hi[NO_ * E_],  g_mfn_lo[NO_ * E_];
__device__ __align__(16) __nv_bfloat16 g_gc1_hi[NO_ * HID_], g_gc1_lo[NO_ * HID_];
__device__ __align__(16) __nv_bfloat16 g_wtq_hi[E_ * E_], g_wtq_lo[E_ * E_];
__device__ __align__(16) __nv_bfloat16 g_wtk_hi[E_ * E_], g_wtk_lo[E_ * E_];
__device__ __align__(16) __nv_bfloat16 g_wtv_hi[E_ * E_], g_wtv_lo[E_ * E_];
__device__ __align__(16) __nv_bfloat16 g_wts_hi[E_ * E_], g_wts_lo[E_ * E_];
__device__ __align__(16) __nv_bfloat16 g_w2t_hi[HID_ * E_], g_w2t_lo[HID_ * E_];
__device__ __align__(16) __nv_bfloat16 g_w3t_hi[E_ * HID_], g_w3t_lo[E_ * HID_];

__device__ int g_deg_m[NM_];
__device__ int g_off_m[NM_ + 1];
__device__ int g_pos_m[NM_];
__device__ int g_csr_m[EM_];
__device__ int g_bsum_m[256];
__device__ int g_deg_o[NO_];
__device__ int g_off_o[NO_ + 1];
__device__ int g_pos_o[NO_];
__device__ int g_csr_o[EO_];
__device__ int g_bsum_o[256];

// ---------------- helpers ----------------
__device__ __forceinline__ uint32_t smem_u32(const void* p) {
    uint32_t a;
    asm("{ .reg .u64 t; cvta.to.shared.u64 t, %1; cvt.u32.u64 %0, t; }" : "=r"(a) : "l"(p));
    return a;
}
__device__ __forceinline__ void cp16(uint32_t dst, const void* src) {
    asm volatile("cp.async.cg.shared.global [%0], [%1], 16;" :: "r"(dst), "l"(src));
}
__device__ __forceinline__ void cp_commit() {
    asm volatile("cp.async.commit_group;" ::: "memory");
}
template <int N>
__device__ __forceinline__ void cp_wait() {
    asm volatile("cp.async.wait_group %0;" :: "n"(N) : "memory");
}
__device__ __forceinline__ void mma_bf16(float* d, const uint32_t* a, const uint32_t* b) {
    asm volatile(
        "mma.sync.aligned.m16n8k16.row.col.f32.bf16.bf16.f32 "
        "{%0,%1,%2,%3}, {%4,%5,%6,%7}, {%8,%9}, {%0,%1,%2,%3};"
        : "+f"(d[0]), "+f"(d[1]), "+f"(d[2]), "+f"(d[3])
        : "r"(a[0]), "r"(a[1]), "r"(a[2]), "r"(a[3]), "r"(b[0]), "r"(b[1]));
}

__device__ __forceinline__ void split_store4(__nv_bfloat16* hi, __nv_bfloat16* lo,
                                             size_t base, float4 v) {
    __nv_bfloat162 h0 = __floats2bfloat162_rn(v.x, v.y);
    __nv_bfloat162 h1 = __floats2bfloat162_rn(v.z, v.w);
    float rx = __bfloat162float(h0.x), ry = __bfloat162float(h0.y);
    float rz = __bfloat162float(h1.x), rw = __bfloat162float(h1.y);
    __nv_bfloat162 l0 = __floats2bfloat162_rn(v.x - rx, v.y - ry);
    __nv_bfloat162 l1 = __floats2bfloat162_rn(v.z - rz, v.w - rw);
    uint2 hp = {*(uint32_t*)&h0, *(uint32_t*)&h1};
    uint2 lp = {*(uint32_t*)&l0, *(uint32_t*)&l1};
    *(uint2*)(hi + base) = hp;
    *(uint2*)(lo + base) = lp;
}

// ---------------- weight transpose + split ----------------
__global__ void wsplit_kernel(const float* __restrict__ W, __nv_bfloat16* __restrict__ hi,
                              __nv_bfloat16* __restrict__ lo, int K, int N) {
    int i = blockIdx.x * blockDim.x + threadIdx.x;
    if (i >= K * N) return;
    int n = i / K, k = i - n * K;
    float v = W[(size_t)k * N + n];
    __nv_bfloat16 h = __float2bfloat16(v);
    hi[i] = h;
    lo[i] = __float2bfloat16(v - __bfloat162float(h));
}

__global__ void wsplit4_kernel(const float* __restrict__ Wq, const float* __restrict__ Wk,
                               const float* __restrict__ Wv, const float* __restrict__ Ws) {
    const float* W; __nv_bfloat16 *hi, *lo;
    switch (blockIdx.y) {
        case 0: W = Wq; hi = g_wtq_hi; lo = g_wtq_lo; break;
        case 1: W = Wk; hi = g_wtk_hi; lo = g_wtk_lo; break;
        case 2: W = Wv; hi = g_wtv_hi; lo = g_wtv_lo; break;
        default: W = Ws; hi = g_wts_hi; lo = g_wts_lo; break;
    }
    int i = blockIdx.x * blockDim.x + threadIdx.x;
    if (i >= E_ * E_) return;
    int n = i / E_, k = i - n * E_;
    float v = W[(size_t)k * E_ + n];
    __nv_bfloat16 h = __float2bfloat16(v);
    hi[i] = h;
    lo[i] = __float2bfloat16(v - __bfloat162float(h));
}

// ---------------- bf16x3 mma.sync GEMM, cp.async double-buffered -----------------
// (round-8 scalar-LDS inner loop — measured-best; now 2 CTAs/SM)
#define GSTR 40
#define GST_ELEMS (128 * GSTR)
#define STAGE_ELEMS (4 * GST_ELEMS)
#define GEMM_SMEM (2 * STAGE_ELEMS * 2)

__device__ void bf16_gemm_body(const __nv_bfloat16* __restrict__ Ahi,
                               const __nv_bfloat16* __restrict__ Alo,
                               const __nv_bfloat16* __restrict__ Bhi,
                               const __nv_bfloat16* __restrict__ Blo,
                               const float* __restrict__ bias, float* __restrict__ C,
                               int row0, int K, int Ntot, int col0) {
    extern __shared__ __align__(16) __nv_bfloat16 smb[];
    uint32_t sbase = smem_u32(smb);
    int tid = threadIdx.x;
    int wid = tid >> 5, lane = tid & 31;
    int wm = wid >> 2, wn = wid & 3, gr = lane >> 2, tg = lane & 3;

    float acc[4][4][4] = {};
    int nch = K >> 5;

    auto issue = [&](int c) {
        int kt = c << 5;
        uint32_t base = sbase + (uint32_t)(c & 1) * (STAGE_ELEMS * 2);
#pragma unroll
        for (int it = 0; it < 2; it++) {
            int idx = it * 256 + tid;
            int row = idx >> 2, g8 = (idx & 3) * 8;
            size_t goff = (size_t)(row0 + row) * K + kt + g8;
            uint32_t d = base + (uint32_t)(row * GSTR + g8) * 2;
            cp16(d, Ahi + goff);
            cp16(d + GST_ELEMS * 2, Alo + goff);
        }
#pragma unroll
        for (int it = 0; it < 2; it++) {
            int idx = it * 256 + tid;
            int n = idx >> 2, g8 = (idx & 3) * 8;
            size_t goff = (size_t)(col0 + n) * K + kt + g8;
            uint32_t d = base + (uint32_t)(2 * GST_ELEMS + n * GSTR + g8) * 2;
            cp16(d, Bhi + goff);
            cp16(d + GST_ELEMS * 2, Blo + goff);
        }
        cp_commit();
    };

    issue(0);
    for (int c = 0; c < nch; c++) {
        if (c + 1 < nch) { issue(c + 1); cp_wait<1>(); }
        else             { cp_wait<0>(); }
        __syncthreads();

        const uint32_t* S = reinterpret_cast<const uint32_t*>(smb) + (c & 1) * (STAGE_ELEMS / 2);
        const uint32_t* A32h = S;
        const uint32_t* A32l = S + GST_ELEMS / 2;
        const uint32_t* B32h = S + GST_ELEMS;
        const uint32_t* B32l = S + GST_ELEMS + GST_ELEMS / 2;

#pragma unroll
        for (int ks = 0; ks < 2; ks++) {
            int kb = ks * 8;
            uint32_t ah[4][4], al[4][4], bh[4][2], bl[4][2];
#pragma unroll
            for (int mt = 0; mt < 4; mt++) {
                int r = wm * 64 + mt * 16 + gr;
                int o = r * (GSTR / 2) + kb + tg;
                ah[mt][0] = A32h[o];
                ah[mt][1] = A32h[o + 8 * (GSTR / 2)];
                ah[mt][2] = A32h[o + 4];
                ah[mt][3] = A32h[o + 8 * (GSTR / 2) + 4];
                al[mt][0] = A32l[o];
                al[mt][1] = A32l[o + 8 * (GSTR / 2)];
                al[mt][2] = A32l[o + 4];
                al[mt][3] = A32l[o + 8 * (GSTR / 2) + 4];
            }
#pragma unroll
            for (int nt = 0; nt < 4; nt++) {
                int n = wn * 32 + nt * 8 + gr;
                int o = n * (GSTR / 2) + kb + tg;
                bh[nt][0] = B32h[o];
                bh[nt][1] = B32h[o + 4];
                bl[nt][0] = B32l[o];
                bl[nt][1] = B32l[o + 4];
            }
#pragma unroll
            for (int mt = 0; mt < 4; mt++)
#pragma unroll
                for (int nt = 0; nt < 4; nt++) {
                    mma_bf16(acc[mt][nt], ah[mt], bh[nt]);
                    mma_bf16(acc[mt][nt], ah[mt], bl[nt]);
                    mma_bf16(acc[mt][nt], al[mt], bh[nt]);
                }
        }
        __syncthreads();
    }

#pragma unroll
    for (int mt = 0; mt < 4; mt++) {
#pragma unroll
        for (int nt = 0; nt < 4; nt++) {
            int row = row0 + wm * 64 + mt * 16 + gr;
            int col = col0 + wn * 32 + nt * 8 + 2 * tg;
            float b0 = 0.f, b1 = 0.f;
            if (bias) { b0 = bias[col]; b1 = bias[col + 1]; }
            float2 o0 = {acc[mt][nt][0] + b0, acc[mt][nt][1] + b1};
            float2 o1 = {acc[mt][nt][2] + b0, acc[mt][nt][3] + b1};
            *(float2*)&C[(size_t)row * Ntot + col] = o0;
            *(float2*)&C[(size_t)(row + 8) * Ntot + col] = o1;
        }
    }
}

__global__ __launch_bounds__(256, 2) void bf16_gemm_qkvs(
    const __nv_bfloat16* __restrict__ Ahi, const __nv_bfloat16* __restrict__ Alo,
    const float* __restrict__ bq, float* __restrict__ Cq,
    const float* __restrict__ bk, float* __restrict__ Ck,
    const float* __restrict__ bv, float* __restrict__ Cv,
    const float* __restrict__ bs, float* __restrict__ Cs) {
    const __nv_bfloat16 *Bh, *Bl; const float* bias; float* C;
    switch (blockIdx.y) {
        case 0: Bh = g_wtq_hi; Bl = g_wtq_lo; bias = bq; C = Cq; break;
        case 1: Bh = g_wtk_hi; Bl = g_wtk_lo; bias = bk; C = Ck; break;
        case 2: Bh = g_wtv_hi; Bl = g_wtv_lo; bias = bv; C = Cv; break;
        default: Bh = g_wts_hi; Bl = g_wts_lo; bias = bs; C = Cs; break;
    }
    bf16_gemm_body(Ahi, Alo, Bh, Bl, bias, C, blockIdx.x * 128, E_, E_, 0);
}

__global__ __launch_bounds__(256, 2) void bf16_gemm(
    const __nv_bfloat16* __restrict__ Ahi, const __nv_bfloat16* __restrict__ Alo,
    const __nv_bfloat16* __restrict__ Bhi, const __nv_bfloat16* __restrict__ Blo,
    float* __restrict__ C, int K, int Ntot) {
    bf16_gemm_body(Ahi, Alo, Bhi, Blo, nullptr, C, blockIdx.x * 128, K, Ntot, blockIdx.y * 128);
}

// ---------------- CSR build ----------------
__global__ void zero_deg_kernel() {
    int i = blockIdx.x * blockDim.x + threadIdx.x;
    if (i < NM_) g_deg_m[i] = 0;
    if (i < NO_) g_deg_o[i] = 0;
}
__global__ void count_kernel(const int* __restrict__ dst, int* __restrict__ deg, int ne) {
    int e = blockIdx.x * blockDim.x + threadIdx.x;
    if (e < ne) atomicAdd(&deg[dst[e]], 1);
}
__global__ void scan_local_kernel(const int* __restrict__ deg, int* __restrict__ off,
                                  int* __restrict__ bsum) {
    __shared__ int ws[8];
    int tid = threadIdx.x;
    int base = blockIdx.x * 1024 + tid * 4;
    int4 d = *(const int4*)&deg[base];
    int s = d.x + d.y + d.z + d.w;
    int lane = tid & 31, wid = tid >> 5;
    int v = s;
#pragma unroll
    for (int o = 1; o < 32; o <<= 1) {
        int t = __shfl_up_sync(0xffffffffu, v, o);
        if (lane >= o) v += t;
    }
    if (lane == 31) ws[wid] = v;
    __syncthreads();
    if (tid == 0) {
        int run = 0;
#pragma unroll
        for (int w = 0; w < 8; w++) { int t = ws[w]; ws[w] = run; run += t; }
    }
    __syncthreads();
    int excl = v - s + ws[wid];
    int4 o4;
    o4.x = excl;
    o4.y = excl + d.x;
    o4.z = o4.y + d.y;
    o4.w = o4.z + d.z;
    *(int4*)&off[base] = o4;
    if (tid == 255) bsum[blockIdx.x] = excl + s;
}
__global__ void scan_bsums_kernel(int* __restrict__ bsum, int nb, int* __restrict__ off, int n) {
    __shared__ int sh[128];
    int tid = threadIdx.x;
    int val = (tid < nb) ? bsum[tid] : 0;
    sh[tid] = val;
    __syncthreads();
    int acc = val;
    for (int o = 1; o < 128; o <<= 1) {
        int t = (tid >= o) ? sh[tid - o] : 0;
        __syncthreads();
        acc += t;
        sh[tid] = acc;
        __syncthreads();
    }
    if (tid < nb) bsum[tid] = acc - val;
    if (tid == 127) off[n] = sh[127];
}
__global__ void scan_add_kernel(int* __restrict__ off, int* __restrict__ pos,
                                const int* __restrict__ bsum, int n) {
    int i = blockIdx.x * blockDim.x + threadIdx.x;
    if (i < n) {
        int v = off[i] + bsum[i >> 10];
        off[i] = v;
        pos[i] = v;
    }
}
__global__ void scatter_kernel(const int* __restrict__ src, const int* __restrict__ dst,
                               int* __restrict__ pos, int* __restrict__ csr, int ne) {
    int e = blockIdx.x * blockDim.x + threadIdx.x;
    if (e < ne) {
        int t = dst[e];
        int slot = atomicAdd(&pos[t], 1);
        csr[slot] = src[e];
    }
}
__global__ void dinv_kernel() {
    int i = blockIdx.x * blockDim.x + threadIdx.x;
    if (i < NO_) g_dinv[i] = rsqrtf((float)(g_deg_o[i] + 1));
}

// ---------------- masked mean (fp32 out) ----------------
__global__ void masked_mean4_kernel(const int* __restrict__ tok,
                                    const float* __restrict__ table,
                                    float* __restrict__ out, int L) {
    __shared__ int ts[4][64];
    int warp = threadIdx.x >> 5, lane = threadIdx.x & 31;
    int n = blockIdx.x * 4 + warp;
    for (int j = lane; j < L; j += 32) ts[warp][j] = tok[n * L + j];
    __syncwarp();
    const float4* t4 = (const float4*)table;
    float4 acc = {0.f, 0.f, 0.f, 0.f};
    int cnt = 0;
    for (int j = 0; j < L; j++) {
        int t = ts[warp][j];
        if (t != 0) {
            float4 e = t4[(size_t)t * 32 + lane];
            acc.x += e.x; acc.y += e.y; acc.z += e.z; acc.w += e.w;
            cnt++;
        }
    }
    float inv = 1.f / (float)(cnt > 1 ? cnt : 1);
    float4 o = {acc.x * inv, acc.y * inv, acc.z * inv, acc.w * inv};
    ((float4*)out)[(size_t)n * 32 + lane] = o;
}

// ---------------- masked mean (bf16 hi/lo out) ----------------
__global__ void masked_mean4_bf16_kernel(const int* __restrict__ tok,
                                         const float* __restrict__ table,
                                         __nv_bfloat16* __restrict__ hi,
                                         __nv_bfloat16* __restrict__ lo, int L) {
    __shared__ int ts[4][64];
    int warp = threadIdx.x >> 5, lane = threadIdx.x & 31;
    int n = blockIdx.x * 4 + warp;
    for (int j = lane; j < L; j += 32) ts[warp][j] = tok[n * L + j];
    __syncwarp();
    const float4* t4 = (const float4*)table;
    float4 acc = {0.f, 0.f, 0.f, 0.f};
    int cnt = 0;
    for (int j = 0; j < L; j++) {
        int t = ts[warp][j];
        if (t != 0) {
            float4 e = t4[(size_t)t * 32 + lane];
            acc.x += e.x; acc.y += e.y; acc.z += e.z; acc.w += e.w;
            cnt++;
        }
    }
    float inv = 1.f / (float)(cnt > 1 ? cnt : 1);
    float4 o = {acc.x * inv, acc.y * inv, acc.z * inv, acc.w * inv};
    split_store4(hi, lo, ((size_t)n * 32 + lane) * 4, o);
}

// ---------------- fused attn + global-attention-8 + (.,+stmt)*0.5 -----------------
__global__ __launch_bounds__(256) void attn_gattn8_kernel(const float* __restrict__ Wg,
                                                          const float* __restrict__ bg) {
    __shared__ float sh_rows[8][132];
    __shared__ float sh_gate[8];
    int tid = threadIdx.x;
    int warp = tid >> 5, lane = tid & 31;
    int n = blockIdx.x;
    int t = n * 8 + warp;

    const float4* q4 = (const float4*)g_q;
    const float4* k4 = (const float4*)g_k;
    const float4* v4 = (const float4*)g_v;
    float4 qv = q4[(size_t)t * 32 + lane];
    float m = -1e30f, ss = 0.f;
    float4 acc = {0.f, 0.f, 0.f, 0.f};
    int beg = g_off_m[t], end = g_off_m[t + 1];
    for (int i = beg; i < end; i++) {
        int s = g_csr_m[i];
        float4 kv = k4[(size_t)s * 32 + lane];
        float p = qv.x * kv.x + qv.y * kv.y + qv.z * kv.z + qv.w * kv.w;
        p += __shfl_xor_sync(0xffffffffu, p, 1);
        p += __shfl_xor_sync(0xffffffffu, p, 2);
        float sc = p * 0.25f;
        float mn = fmaxf(m, sc);
        float scale = __expf(m - mn);
        float w = __expf(sc - mn);
        float4 vv = v4[(size_t)s * 32 + lane];
        ss = ss * scale + w;
        acc.x = acc.x * scale + w * vv.x;
        acc.y = acc.y * scale + w * vv.y;
        acc.z = acc.z * scale + w * vv.z;
        acc.w = acc.w * scale + w * vv.w;
        m = mn;
    }
    float inv = 1.f / (ss + 1e-16f);
    float4 h = ((const float4*)g_hidden)[(size_t)t * 32 + lane];
    h.x += acc.x * inv; h.y += acc.y * inv;
    h.z += acc.z * inv; h.w += acc.w * inv;

    float4 wg = ((const float4*)Wg)[lane];
    float p = h.x * wg.x + h.y * wg.y + h.z * wg.z + h.w * wg.w;
#pragma unroll
    for (int off = 16; off; off >>= 1) p += __shfl_xor_sync(0xffffffffu, p, off);

    *(float4*)&sh_rows[warp][lane * 4] = h;
    if (lane == 0) sh_gate[warp] = p + bg[0];
    __syncthreads();

    if (tid < E_) {
        float gm = sh_gate[0];
#pragma unroll
        for (int j = 1; j < 8; j++) gm = fmaxf(gm, sh_gate[j]);
        float e[8], s = 0.f;
#pragma unroll
        for (int j = 0; j < 8; j++) { e[j] = __expf(sh_gate[j] - gm); s += e[j]; }
        float is = 1.f / (s + 1e-16f);
        float o = 0.f;
#pragma unroll
        for (int j = 0; j < 8; j++) o += e[j] * is * sh_rows[j][tid];
        float res = (o + g_stmt[(size_t)n * E_ + tid]) * 0.5f;
        __nv_bfloat16 hb = __float2bfloat16(res);
        g_mfn_hi[(size_t)n * E_ + tid] = hb;
        g_mfn_lo[(size_t)n * E_ + tid] = __float2bfloat16(res - __bfloat162float(hb));
    }
}

// ---------------- GCN gather -> relu + bf16 split ----------------
__global__ void gcn_gather_split_kernel(const float* __restrict__ xw,
                                        const float* __restrict__ bias,
                                        __nv_bfloat16* __restrict__ hi,
                                        __nv_bfloat16* __restrict__ lo, int Mv4) {
    int warp = threadIdx.x >> 5, lane = threadIdx.x & 31;
    int t = blockIdx.x * 8 + warp;
    float di = g_dinv[t];
    int beg = g_off_o[t], end = g_off_o[t + 1];
    const float4* x4 = (const float4*)xw;
    for (int c = lane; c < Mv4; c += 32) {
        float4 a = x4[(size_t)t * Mv4 + c];
        float4 bv = ((const float4*)bias)[c];
        float d2 = di * di;
        float4 acc = {a.x * d2 + bv.x, a.y * d2 + bv.y, a.z * d2 + bv.z, a.w * d2 + bv.w};
        for (int i = beg; i < end; i++) {
            int s = g_csr_o[i];
            float nr = g_dinv[s] * di;
            float4 x = x4[(size_t)s * Mv4 + c];
            acc.x += nr * x.x; acc.y += nr * x.y;
            acc.z += nr * x.z; acc.w += nr * x.w;
        }
        acc.x = fmaxf(acc.x, 0.f); acc.y = fmaxf(acc.y, 0.f);
        acc.z = fmaxf(acc.z, 0.f); acc.w = fmaxf(acc.w, 0.f);
        split_store4(hi, lo, ((size_t)t * Mv4 + c) * 4, acc);
    }
}

// ---------------- GCN gather -> fp32 ----------------
__global__ void gcn_gather_kernel(const float* __restrict__ xw, const float* __restrict__ bias,
                                  float* __restrict__ out, int Mv4) {
    int warp = threadIdx.x >> 5, lane = threadIdx.x & 31;
    int t = blockIdx.x * 8 + warp;
    float di = g_dinv[t];
    int beg = g_off_o[t], end = g_off_o[t + 1];
    const float4* x4 = (const float4*)xw;
    for (int c = lane; c < Mv4; c += 32) {
        float4 a = x4[(size_t)t * Mv4 + c];
        float4 bv = ((const float4*)bias)[c];
        float d2 = di * di;
        float4 acc = {a.x * d2 + bv.x, a.y * d2 + bv.y, a.z * d2 + bv.z, a.w * d2 + bv.w};
        for (int i = beg; i < end; i++) {
            int s = g_csr_o[i];
            float nr = g_dinv[s] * di;
            float4 x = x4[(size_t)s * Mv4 + c];
            acc.x += nr * x.x; acc.y += nr * x.y;
            acc.z += nr * x.z; acc.w += nr * x.w;
        }
        ((float4*)out)[(size_t)t * Mv4 + c] = acc;
    }
}

// ---------------- fused global attention (segments of 40) + cosine ----------------
__global__ void gattn40_cos_kernel(const float* __restrict__ Wg, const float* __restrict__ bg,
                                   float* __restrict__ out) {
    __shared__ float gate[40];
    __shared__ float alpha[40];
    __shared__ float ms[2];
    __shared__ float red[3][4];
    int b = blockIdx.x;
    int tid = threadIdx.x;  // 128
    int warp = tid >> 5, lane = tid & 31;
    float4 wg = ((const float4*)Wg)[lane];
    for (int j = warp; j < 40; j += 4) {
        float4 xv = ((const float4*)g_fs)[(size_t)(b * 40 + j) * 32 + lane];
        float p = xv.x * wg.x + xv.y * wg.y + xv.z * wg.z + xv.w * wg.w;
#pragma unroll
        for (int off = 16; off; off >>= 1) p += __shfl_xor_sync(0xffffffffu, p, off);
        if (lane == 0) gate[j] = p + bg[0];
    }
    __syncthreads();
    if (tid == 0) {
        float m = gate[0];
        for (int j = 1; j < 40; j++) m = fmaxf(m, gate[j]);
        float s = 0.f;
        for (int j = 0; j < 40; j++) s += __expf(gate[j] - m);
        ms[0] = m; ms[1] = s;
    }
    __syncthreads();
    if (tid < 40) alpha[tid] = __expf(gate[tid] - ms[0]) / (ms[1] + 1e-16f);
    __syncthreads();
    float f = 0.f;
    for (int j = 0; j < 40; j++)
        f += alpha[j] * g_fs[(size_t)(b * 40 + j) * E_ + tid];
    float hh = g_hn[(size_t)b * E_ + tid];
    float dt = f * hh, na = f * f, nb = hh * hh;
#pragma unroll
    for (int off = 16; off; off >>= 1) {
        dt += __shfl_xor_sync(0xffffffffu, dt, off);
        na += __shfl_xor_sync(0xffffffffu, na, off);
        nb += __shfl_xor_sync(0xffffffffu, nb, off);
    }
    if (lane == 0) { red[0][warp] = dt; red[1][warp] = na; red[2][warp] = nb; }
    __syncthreads();
    if (tid == 0) {
        float d = red[0][0] + red[0][1] + red[0][2] + red[0][3];
        float a = red[1][0] + red[1][1] + red[1][2] + red[1][3];
        float c = red[2][0] + red[2][1] + red[2][2] + red[2][3];
        out[b] = d / (fmaxf(sqrtf(a), 1e-8f) * fmaxf(sqrtf(c), 1e-8f));
    }
}

// ---------------- launch (stream DAG inside graph capture) ----------------
extern "C" void kernel_launch(void* const* d_in, const int* in_sizes, int n_in,
                              void* d_out, int out_size) {
    const int* desc_tokens = (const int*)d_in[0];
    const int* x_tokens    = (const int*)d_in[1];
    const int* mini_tokens = (const int*)d_in[2];
    const int* src         = (const int*)d_in[3];
    const int* dst         = (const int*)d_in[4];
    const int* mini_src    = (const int*)d_in[5];
    const int* mini_dst    = (const int*)d_in[6];
    const float* desc_table  = (const float*)d_in[9];
    const float* code_table  = (const float*)d_in[10];
    const float* code_table2 = (const float*)d_in[11];
    const float* Wq = (const float*)d_in[12]; const float* bq = (const float*)d_in[13];
    const float* Wk = (const float*)d_in[14]; const float* bk = (const float*)d_in[15];
    const float* Wv = (const float*)d_in[16]; const float* bv = (const float*)d_in[17];
    const float* Wskip = (const float*)d_in[18]; const float* bskip = (const float*)d_in[19];
    const float* W2 = (const float*)d_in[20]; const float* b2 = (const float*)d_in[21];
    const float* W3 = (const float*)d_in[22]; const float* b3 = (const float*)d_in[23];
    const float* Wg = (const float*)d_in[24]; const float* bg = (const float*)d_in[25];
    float* out = (float*)d_out;

    float *p_q, *p_k, *p_v, *p_hidden, *p_hn, *p_stmt, *p_xw1, *p_xw2, *p_fs;
    cudaGetSymbolAddress((void**)&p_q, g_q);
    cudaGetSymbolAddress((void**)&p_k, g_k);
    cudaGetSymbolAddress((void**)&p_v, g_v);
    cudaGetSymbolAddress((void**)&p_hidden, g_hidden);
    cudaGetSymbolAddress((void**)&p_hn, g_hn);
    cudaGetSymbolAddress((void**)&p_stmt, g_stmt);
    cudaGetSymbolAddress((void**)&p_xw1, g_xw1);
    cudaGetSymbolAddress((void**)&p_xw2, g_xw2);
    cudaGetSymbolAddress((void**)&p_fs, g_fs);

    __nv_bfloat16 *p_mini_hi, *p_mini_lo, *p_mfn_hi, *p_mfn_lo, *p_gc1_hi, *p_gc1_lo;
    __nv_bfloat16 *p_w2t_hi, *p_w2t_lo, *p_w3t_hi, *p_w3t_lo;
    cudaGetSymbolAddress((void**)&p_mini_hi, g_mini_hi);
    cudaGetSymbolAddress((void**)&p_mini_lo, g_mini_lo);
    cudaGetSymbolAddress((void**)&p_mfn_hi, g_mfn_hi);
    cudaGetSymbolAddress((void**)&p_mfn_lo, g_mfn_lo);
    cudaGetSymbolAddress((void**)&p_gc1_hi, g_gc1_hi);
    cudaGetSymbolAddress((void**)&p_gc1_lo, g_gc1_lo);
    cudaGetSymbolAddress((void**)&p_w2t_hi, g_w2t_hi);
    cudaGetSymbolAddress((void**)&p_w2t_lo, g_w2t_lo);
    cudaGetSymbolAddress((void**)&p_w3t_hi, g_w3t_hi);
    cudaGetSymbolAddress((void**)&p_w3t_lo, g_w3t_lo);

    int *p_deg_m, *p_off_m, *p_pos_m, *p_csr_m, *p_bsum_m;
    int *p_deg_o, *p_off_o, *p_pos_o, *p_csr_o, *p_bsum_o;
    cudaGetSymbolAddress((void**)&p_deg_m, g_deg_m);
    cudaGetSymbolAddress((void**)&p_off_m, g_off_m);
    cudaGetSymbolAddress((void**)&p_pos_m, g_pos_m);
    cudaGetSymbolAddress((void**)&p_csr_m, g_csr_m);
    cudaGetSymbolAddress((void**)&p_bsum_m, g_bsum_m);
    cudaGetSymbolAddress((void**)&p_deg_o, g_deg_o);
    cudaGetSymbolAddress((void**)&p_off_o, g_off_o);
    cudaGetSymbolAddress((void**)&p_pos_o, g_pos_o);
    cudaGetSymbolAddress((void**)&p_csr_o, g_csr_o);
    cudaGetSymbolAddress((void**)&p_bsum_o, g_bsum_o);

    cudaFuncSetAttribute(bf16_gemm_qkvs, cudaFuncAttributeMaxDynamicSharedMemorySize, GEMM_SMEM);
    cudaFuncSetAttribute(bf16_gemm, cudaFuncAttributeMaxDynamicSharedMemorySize, GEMM_SMEM);

    static cudaStream_t s1 = nullptr, s2 = nullptr;
    static cudaEvent_t e_root = nullptr, e_csrm = nullptr, e_csro = nullptr,
                       e_ws = nullptr, e_emb2 = nullptr;
    if (!s1) {
        cudaStreamCreateWithFlags(&s1, cudaStreamNonBlocking);
        cudaStreamCreateWithFlags(&s2, cudaStreamNonBlocking);
        cudaEventCreateWithFlags(&e_root, cudaEventDisableTiming);
        cudaEventCreateWithFlags(&e_csrm, cudaEventDisableTiming);
        cudaEventCreateWithFlags(&e_csro, cudaEventDisableTiming);
        cudaEventCreateWithFlags(&e_ws, cudaEventDisableTiming);
        cudaEventCreateWithFlags(&e_emb2, cudaEventDisableTiming);
    }

    cudaEventRecord(e_root, 0);
    cudaStreamWaitEvent(s1, e_root, 0);
    cudaStreamWaitEvent(s2, e_root, 0);

    // ---- s1: CSR builds ----
    zero_deg_kernel<<<(NM_ + 255) / 256, 256, 0, s1>>>();
    count_kernel<<<(EM_ + 255) / 256, 256, 0, s1>>>(mini_dst, p_deg_m, EM_);
    count_kernel<<<(EO_ + 255) / 256, 256, 0, s1>>>(dst, p_deg_o, EO_);
    scan_local_kernel<<<NM_ / 1024, 256, 0, s1>>>(p_deg_m, p_off_m, p_bsum_m);
    scan_bsums_kernel<<<1, 128, 0, s1>>>(p_bsum_m, NM_ / 1024, p_off_m, NM_);
    scan_add_kernel<<<NM_ / 256, 256, 0, s1>>>(p_off_m, p_pos_m, p_bsum_m, NM_);
    scatter_kernel<<<(EM_ + 255) / 256, 256, 0, s1>>>(mini_src, mini_dst, p_pos_m, p_csr_m, EM_);
    cudaEventRecord(e_csrm, s1);
    scan_local_kernel<<<NO_ / 1024, 256, 0, s1>>>(p_deg_o, p_off_o, p_bsum_o);
    scan_bsums_kernel<<<1, 128, 0, s1>>>(p_bsum_o, NO_ / 1024, p_off_o, NO_);
    scan_add_kernel<<<NO_ / 256, 256, 0, s1>>>(p_off_o, p_pos_o, p_bsum_o, NO_);
    dinv_kernel<<<(NO_ + 255) / 256, 256, 0, s1>>>();
    scatter_kernel<<<(EO_ + 255) / 256, 256, 0, s1>>>(src, dst, p_pos_o, p_csr_o, EO_);
    cudaEventRecord(e_csro, s1);

    // ---- s2: weight splits + secondary embeddings ----
    {
        dim3 g((E_ * E_ + 255) / 256, 4);
        wsplit4_kernel<<<g, 256, 0, s2>>>(Wq, Wk, Wv, Wskip);
    }
    wsplit_kernel<<<(E_ * HID_ + 255) / 256, 256, 0, s2>>>(W2, p_w2t_hi, p_w2t_lo, E_, HID_);
    wsplit_kernel<<<(HID_ * E_ + 255) / 256, 256, 0, s2>>>(W3, p_w3t_hi, p_w3t_lo, HID_, E_);
    cudaEventRecord(e_ws, s2);
    masked_mean4_kernel<<<NO_ / 4, 128, 0, s2>>>(x_tokens, code_table2, p_stmt, LO_);
    masked_mean4_kernel<<<B_ / 4, 128, 0, s2>>>(desc_tokens, desc_table, p_hn, LD_);
    cudaEventRecord(e_emb2, s2);

    // ---- main stream: critical path ----
    masked_mean4_bf16_kernel<<<NM_ / 4, 128>>>(mini_tokens, code_table, p_mini_hi, p_mini_lo, LM_);

    cudaStreamWaitEvent(0, e_ws, 0);
    {
        dim3 grid(NM_ / 128, 4);
        bf16_gemm_qkvs<<<grid, 256, GEMM_SMEM>>>(p_mini_hi, p_mini_lo,
                                                 bq, p_q, bk, p_k, bv, p_v, bskip, p_hidden);
    }

    cudaStreamWaitEvent(0, e_csrm, 0);
    cudaStreamWaitEvent(0, e_emb2, 0);
    attn_gattn8_kernel<<<NO_, 256>>>(Wg, bg);

    {
        dim3 grid(NO_ / 128, HID_ / 128);
        bf16_gemm<<<grid, 256, GEMM_SMEM>>>(p_mfn_hi, p_mfn_lo, p_w2t_hi, p_w2t_lo,
                                            p_xw1, E_, HID_);
    }
    cudaStreamWaitEvent(0, e_csro, 0);
    gcn_gather_split_kernel<<<NO_ / 8, 256>>>(p_xw1, b2, p_gc1_hi, p_gc1_lo, HID_ / 4);

    {
        dim3 grid(NO_ / 128, E_ / 128);
        bf16_gemm<<<grid, 256, GEMM_SMEM>>>(p_gc1_hi, p_gc1_lo, p_w3t_hi, p_w3t_lo,
                                            p_xw2, HID_, E_);
    }
    gcn_gather_kernel<<<NO_ / 8, 256>>>(p_xw2, b3, p_fs, E_ / 4);

    gattn40_cos_kernel<<<B_, E_>>>(Wg, bg, out);
    (void)in_sizes; (void)n_in; (void)out_size;
}

// round 13
// speedup vs baseline: 1.1177x; 1.1000x over previous
#include <cuda_runtime.h>
#include <cuda_fp16.h>
#include <cstdint>

#define B_   256
#define LD_  64
#define NO_  10240
#define LO_  32
#define NM_  81920
#define LM_  16
#define EO_  81920
#define EM_  327680
#define E_   128
#define HID_ 256
#define H_   8
#define Dh_  16

// ---------------- scratch ----------------
__device__ float g_hn[B_ * E_];
__device__ float g_stmt[NO_ * E_];
__device__ float g_q[NM_ * E_];
__device__ float g_k[NM_ * E_];
__device__ float g_v[NM_ * E_];
__device__ float g_hidden[NM_ * E_];    // skip (QKVS output); read-only in fused attn
__device__ float g_dinv[NO_];
__device__ float g_xw1[NO_ * HID_];
__device__ float g_xw2[NO_ * E_];
__device__ float g_fs[NO_ * E_];

// fp16 operand buffers: A single-precision fp16, weights hi/lo split
__device__ __align__(16) __half g_mini_h[NM_ * E_];
__device__ __align__(16) __half g_mfn_h[NO_ * E_];
__device__ __align__(16) __half g_gc1_h[NO_ * HID_];
__device__ __align__(16) __half g_wtq_hi[E_ * E_], g_wtq_lo[E_ * E_];
__device__ __align__(16) __half g_wtk_hi[E_ * E_], g_wtk_lo[E_ * E_];
__device__ __align__(16) __half g_wtv_hi[E_ * E_], g_wtv_lo[E_ * E_];
__device__ __align__(16) __half g_wts_hi[E_ * E_], g_wts_lo[E_ * E_];
__device__ __align__(16) __half g_w2t_hi[HID_ * E_], g_w2t_lo[HID_ * E_];
__device__ __align__(16) __half g_w3t_hi[E_ * HID_], g_w3t_lo[E_ * HID_];

__device__ int g_deg_m[NM_];
__device__ int g_off_m[NM_ + 1];
__device__ int g_pos_m[NM_];
__device__ int g_csr_m[EM_];
__device__ int g_bsum_m[256];
__device__ int g_deg_o[NO_];
__device__ int g_off_o[NO_ + 1];
__device__ int g_pos_o[NO_];
__device__ int g_csr_o[EO_];
__device__ int g_bsum_o[256];

// ---------------- helpers ----------------
__device__ __forceinline__ uint32_t smem_u32(const void* p) {
    uint32_t a;
    asm("{ .reg .u64 t; cvta.to.shared.u64 t, %1; cvt.u32.u64 %0, t; }" : "=r"(a) : "l"(p));
    return a;
}
__device__ __forceinline__ void cp16(uint32_t dst, const void* src) {
    asm volatile("cp.async.cg.shared.global [%0], [%1], 16;" :: "r"(dst), "l"(src));
}
__device__ __forceinline__ void cp_commit() {
    asm volatile("cp.async.commit_group;" ::: "memory");
}
template <int N>
__device__ __forceinline__ void cp_wait() {
    asm volatile("cp.async.wait_group %0;" :: "n"(N) : "memory");
}
__device__ __forceinline__ void mma_f16(float* d, const uint32_t* a, const uint32_t* b) {
    asm volatile(
        "mma.sync.aligned.m16n8k16.row.col.f32.f16.f16.f32 "
        "{%0,%1,%2,%3}, {%4,%5,%6,%7}, {%8,%9}, {%0,%1,%2,%3};"
        : "+f"(d[0]), "+f"(d[1]), "+f"(d[2]), "+f"(d[3])
        : "r"(a[0]), "r"(a[1]), "r"(a[2]), "r"(a[3]), "r"(b[0]), "r"(b[1]));
}

// store 4 consecutive fp16 values (single precision A operand)
__device__ __forceinline__ void h4_store(__half* dst, size_t base, float4 v) {
    __half2 p0 = __floats2half2_rn(v.x, v.y);
    __half2 p1 = __floats2half2_rn(v.z, v.w);
    uint2 val = {*(uint32_t*)&p0, *(uint32_t*)&p1};
    *(uint2*)(dst + base) = val;
}

// ---------------- weight transpose + split (fp16 hi/lo) ----------------
__global__ void wsplit_kernel(const float* __restrict__ W, __half* __restrict__ hi,
                              __half* __restrict__ lo, int K, int N) {
    int i = blockIdx.x * blockDim.x + threadIdx.x;
    if (i >= K * N) return;
    int n = i / K, k = i - n * K;
    float v = W[(size_t)k * N + n];
    __half h = __float2half(v);
    hi[i] = h;
    lo[i] = __float2half(v - __half2float(h));
}

__global__ void wsplit4_kernel(const float* __restrict__ Wq, const float* __restrict__ Wk,
                               const float* __restrict__ Wv, const float* __restrict__ Ws) {
    const float* W; __half *hi, *lo;
    switch (blockIdx.y) {
        case 0: W = Wq; hi = g_wtq_hi; lo = g_wtq_lo; break;
        case 1: W = Wk; hi = g_wtk_hi; lo = g_wtk_lo; break;
        case 2: W = Wv; hi = g_wtv_hi; lo = g_wtv_lo; break;
        default: W = Ws; hi = g_wts_hi; lo = g_wts_lo; break;
    }
    int i = blockIdx.x * blockDim.x + threadIdx.x;
    if (i >= E_ * E_) return;
    int n = i / E_, k = i - n * E_;
    float v = W[(size_t)k * E_ + n];
    __half h = __float2half(v);
    hi[i] = h;
    lo[i] = __float2half(v - __half2float(h));
}

// ---------------- fp16x2 mma.sync GEMM, cp.async double-buffered ------------------
// C = A@W (+bias); A single fp16 [*,K] row-major; B fp16 hi/lo transposed [Ntot][K].
#define GSTR 40
#define GST_ELEMS (128 * GSTR)          // 5120 halves per array
#define STAGE_ELEMS (3 * GST_ELEMS)     // A, Bhi, Blo
#define GEMM_SMEM (2 * STAGE_ELEMS * 2) // 61440 bytes

__device__ void f16_gemm_body(const __half* __restrict__ A,
                              const __half* __restrict__ Bhi,
                              const __half* __restrict__ Blo,
                              const float* __restrict__ bias, float* __restrict__ C,
                              int row0, int K, int Ntot, int col0) {
    extern __shared__ __align__(16) __half smb[];
    uint32_t sbase = smem_u32(smb);
    int tid = threadIdx.x;
    int wid = tid >> 5, lane = tid & 31;
    int wm = wid >> 2, wn = wid & 3, gr = lane >> 2, tg = lane & 3;

    float acc[4][4][4] = {};
    int nch = K >> 5;

    auto issue = [&](int c) {
        int kt = c << 5;
        uint32_t base = sbase + (uint32_t)(c & 1) * (STAGE_ELEMS * 2);
#pragma unroll
        for (int it = 0; it < 2; it++) {
            int idx = it * 256 + tid;
            int row = idx >> 2, g8 = (idx & 3) * 8;
            size_t goff = (size_t)(row0 + row) * K + kt + g8;
            uint32_t d = base + (uint32_t)(row * GSTR + g8) * 2;
            cp16(d, A + goff);
        }
#pragma unroll
        for (int it = 0; it < 2; it++) {
            int idx = it * 256 + tid;
            int n = idx >> 2, g8 = (idx & 3) * 8;
            size_t goff = (size_t)(col0 + n) * K + kt + g8;
            uint32_t d = base + (uint32_t)(GST_ELEMS + n * GSTR + g8) * 2;
            cp16(d, Bhi + goff);
            cp16(d + GST_ELEMS * 2, Blo + goff);
        }
        cp_commit();
    };

    issue(0);
    for (int c = 0; c < nch; c++) {
        if (c + 1 < nch) { issue(c + 1); cp_wait<1>(); }
        else             { cp_wait<0>(); }
        __syncthreads();

        const uint32_t* S = reinterpret_cast<const uint32_t*>(smb) + (c & 1) * (STAGE_ELEMS / 2);
        const uint32_t* A32  = S;
        const uint32_t* B32h = S + GST_ELEMS / 2;
        const uint32_t* B32l = S + GST_ELEMS;

#pragma unroll
        for (int ks = 0; ks < 2; ks++) {
            int kb = ks * 8;
            uint32_t af[4][4], bh[4][2], bl[4][2];
#pragma unroll
            for (int mt = 0; mt < 4; mt++) {
                int r = wm * 64 + mt * 16 + gr;
                int o = r * (GSTR / 2) + kb + tg;
                af[mt][0] = A32[o];
                af[mt][1] = A32[o + 8 * (GSTR / 2)];
                af[mt][2] = A32[o + 4];
                af[mt][3] = A32[o + 8 * (GSTR / 2) + 4];
            }
#pragma unroll
            for (int nt = 0; nt < 4; nt++) {
                int n = wn * 32 + nt * 8 + gr;
                int o = n * (GSTR / 2) + kb + tg;
                bh[nt][0] = B32h[o];
                bh[nt][1] = B32h[o + 4];
                bl[nt][0] = B32l[o];
                bl[nt][1] = B32l[o + 4];
            }
#pragma unroll
            for (int mt = 0; mt < 4; mt++)
#pragma unroll
                for (int nt = 0; nt < 4; nt++) {
                    mma_f16(acc[mt][nt], af[mt], bh[nt]);
                    mma_f16(acc[mt][nt], af[mt], bl[nt]);
                }
        }
        __syncthreads();
    }

#pragma unroll
    for (int mt = 0; mt < 4; mt++) {
#pragma unroll
        for (int nt = 0; nt < 4; nt++) {
            int row = row0 + wm * 64 + mt * 16 + gr;
            int col = col0 + wn * 32 + nt * 8 + 2 * tg;
            float b0 = 0.f, b1 = 0.f;
            if (bias) { b0 = bias[col]; b1 = bias[col + 1]; }
            float2 o0 = {acc[mt][nt][0] + b0, acc[mt][nt][1] + b1};
            float2 o1 = {acc[mt][nt][2] + b0, acc[mt][nt][3] + b1};
            *(float2*)&C[(size_t)row * Ntot + col] = o0;
            *(float2*)&C[(size_t)(row + 8) * Ntot + col] = o1;
        }
    }
}

__global__ __launch_bounds__(256, 2) void f16_gemm_qkvs(
    const __half* __restrict__ A,
    const float* __restrict__ bq, float* __restrict__ Cq,
    const float* __restrict__ bk, float* __restrict__ Ck,
    const float* __restrict__ bv, float* __restrict__ Cv,
    const float* __restrict__ bs, float* __restrict__ Cs) {
    const __half *Bh, *Bl; const float* bias; float* C;
    switch (blockIdx.y) {
        case 0: Bh = g_wtq_hi; Bl = g_wtq_lo; bias = bq; C = Cq; break;
        case 1: Bh = g_wtk_hi; Bl = g_wtk_lo; bias = bk; C = Ck; break;
        case 2: Bh = g_wtv_hi; Bl = g_wtv_lo; bias = bv; C = Cv; break;
        default: Bh = g_wts_hi; Bl = g_wts_lo; bias = bs; C = Cs; break;
    }
    f16_gemm_body(A, Bh, Bl, bias, C, blockIdx.x * 128, E_, E_, 0);
}

__global__ __launch_bounds__(256, 2) void f16_gemm(
    const __half* __restrict__ A, const __half* __restrict__ Bhi,
    const __half* __restrict__ Blo, float* __restrict__ C, int K, int Ntot) {
    f16_gemm_body(A, Bhi, Blo, nullptr, C, blockIdx.x * 128, K, Ntot, blockIdx.y * 128);
}

// ---------------- CSR build ----------------
__global__ void zero_deg_kernel() {
    int i = blockIdx.x * blockDim.x + threadIdx.x;
    if (i < NM_) g_deg_m[i] = 0;
    if (i < NO_) g_deg_o[i] = 0;
}
__global__ void count_kernel(const int* __restrict__ dst, int* __restrict__ deg, int ne) {
    int e = blockIdx.x * blockDim.x + threadIdx.x;
    if (e < ne) atomicAdd(&deg[dst[e]], 1);
}
__global__ void scan_local_kernel(const int* __restrict__ deg, int* __restrict__ off,
                                  int* __restrict__ bsum) {
    __shared__ int ws[8];
    int tid = threadIdx.x;
    int base = blockIdx.x * 1024 + tid * 4;
    int4 d = *(const int4*)&deg[base];
    int s = d.x + d.y + d.z + d.w;
    int lane = tid & 31, wid = tid >> 5;
    int v = s;
#pragma unroll
    for (int o = 1; o < 32; o <<= 1) {
        int t = __shfl_up_sync(0xffffffffu, v, o);
        if (lane >= o) v += t;
    }
    if (lane == 31) ws[wid] = v;
    __syncthreads();
    if (tid == 0) {
        int run = 0;
#pragma unroll
        for (int w = 0; w < 8; w++) { int t = ws[w]; ws[w] = run; run += t; }
    }
    __syncthreads();
    int excl = v - s + ws[wid];
    int4 o4;
    o4.x = excl;
    o4.y = excl + d.x;
    o4.z = o4.y + d.y;
    o4.w = o4.z + d.z;
    *(int4*)&off[base] = o4;
    if (tid == 255) bsum[blockIdx.x] = excl + s;
}
__global__ void scan_bsums_kernel(int* __restrict__ bsum, int nb, int* __restrict__ off, int n) {
    __shared__ int sh[128];
    int tid = threadIdx.x;
    int val = (tid < nb) ? bsum[tid] : 0;
    sh[tid] = val;
    __syncthreads();
    int acc = val;
    for (int o = 1; o < 128; o <<= 1) {
        int t = (tid >= o) ? sh[tid - o] : 0;
        __syncthreads();
        acc += t;
        sh[tid] = acc;
        __syncthreads();
    }
    if (tid < nb) bsum[tid] = acc - val;
    if (tid == 127) off[n] = sh[127];
}
__global__ void scan_add_kernel(int* __restrict__ off, int* __restrict__ pos,
                                const int* __restrict__ bsum, int n) {
    int i = blockIdx.x * blockDim.x + threadIdx.x;
    if (i < n) {
        int v = off[i] + bsum[i >> 10];
        off[i] = v;
        pos[i] = v;
    }
}
__global__ void scatter_kernel(const int* __restrict__ src, const int* __restrict__ dst,
                               int* __restrict__ pos, int* __restrict__ csr, int ne) {
    int e = blockIdx.x * blockDim.x + threadIdx.x;
    if (e < ne) {
        int t = dst[e];
        int slot = atomicAdd(&pos[t], 1);
        csr[slot] = src[e];
    }
}
__global__ void dinv_kernel() {
    int i = blockIdx.x * blockDim.x + threadIdx.x;
    if (i < NO_) g_dinv[i] = rsqrtf((float)(g_deg_o[i] + 1));
}

// ---------------- masked mean (fp32 out) ----------------
__global__ void masked_mean4_kernel(const int* __restrict__ tok,
                                    const float* __restrict__ table,
                                    float* __restrict__ out, int L) {
    __shared__ int ts[4][64];
    int warp = threadIdx.x >> 5, lane = threadIdx.x & 31;
    int n = blockIdx.x * 4 + warp;
    for (int j = lane; j < L; j += 32) ts[warp][j] = tok[n * L + j];
    __syncwarp();
    const float4* t4 = (const float4*)table;
    float4 acc = {0.f, 0.f, 0.f, 0.f};
    int cnt = 0;
    for (int j = 0; j < L; j++) {
        int t = ts[warp][j];
        if (t != 0) {
            float4 e = t4[(size_t)t * 32 + lane];
            acc.x += e.x; acc.y += e.y; acc.z += e.z; acc.w += e.w;
            cnt++;
        }
    }
    float inv = 1.f / (float)(cnt > 1 ? cnt : 1);
    float4 o = {acc.x * inv, acc.y * inv, acc.z * inv, acc.w * inv};
    ((float4*)out)[(size_t)n * 32 + lane] = o;
}

// ---------------- masked mean (fp16 out) ----------------
__global__ void masked_mean4_f16_kernel(const int* __restrict__ tok,
                                        const float* __restrict__ table,
                                        __half* __restrict__ outh, int L) {
    __shared__ int ts[4][64];
    int warp = threadIdx.x >> 5, lane = threadIdx.x & 31;
    int n = blockIdx.x * 4 + warp;
    for (int j = lane; j < L; j += 32) ts[warp][j] = tok[n * L + j];
    __syncwarp();
    const float4* t4 = (const float4*)table;
    float4 acc = {0.f, 0.f, 0.f, 0.f};
    int cnt = 0;
    for (int j = 0; j < L; j++) {
        int t = ts[warp][j];
        if (t != 0) {
            float4 e = t4[(size_t)t * 32 + lane];
            acc.x += e.x; acc.y += e.y; acc.z += e.z; acc.w += e.w;
            cnt++;
        }
    }
    float inv = 1.f / (float)(cnt > 1 ? cnt : 1);
    float4 o = {acc.x * inv, acc.y * inv, acc.z * inv, acc.w * inv};
    h4_store(outh, ((size_t)n * 32 + lane) * 4, o);
}

// ---------------- fused attn + global-attention-8 + (.,+stmt)*0.5 -----------------
__global__ __launch_bounds__(256) void attn_gattn8_kernel(const float* __restrict__ Wg,
                                                          const float* __restrict__ bg) {
    __shared__ float sh_rows[8][132];
    __shared__ float sh_gate[8];
    int tid = threadIdx.x;
    int warp = tid >> 5, lane = tid & 31;
    int n = blockIdx.x;
    int t = n * 8 + warp;

    const float4* q4 = (const float4*)g_q;
    const float4* k4 = (const float4*)g_k;
    const float4* v4 = (const float4*)g_v;
    float4 qv = q4[(size_t)t * 32 + lane];
    float m = -1e30f, ss = 0.f;
    float4 acc = {0.f, 0.f, 0.f, 0.f};
    int beg = g_off_m[t], end = g_off_m[t + 1];
    for (int i = beg; i < end; i++) {
        int s = g_csr_m[i];
        float4 kv = k4[(size_t)s * 32 + lane];
        float p = qv.x * kv.x + qv.y * kv.y + qv.z * kv.z + qv.w * kv.w;
        p += __shfl_xor_sync(0xffffffffu, p, 1);
        p += __shfl_xor_sync(0xffffffffu, p, 2);
        float sc = p * 0.25f;
        float mn = fmaxf(m, sc);
        float scale = __expf(m - mn);
        float w = __expf(sc - mn);
        float4 vv = v4[(size_t)s * 32 + lane];
        ss = ss * scale + w;
        acc.x = acc.x * scale + w * vv.x;
        acc.y = acc.y * scale + w * vv.y;
        acc.z = acc.z * scale + w * vv.z;
        acc.w = acc.w * scale + w * vv.w;
        m = mn;
    }
    float inv = 1.f / (ss + 1e-16f);
    float4 h = ((const float4*)g_hidden)[(size_t)t * 32 + lane];
    h.x += acc.x * inv; h.y += acc.y * inv;
    h.z += acc.z * inv; h.w += acc.w * inv;

    float4 wg = ((const float4*)Wg)[lane];
    float p = h.x * wg.x + h.y * wg.y + h.z * wg.z + h.w * wg.w;
#pragma unroll
    for (int off = 16; off; off >>= 1) p += __shfl_xor_sync(0xffffffffu, p, off);

    *(float4*)&sh_rows[warp][lane * 4] = h;
    if (lane == 0) sh_gate[warp] = p + bg[0];
    __syncthreads();

    if (tid < E_) {
        float gm = sh_gate[0];
#pragma unroll
        for (int j = 1; j < 8; j++) gm = fmaxf(gm, sh_gate[j]);
        float e[8], s = 0.f;
#pragma unroll
        for (int j = 0; j < 8; j++) { e[j] = __expf(sh_gate[j] - gm); s += e[j]; }
        float is = 1.f / (s + 1e-16f);
        float o = 0.f;
#pragma unroll
        for (int j = 0; j < 8; j++) o += e[j] * is * sh_rows[j][tid];
        float res = (o + g_stmt[(size_t)n * E_ + tid]) * 0.5f;
        g_mfn_h[(size_t)n * E_ + tid] = __float2half(res);
    }
}

// ---------------- GCN gather -> relu + fp16 ----------------
__global__ void gcn_gather_f16_kernel(const float* __restrict__ xw,
                                      const float* __restrict__ bias,
                                      __half* __restrict__ outh, int Mv4) {
    int warp = threadIdx.x >> 5, lane = threadIdx.x & 31;
    int t = blockIdx.x * 8 + warp;
    float di = g_dinv[t];
    int beg = g_off_o[t], end = g_off_o[t + 1];
    const float4* x4 = (const float4*)xw;
    for (int c = lane; c < Mv4; c += 32) {
        float4 a = x4[(size_t)t * Mv4 + c];
        float4 bv = ((const float4*)bias)[c];
        float d2 = di * di;
        float4 acc = {a.x * d2 + bv.x, a.y * d2 + bv.y, a.z * d2 + bv.z, a.w * d2 + bv.w};
        for (int i = beg; i < end; i++) {
            int s = g_csr_o[i];
            float nr = g_dinv[s] * di;
            float4 x = x4[(size_t)s * Mv4 + c];
            acc.x += nr * x.x; acc.y += nr * x.y;
            acc.z += nr * x.z; acc.w += nr * x.w;
        }
        acc.x = fmaxf(acc.x, 0.f); acc.y = fmaxf(acc.y, 0.f);
        acc.z = fmaxf(acc.z, 0.f); acc.w = fmaxf(acc.w, 0.f);
        h4_store(outh, ((size_t)t * Mv4 + c) * 4, acc);
    }
}

// ---------------- GCN gather -> fp32 ----------------
__global__ void gcn_gather_kernel(const float* __restrict__ xw, const float* __restrict__ bias,
                                  float* __restrict__ out, int Mv4) {
    int warp = threadIdx.x >> 5, lane = threadIdx.x & 31;
    int t = blockIdx.x * 8 + warp;
    float di = g_dinv[t];
    int beg = g_off_o[t], end = g_off_o[t + 1];
    const float4* x4 = (const float4*)xw;
    for (int c = lane; c < Mv4; c += 32) {
        float4 a = x4[(size_t)t * Mv4 + c];
        float4 bv = ((const float4*)bias)[c];
        float d2 = di * di;
        float4 acc = {a.x * d2 + bv.x, a.y * d2 + bv.y, a.z * d2 + bv.z, a.w * d2 + bv.w};
        for (int i = beg; i < end; i++) {
            int s = g_csr_o[i];
            float nr = g_dinv[s] * di;
            float4 x = x4[(size_t)s * Mv4 + c];
            acc.x += nr * x.x; acc.y += nr * x.y;
            acc.z += nr * x.z; acc.w += nr * x.w;
        }
        ((float4*)out)[(size_t)t * Mv4 + c] = acc;
    }
}

// ---------------- fused global attention (segments of 40) + cosine ----------------
__global__ void gattn40_cos_kernel(const float* __restrict__ Wg, const float* __restrict__ bg,
                                   float* __restrict__ out) {
    __shared__ float gate[40];
    __shared__ float alpha[40];
    __shared__ float ms[2];
    __shared__ float red[3][4];
    int b = blockIdx.x;
    int tid = threadIdx.x;  // 128
    int warp = tid >> 5, lane = tid & 31;
    float4 wg = ((const float4*)Wg)[lane];
    for (int j = warp; j < 40; j += 4) {
        float4 xv = ((const float4*)g_fs)[(size_t)(b * 40 + j) * 32 + lane];
        float p = xv.x * wg.x + xv.y * wg.y + xv.z * wg.z + xv.w * wg.w;
#pragma unroll
        for (int off = 16; off; off >>= 1) p += __shfl_xor_sync(0xffffffffu, p, off);
        if (lane == 0) gate[j] = p + bg[0];
    }
    __syncthreads();
    if (tid == 0) {
        float m = gate[0];
        for (int j = 1; j < 40; j++) m = fmaxf(m, gate[j]);
        float s = 0.f;
        for (int j = 0; j < 40; j++) s += __expf(gate[j] - m);
        ms[0] = m; ms[1] = s;
    }
    __syncthreads();
    if (tid < 40) alpha[tid] = __expf(gate[tid] - ms[0]) / (ms[1] + 1e-16f);
    __syncthreads();
    float f = 0.f;
    for (int j = 0; j < 40; j++)
        f += alpha[j] * g_fs[(size_t)(b * 40 + j) * E_ + tid];
    float hh = g_hn[(size_t)b * E_ + tid];
    float dt = f * hh, na = f * f, nb = hh * hh;
#pragma unroll
    for (int off = 16; off; off >>= 1) {
        dt += __shfl_xor_sync(0xffffffffu, dt, off);
        na += __shfl_xor_sync(0xffffffffu, na, off);
        nb += __shfl_xor_sync(0xffffffffu, nb, off);
    }
    if (lane == 0) { red[0][warp] = dt; red[1][warp] = na; red[2][warp] = nb; }
    __syncthreads();
    if (tid == 0) {
        float d = red[0][0] + red[0][1] + red[0][2] + red[0][3];
        float a = red[1][0] + red[1][1] + red[1][2] + red[1][3];
        float c = red[2][0] + red[2][1] + red[2][2] + red[2][3];
        out[b] = d / (fmaxf(sqrtf(a), 1e-8f) * fmaxf(sqrtf(c), 1e-8f));
    }
}

// ---------------- launch (stream DAG inside graph capture) ----------------
extern "C" void kernel_launch(void* const* d_in, const int* in_sizes, int n_in,
                              void* d_out, int out_size) {
    const int* desc_tokens = (const int*)d_in[0];
    const int* x_tokens    = (const int*)d_in[1];
    const int* mini_tokens = (const int*)d_in[2];
    const int* src         = (const int*)d_in[3];
    const int* dst         = (const int*)d_in[4];
    const int* mini_src    = (const int*)d_in[5];
    const int* mini_dst    = (const int*)d_in[6];
    const float* desc_table  = (const float*)d_in[9];
    const float* code_table  = (const float*)d_in[10];
    const float* code_table2 = (const float*)d_in[11];
    const float* Wq = (const float*)d_in[12]; const float* bq = (const float*)d_in[13];
    const float* Wk = (const float*)d_in[14]; const float* bk = (const float*)d_in[15];
    const float* Wv = (const float*)d_in[16]; const float* bv = (const float*)d_in[17];
    const float* Wskip = (const float*)d_in[18]; const float* bskip = (const float*)d_in[19];
    const float* W2 = (const float*)d_in[20]; const float* b2 = (const float*)d_in[21];
    const float* W3 = (const float*)d_in[22]; const float* b3 = (const float*)d_in[23];
    const float* Wg = (const float*)d_in[24]; const float* bg = (const float*)d_in[25];
    float* out = (float*)d_out;

    float *p_q, *p_k, *p_v, *p_hidden, *p_hn, *p_stmt, *p_xw1, *p_xw2, *p_fs;
    cudaGetSymbolAddress((void**)&p_q, g_q);
    cudaGetSymbolAddress((void**)&p_k, g_k);
    cudaGetSymbolAddress((void**)&p_v, g_v);
    cudaGetSymbolAddress((void**)&p_hidden, g_hidden);
    cudaGetSymbolAddress((void**)&p_hn, g_hn);
    cudaGetSymbolAddress((void**)&p_stmt, g_stmt);
    cudaGetSymbolAddress((void**)&p_xw1, g_xw1);
    cudaGetSymbolAddress((void**)&p_xw2, g_xw2);
    cudaGetSymbolAddress((void**)&p_fs, g_fs);

    __half *p_mini_h, *p_mfn_h, *p_gc1_h;
    __half *p_w2t_hi, *p_w2t_lo, *p_w3t_hi, *p_w3t_lo;
    cudaGetSymbolAddress((void**)&p_mini_h, g_mini_h);
    cudaGetSymbolAddress((void**)&p_mfn_h, g_mfn_h);
    cudaGetSymbolAddress((void**)&p_gc1_h, g_gc1_h);
    cudaGetSymbolAddress((void**)&p_w2t_hi, g_w2t_hi);
    cudaGetSymbolAddress((void**)&p_w2t_lo, g_w2t_lo);
    cudaGetSymbolAddress((void**)&p_w3t_hi, g_w3t_hi);
    cudaGetSymbolAddress((void**)&p_w3t_lo, g_w3t_lo);

    int *p_deg_m, *p_off_m, *p_pos_m, *p_csr_m, *p_bsum_m;
    int *p_deg_o, *p_off_o, *p_pos_o, *p_csr_o, *p_bsum_o;
    cudaGetSymbolAddress((void**)&p_deg_m, g_deg_m);
    cudaGetSymbolAddress((void**)&p_off_m, g_off_m);
    cudaGetSymbolAddress((void**)&p_pos_m, g_pos_m);
    cudaGetSymbolAddress((void**)&p_csr_m, g_csr_m);
    cudaGetSymbolAddress((void**)&p_bsum_m, g_bsum_m);
    cudaGetSymbolAddress((void**)&p_deg_o, g_deg_o);
    cudaGetSymbolAddress((void**)&p_off_o, g_off_o);
    cudaGetSymbolAddress((void**)&p_pos_o, g_pos_o);
    cudaGetSymbolAddress((void**)&p_csr_o, g_csr_o);
    cudaGetSymbolAddress((void**)&p_bsum_o, g_bsum_o);

    cudaFuncSetAttribute(f16_gemm_qkvs, cudaFuncAttributeMaxDynamicSharedMemorySize, GEMM_SMEM);
    cudaFuncSetAttribute(f16_gemm, cudaFuncAttributeMaxDynamicSharedMemorySize, GEMM_SMEM);

    static cudaStream_t s1 = nullptr, s2 = nullptr;
    static cudaEvent_t e_root = nullptr, e_csrm = nullptr, e_csro = nullptr,
                       e_ws = nullptr, e_emb2 = nullptr;
    if (!s1) {
        cudaStreamCreateWithFlags(&s1, cudaStreamNonBlocking);
        cudaStreamCreateWithFlags(&s2, cudaStreamNonBlocking);
        cudaEventCreateWithFlags(&e_root, cudaEventDisableTiming);
        cudaEventCreateWithFlags(&e_csrm, cudaEventDisableTiming);
        cudaEventCreateWithFlags(&e_csro, cudaEventDisableTiming);
        cudaEventCreateWithFlags(&e_ws, cudaEventDisableTiming);
        cudaEventCreateWithFlags(&e_emb2, cudaEventDisableTiming);
    }

    cudaEventRecord(e_root, 0);
    cudaStreamWaitEvent(s1, e_root, 0);
    cudaStreamWaitEvent(s2, e_root, 0);

    // ---- s1: CSR builds ----
    zero_deg_kernel<<<(NM_ + 255) / 256, 256, 0, s1>>>();
    count_kernel<<<(EM_ + 255) / 256, 256, 0, s1>>>(mini_dst, p_deg_m, EM_);
    count_kernel<<<(EO_ + 255) / 256, 256, 0, s1>>>(dst, p_deg_o, EO_);
    scan_local_kernel<<<NM_ / 1024, 256, 0, s1>>>(p_deg_m, p_off_m, p_bsum_m);
    scan_bsums_kernel<<<1, 128, 0, s1>>>(p_bsum_m, NM_ / 1024, p_off_m, NM_);
    scan_add_kernel<<<NM_ / 256, 256, 0, s1>>>(p_off_m, p_pos_m, p_bsum_m, NM_);
    scatter_kernel<<<(EM_ + 255) / 256, 256, 0, s1>>>(mini_src, mini_dst, p_pos_m, p_csr_m, EM_);
    cudaEventRecord(e_csrm, s1);
    scan_local_kernel<<<NO_ / 1024, 256, 0, s1>>>(p_deg_o, p_off_o, p_bsum_o);
    scan_bsums_kernel<<<1, 128, 0, s1>>>(p_bsum_o, NO_ / 1024, p_off_o, NO_);
    scan_add_kernel<<<NO_ / 256, 256, 0, s1>>>(p_off_o, p_pos_o, p_bsum_o, NO_);
    dinv_kernel<<<(NO_ + 255) / 256, 256, 0, s1>>>();
    scatter_kernel<<<(EO_ + 255) / 256, 256, 0, s1>>>(src, dst, p_pos_o, p_csr_o, EO_);
    cudaEventRecord(e_csro, s1);

    // ---- s2: weight splits + secondary embeddings ----
    {
        dim3 g((E_ * E_ + 255) / 256, 4);
        wsplit4_kernel<<<g, 256, 0, s2>>>(Wq, Wk, Wv, Wskip);
    }
    wsplit_kernel<<<(E_ * HID_ + 255) / 256, 256, 0, s2>>>(W2, p_w2t_hi, p_w2t_lo, E_, HID_);
    wsplit_kernel<<<(HID_ * E_ + 255) / 256, 256, 0, s2>>>(W3, p_w3t_hi, p_w3t_lo, HID_, E_);
    cudaEventRecord(e_ws, s2);
    masked_mean4_kernel<<<NO_ / 4, 128, 0, s2>>>(x_tokens, code_table2, p_stmt, LO_);
    masked_mean4_kernel<<<B_ / 4, 128, 0, s2>>>(desc_tokens, desc_table, p_hn, LD_);
    cudaEventRecord(e_emb2, s2);

    // ---- main stream: critical path ----
    masked_mean4_f16_kernel<<<NM_ / 4, 128>>>(mini_tokens, code_table, p_mini_h, LM_);

    cudaStreamWaitEvent(0, e_ws, 0);
    {
        dim3 grid(NM_ / 128, 4);
        f16_gemm_qkvs<<<grid, 256, GEMM_SMEM>>>(p_mini_h,
                                                bq, p_q, bk, p_k, bv, p_v, bskip, p_hidden);
    }

    cudaStreamWaitEvent(0, e_csrm, 0);
    cudaStreamWaitEvent(0, e_emb2, 0);
    attn_gattn8_kernel<<<NO_, 256>>>(Wg, bg);

    {
        dim3 grid(NO_ / 128, HID_ / 128);
        f16_gemm<<<grid, 256, GEMM_SMEM>>>(p_mfn_h, p_w2t_hi, p_w2t_lo, p_xw1, E_, HID_);
    }
    cudaStreamWaitEvent(0, e_csro, 0);
    gcn_gather_f16_kernel<<<NO_ / 8, 256>>>(p_xw1, b2, p_gc1_h, HID_ / 4);

    {
        dim3 grid(NO_ / 128, E_ / 128);
        f16_gemm<<<grid, 256, GEMM_SMEM>>>(p_gc1_h, p_w3t_hi, p_w3t_lo, p_xw2, HID_, E_);
    }
    gcn_gather_kernel<<<NO_ / 8, 256>>>(p_xw2, b3, p_fs, E_ / 4);

    gattn40_cos_kernel<<<B_, E_>>>(Wg, bg, out);
    (void)in_sizes; (void)n_in; (void)out_size;
}

// round 14
// speedup vs baseline: 1.2416x; 1.1108x over previous
#include <cuda_runtime.h>
#include <cuda_fp16.h>
#include <cstdint>

#define B_   256
#define LD_  64
#define NO_  10240
#define LO_  32
#define NM_  81920
#define LM_  16
#define EO_  81920
#define EM_  327680
#define E_   128
#define HID_ 256
#define H_   8
#define Dh_  16

// ---------------- scratch ----------------
__device__ float g_hn[B_ * E_];
__device__ float g_stmt[NO_ * E_];
__device__ float g_q[NM_ * E_];
__device__ float g_k[NM_ * E_];
__device__ float g_v[NM_ * E_];
__device__ float g_hidden[NM_ * E_];    // skip (QKVS output); read-only in fused attn
__device__ float g_dinv[NO_];
__device__ float g_xw1[NO_ * HID_];
__device__ float g_xw2[NO_ * E_];
__device__ float g_fs[NO_ * E_];

// fp16 operand buffers (single precision both sides)
__device__ __align__(16) __half g_mini_h[NM_ * E_];
__device__ __align__(16) __half g_mfn_h[NO_ * E_];
__device__ __align__(16) __half g_gc1_h[NO_ * HID_];
__device__ __align__(16) __half g_wtq[E_ * E_];
__device__ __align__(16) __half g_wtk[E_ * E_];
__device__ __align__(16) __half g_wtv[E_ * E_];
__device__ __align__(16) __half g_wts[E_ * E_];
__device__ __align__(16) __half g_w2t[HID_ * E_];
__device__ __align__(16) __half g_w3t[E_ * HID_];

__device__ int g_deg_m[NM_];
__device__ int g_off_m[NM_ + 1];
__device__ int g_pos_m[NM_];
__device__ int g_csr_m[EM_];
__device__ int g_bsum_m[256];
__device__ int g_deg_o[NO_];
__device__ int g_off_o[NO_ + 1];
__device__ int g_pos_o[NO_];
__device__ int g_csr_o[EO_];
__device__ int g_bsum_o[256];

// ---------------- helpers ----------------
__device__ __forceinline__ uint32_t smem_u32(const void* p) {
    uint32_t a;
    asm("{ .reg .u64 t; cvta.to.shared.u64 t, %1; cvt.u32.u64 %0, t; }" : "=r"(a) : "l"(p));
    return a;
}
__device__ __forceinline__ void cp16(uint32_t dst, const void* src) {
    asm volatile("cp.async.cg.shared.global [%0], [%1], 16;" :: "r"(dst), "l"(src));
}
__device__ __forceinline__ void cp_commit() {
    asm volatile("cp.async.commit_group;" ::: "memory");
}
template <int N>
__device__ __forceinline__ void cp_wait() {
    asm volatile("cp.async.wait_group %0;" :: "n"(N) : "memory");
}
__device__ __forceinline__ void mma_f16(float* d, const uint32_t* a, const uint32_t* b) {
    asm volatile(
        "mma.sync.aligned.m16n8k16.row.col.f32.f16.f16.f32 "
        "{%0,%1,%2,%3}, {%4,%5,%6,%7}, {%8,%9}, {%0,%1,%2,%3};"
        : "+f"(d[0]), "+f"(d[1]), "+f"(d[2]), "+f"(d[3])
        : "r"(a[0]), "r"(a[1]), "r"(a[2]), "r"(a[3]), "r"(b[0]), "r"(b[1]));
}

__device__ __forceinline__ void h4_store(__half* dst, size_t base, float4 v) {
    __half2 p0 = __floats2half2_rn(v.x, v.y);
    __half2 p1 = __floats2half2_rn(v.z, v.w);
    uint2 val = {*(uint32_t*)&p0, *(uint32_t*)&p1};
    *(uint2*)(dst + base) = val;
}

// ---------------- weight transpose (fp16) ----------------
__global__ void wsplit_kernel(const float* __restrict__ W, __half* __restrict__ outh,
                              int K, int N) {
    int i = blockIdx.x * blockDim.x + threadIdx.x;
    if (i >= K * N) return;
    int n = i / K, k = i - n * K;
    outh[i] = __float2half(W[(size_t)k * N + n]);
}

__global__ void wsplit4_kernel(const float* __restrict__ Wq, const float* __restrict__ Wk,
                               const float* __restrict__ Wv, const float* __restrict__ Ws) {
    const float* W; __half* outh;
    switch (blockIdx.y) {
        case 0: W = Wq; outh = g_wtq; break;
        case 1: W = Wk; outh = g_wtk; break;
        case 2: W = Wv; outh = g_wtv; break;
        default: W = Ws; outh = g_wts; break;
    }
    int i = blockIdx.x * blockDim.x + threadIdx.x;
    if (i >= E_ * E_) return;
    int n = i / E_, k = i - n * E_;
    outh[i] = __float2half(W[(size_t)k * E_ + n]);
}

// ---------------- fp16 mma.sync GEMM, cp.async double-buffered --------------------
#define GSTR 40
#define GST_ELEMS (128 * GSTR)          // 5120 halves per array
#define STAGE_ELEMS (2 * GST_ELEMS)     // A, B
#define GEMM_SMEM (2 * STAGE_ELEMS * 2) // 40960 bytes

__device__ void f16_gemm_body(const __half* __restrict__ A,
                              const __half* __restrict__ Bt,
                              const float* __restrict__ bias, float* __restrict__ C,
                              int row0, int K, int Ntot, int col0) {
    extern __shared__ __align__(16) __half smb[];
    uint32_t sbase = smem_u32(smb);
    int tid = threadIdx.x;
    int wid = tid >> 5, lane = tid & 31;
    int wm = wid >> 2, wn = wid & 3, gr = lane >> 2, tg = lane & 3;

    float acc[4][4][4] = {};
    int nch = K >> 5;

    auto issue = [&](int c) {
        int kt = c << 5;
        uint32_t base = sbase + (uint32_t)(c & 1) * (STAGE_ELEMS * 2);
#pragma unroll
        for (int it = 0; it < 2; it++) {
            int idx = it * 256 + tid;
            int row = idx >> 2, g8 = (idx & 3) * 8;
            size_t goff = (size_t)(row0 + row) * K + kt + g8;
            cp16(base + (uint32_t)(row * GSTR + g8) * 2, A + goff);
        }
#pragma unroll
        for (int it = 0; it < 2; it++) {
            int idx = it * 256 + tid;
            int n = idx >> 2, g8 = (idx & 3) * 8;
            size_t goff = (size_t)(col0 + n) * K + kt + g8;
            cp16(base + (uint32_t)(GST_ELEMS + n * GSTR + g8) * 2, Bt + goff);
        }
        cp_commit();
    };

    issue(0);
    for (int c = 0; c < nch; c++) {
        if (c + 1 < nch) { issue(c + 1); cp_wait<1>(); }
        else             { cp_wait<0>(); }
        __syncthreads();

        const uint32_t* S = reinterpret_cast<const uint32_t*>(smb) + (c & 1) * (STAGE_ELEMS / 2);
        const uint32_t* A32 = S;
        const uint32_t* B32 = S + GST_ELEMS / 2;

#pragma unroll
        for (int ks = 0; ks < 2; ks++) {
            int kb = ks * 8;
            uint32_t af[4][4], bf[4][2];
#pragma unroll
            for (int mt = 0; mt < 4; mt++) {
                int r = wm * 64 + mt * 16 + gr;
                int o = r * (GSTR / 2) + kb + tg;
                af[mt][0] = A32[o];
                af[mt][1] = A32[o + 8 * (GSTR / 2)];
                af[mt][2] = A32[o + 4];
                af[mt][3] = A32[o + 8 * (GSTR / 2) + 4];
            }
#pragma unroll
            for (int nt = 0; nt < 4; nt++) {
                int n = wn * 32 + nt * 8 + gr;
                int o = n * (GSTR / 2) + kb + tg;
                bf[nt][0] = B32[o];
                bf[nt][1] = B32[o + 4];
            }
#pragma unroll
            for (int mt = 0; mt < 4; mt++)
#pragma unroll
                for (int nt = 0; nt < 4; nt++)
                    mma_f16(acc[mt][nt], af[mt], bf[nt]);
        }
        __syncthreads();
    }

#pragma unroll
    for (int mt = 0; mt < 4; mt++) {
#pragma unroll
        for (int nt = 0; nt < 4; nt++) {
            int row = row0 + wm * 64 + mt * 16 + gr;
            int col = col0 + wn * 32 + nt * 8 + 2 * tg;
            float b0 = 0.f, b1 = 0.f;
            if (bias) { b0 = bias[col]; b1 = bias[col + 1]; }
            float2 o0 = {acc[mt][nt][0] + b0, acc[mt][nt][1] + b1};
            float2 o1 = {acc[mt][nt][2] + b0, acc[mt][nt][3] + b1};
            *(float2*)&C[(size_t)row * Ntot + col] = o0;
            *(float2*)&C[(size_t)(row + 8) * Ntot + col] = o1;
        }
    }
}

__global__ __launch_bounds__(256, 2) void f16_gemm_qkvs(
    const __half* __restrict__ A,
    const float* __restrict__ bq, float* __restrict__ Cq,
    const float* __restrict__ bk, float* __restrict__ Ck,
    const float* __restrict__ bv, float* __restrict__ Cv,
    const float* __restrict__ bs, float* __restrict__ Cs) {
    const __half* Bt; const float* bias; float* C;
    switch (blockIdx.y) {
        case 0: Bt = g_wtq; bias = bq; C = Cq; break;
        case 1: Bt = g_wtk; bias = bk; C = Ck; break;
        case 2: Bt = g_wtv; bias = bv; C = Cv; break;
        default: Bt = g_wts; bias = bs; C = Cs; break;
    }
    f16_gemm_body(A, Bt, bias, C, blockIdx.x * 128, E_, E_, 0);
}

__global__ __launch_bounds__(256, 2) void f16_gemm(
    const __half* __restrict__ A, const __half* __restrict__ Bt,
    float* __restrict__ C, int K, int Ntot) {
    f16_gemm_body(A, Bt, nullptr, C, blockIdx.x * 128, K, Ntot, blockIdx.y * 128);
}

// ---------------- CSR build ----------------
__global__ void zero_deg_kernel() {
    int i = blockIdx.x * blockDim.x + threadIdx.x;
    if (i < NM_) g_deg_m[i] = 0;
    if (i < NO_) g_deg_o[i] = 0;
}
__global__ void count_kernel(const int* __restrict__ dst, int* __restrict__ deg, int ne) {
    int e = blockIdx.x * blockDim.x + threadIdx.x;
    if (e < ne) atomicAdd(&deg[dst[e]], 1);
}
__global__ void scan_local_kernel(const int* __restrict__ deg, int* __restrict__ off,
                                  int* __restrict__ bsum) {
    __shared__ int ws[8];
    int tid = threadIdx.x;
    int base = blockIdx.x * 1024 + tid * 4;
    int4 d = *(const int4*)&deg[base];
    int s = d.x + d.y + d.z + d.w;
    int lane = tid & 31, wid = tid >> 5;
    int v = s;
#pragma unroll
    for (int o = 1; o < 32; o <<= 1) {
        int t = __shfl_up_sync(0xffffffffu, v, o);
        if (lane >= o) v += t;
    }
    if (lane == 31) ws[wid] = v;
    __syncthreads();
    if (tid == 0) {
        int run = 0;
#pragma unroll
        for (int w = 0; w < 8; w++) { int t = ws[w]; ws[w] = run; run += t; }
    }
    __syncthreads();
    int excl = v - s + ws[wid];
    int4 o4;
    o4.x = excl;
    o4.y = excl + d.x;
    o4.z = o4.y + d.y;
    o4.w = o4.z + d.z;
    *(int4*)&off[base] = o4;
    if (tid == 255) bsum[blockIdx.x] = excl + s;
}
__global__ void scan_bsums_kernel(int* __restrict__ bsum, int nb, int* __restrict__ off, int n) {
    __shared__ int sh[128];
    int tid = threadIdx.x;
    int val = (tid < nb) ? bsum[tid] : 0;
    sh[tid] = val;
    __syncthreads();
    int acc = val;
    for (int o = 1; o < 128; o <<= 1) {
        int t = (tid >= o) ? sh[tid - o] : 0;
        __syncthreads();
        acc += t;
        sh[tid] = acc;
        __syncthreads();
    }
    if (tid < nb) bsum[tid] = acc - val;
    if (tid == 127) off[n] = sh[127];
}
__global__ void scan_add_kernel(int* __restrict__ off, int* __restrict__ pos,
                                const int* __restrict__ bsum, int n) {
    int i = blockIdx.x * blockDim.x + threadIdx.x;
    if (i < n) {
        int v = off[i] + bsum[i >> 10];
        off[i] = v;
        pos[i] = v;
    }
}
__global__ void scatter_kernel(const int* __restrict__ src, const int* __restrict__ dst,
                               int* __restrict__ pos, int* __restrict__ csr, int ne) {
    int e = blockIdx.x * blockDim.x + threadIdx.x;
    if (e < ne) {
        int t = dst[e];
        int slot = atomicAdd(&pos[t], 1);
        csr[slot] = src[e];
    }
}
__global__ void dinv_kernel() {
    int i = blockIdx.x * blockDim.x + threadIdx.x;
    if (i < NO_) g_dinv[i] = rsqrtf((float)(g_deg_o[i] + 1));
}

// ---------------- masked mean (fp32 out) ----------------
__global__ void masked_mean4_kernel(const int* __restrict__ tok,
                                    const float* __restrict__ table,
                                    float* __restrict__ out, int L) {
    __shared__ int ts[4][64];
    int warp = threadIdx.x >> 5, lane = threadIdx.x & 31;
    int n = blockIdx.x * 4 + warp;
    for (int j = lane; j < L; j += 32) ts[warp][j] = tok[n * L + j];
    __syncwarp();
    const float4* t4 = (const float4*)table;
    float4 acc = {0.f, 0.f, 0.f, 0.f};
    int cnt = 0;
    for (int j = 0; j < L; j++) {
        int t = ts[warp][j];
        if (t != 0) {
            float4 e = t4[(size_t)t * 32 + lane];
            acc.x += e.x; acc.y += e.y; acc.z += e.z; acc.w += e.w;
            cnt++;
        }
    }
    float inv = 1.f / (float)(cnt > 1 ? cnt : 1);
    float4 o = {acc.x * inv, acc.y * inv, acc.z * inv, acc.w * inv};
    ((float4*)out)[(size_t)n * 32 + lane] = o;
}

// ---------------- masked mean (fp16 out) ----------------
__global__ void masked_mean4_f16_kernel(const int* __restrict__ tok,
                                        const float* __restrict__ table,
                                        __half* __restrict__ outh, int L) {
    __shared__ int ts[4][64];
    int warp = threadIdx.x >> 5, lane = threadIdx.x & 31;
    int n = blockIdx.x * 4 + warp;
    for (int j = lane; j < L; j += 32) ts[warp][j] = tok[n * L + j];
    __syncwarp();
    const float4* t4 = (const float4*)table;
    float4 acc = {0.f, 0.f, 0.f, 0.f};
    int cnt = 0;
    for (int j = 0; j < L; j++) {
        int t = ts[warp][j];
        if (t != 0) {
            float4 e = t4[(size_t)t * 32 + lane];
            acc.x += e.x; acc.y += e.y; acc.z += e.z; acc.w += e.w;
            cnt++;
        }
    }
    float inv = 1.f / (float)(cnt > 1 ? cnt : 1);
    float4 o = {acc.x * inv, acc.y * inv, acc.z * inv, acc.w * inv};
    h4_store(outh, ((size_t)n * 32 + lane) * 4, o);
}

// ---------------- fused attn + global-attention-8 + (.,+stmt)*0.5 -----------------
__global__ __launch_bounds__(256) void attn_gattn8_kernel(const float* __restrict__ Wg,
                                                          const float* __restrict__ bg) {
    __shared__ float sh_rows[8][132];
    __shared__ float sh_gate[8];
    int tid = threadIdx.x;
    int warp = tid >> 5, lane = tid & 31;
    int n = blockIdx.x;
    int t = n * 8 + warp;

    const float4* q4 = (const float4*)g_q;
    const float4* k4 = (const float4*)g_k;
    const float4* v4 = (const float4*)g_v;
    float4 qv = q4[(size_t)t * 32 + lane];
    float m = -1e30f, ss = 0.f;
    float4 acc = {0.f, 0.f, 0.f, 0.f};
    int beg = g_off_m[t], end = g_off_m[t + 1];
    for (int i = beg; i < end; i++) {
        int s = g_csr_m[i];
        float4 kv = k4[(size_t)s * 32 + lane];
        float p = qv.x * kv.x + qv.y * kv.y + qv.z * kv.z + qv.w * kv.w;
        p += __shfl_xor_sync(0xffffffffu, p, 1);
        p += __shfl_xor_sync(0xffffffffu, p, 2);
        float sc = p * 0.25f;
        float mn = fmaxf(m, sc);
        float scale = __expf(m - mn);
        float w = __expf(sc - mn);
        float4 vv = v4[(size_t)s * 32 + lane];
        ss = ss * scale + w;
        acc.x = acc.x * scale + w * vv.x;
        acc.y = acc.y * scale + w * vv.y;
        acc.z = acc.z * scale + w * vv.z;
        acc.w = acc.w * scale + w * vv.w;
        m = mn;
    }
    float inv = 1.f / (ss + 1e-16f);
    float4 h = ((const float4*)g_hidden)[(size_t)t * 32 + lane];
    h.x += acc.x * inv; h.y += acc.y * inv;
    h.z += acc.z * inv; h.w += acc.w * inv;

    float4 wg = ((const float4*)Wg)[lane];
    float p = h.x * wg.x + h.y * wg.y + h.z * wg.z + h.w * wg.w;
#pragma unroll
    for (int off = 16; off; off >>= 1) p += __shfl_xor_sync(0xffffffffu, p, off);

    *(float4*)&sh_rows[warp][lane * 4] = h;
    if (lane == 0) sh_gate[warp] = p + bg[0];
    __syncthreads();

    if (tid < E_) {
        float gm = sh_gate[0];
#pragma unroll
        for (int j = 1; j < 8; j++) gm = fmaxf(gm, sh_gate[j]);
        float e[8], s = 0.f;
#pragma unroll
        for (int j = 0; j < 8; j++) { e[j] = __expf(sh_gate[j] - gm); s += e[j]; }
        float is = 1.f / (s + 1e-16f);
        float o = 0.f;
#pragma unroll
        for (int j = 0; j < 8; j++) o += e[j] * is * sh_rows[j][tid];
        float res = (o + g_stmt[(size_t)n * E_ + tid]) * 0.5f;
        g_mfn_h[(size_t)n * E_ + tid] = __float2half(res);
    }
}

// ---------------- GCN gather -> relu + fp16 ----------------
__global__ void gcn_gather_f16_kernel(const float* __restrict__ xw,
                                      const float* __restrict__ bias,
                                      __half* __restrict__ outh, int Mv4) {
    int warp = threadIdx.x >> 5, lane = threadIdx.x & 31;
    int t = blockIdx.x * 8 + warp;
    float di = g_dinv[t];
    int beg = g_off_o[t], end = g_off_o[t + 1];
    const float4* x4 = (const float4*)xw;
    for (int c = lane; c < Mv4; c += 32) {
        float4 a = x4[(size_t)t * Mv4 + c];
        float4 bv = ((const float4*)bias)[c];
        float d2 = di * di;
        float4 acc = {a.x * d2 + bv.x, a.y * d2 + bv.y, a.z * d2 + bv.z, a.w * d2 + bv.w};
        for (int i = beg; i < end; i++) {
            int s = g_csr_o[i];
            float nr = g_dinv[s] * di;
            float4 x = x4[(size_t)s * Mv4 + c];
            acc.x += nr * x.x; acc.y += nr * x.y;
            acc.z += nr * x.z; acc.w += nr * x.w;
        }
        acc.x = fmaxf(acc.x, 0.f); acc.y = fmaxf(acc.y, 0.f);
        acc.z = fmaxf(acc.z, 0.f); acc.w = fmaxf(acc.w, 0.f);
        h4_store(outh, ((size_t)t * Mv4 + c) * 4, acc);
    }
}

// ---------------- GCN gather -> fp32 ----------------
__global__ void gcn_gather_kernel(const float* __restrict__ xw, const float* __restrict__ bias,
                                  float* __restrict__ out, int Mv4) {
    int warp = threadIdx.x >> 5, lane = threadIdx.x & 31;
    int t = blockIdx.x * 8 + warp;
    float di = g_dinv[t];
    int beg = g_off_o[t], end = g_off_o[t + 1];
    const float4* x4 = (const float4*)xw;
    for (int c = lane; c < Mv4; c += 32) {
        float4 a = x4[(size_t)t * Mv4 + c];
        float4 bv = ((const float4*)bias)[c];
        float d2 = di * di;
        float4 acc = {a.x * d2 + bv.x, a.y * d2 + bv.y, a.z * d2 + bv.z, a.w * d2 + bv.w};
        for (int i = beg; i < end; i++) {
            int s = g_csr_o[i];
            float nr = g_dinv[s] * di;
            float4 x = x4[(size_t)s * Mv4 + c];
            acc.x += nr * x.x; acc.y += nr * x.y;
            acc.z += nr * x.z; acc.w += nr * x.w;
        }
        ((float4*)out)[(size_t)t * Mv4 + c] = acc;
    }
}

// ---------------- fused global attention (segments of 40) + cosine ----------------
__global__ void gattn40_cos_kernel(const float* __restrict__ Wg, const float* __restrict__ bg,
                                   float* __restrict__ out) {
    __shared__ float gate[40];
    __shared__ float alpha[40];
    __shared__ float ms[2];
    __shared__ float red[3][4];
    int b = blockIdx.x;
    int tid = threadIdx.x;  // 128
    int warp = tid >> 5, lane = tid & 31;
    float4 wg = ((const float4*)Wg)[lane];
    for (int j = warp; j < 40; j += 4) {
        float4 xv = ((const float4*)g_fs)[(size_t)(b * 40 + j) * 32 + lane];
        float p = xv.x * wg.x + xv.y * wg.y + xv.z * wg.z + xv.w * wg.w;
#pragma unroll
        for (int off = 16; off; off >>= 1) p += __shfl_xor_sync(0xffffffffu, p, off);
        if (lane == 0) gate[j] = p + bg[0];
    }
    __syncthreads();
    if (tid == 0) {
        float m = gate[0];
        for (int j = 1; j < 40; j++) m = fmaxf(m, gate[j]);
        float s = 0.f;
        for (int j = 0; j < 40; j++) s += __expf(gate[j] - m);
        ms[0] = m; ms[1] = s;
    }
    __syncthreads();
    if (tid < 40) alpha[tid] = __expf(gate[tid] - ms[0]) / (ms[1] + 1e-16f);
    __syncthreads();
    float f = 0.f;
    for (int j = 0; j < 40; j++)
        f += alpha[j] * g_fs[(size_t)(b * 40 + j) * E_ + tid];
    float hh = g_hn[(size_t)b * E_ + tid];
    float dt = f * hh, na = f * f, nb = hh * hh;
#pragma unroll
    for (int off = 16; off; off >>= 1) {
        dt += __shfl_xor_sync(0xffffffffu, dt, off);
        na += __shfl_xor_sync(0xffffffffu, na, off);
        nb += __shfl_xor_sync(0xffffffffu, nb, off);
    }
    if (lane == 0) { red[0][warp] = dt; red[1][warp] = na; red[2][warp] = nb; }
    __syncthreads();
    if (tid == 0) {
        float d = red[0][0] + red[0][1] + red[0][2] + red[0][3];
        float a = red[1][0] + red[1][1] + red[1][2] + red[1][3];
        float c = red[2][0] + red[2][1] + red[2][2] + red[2][3];
        out[b] = d / (fmaxf(sqrtf(a), 1e-8f) * fmaxf(sqrtf(c), 1e-8f));
    }
}

// ---------------- launch (stream DAG inside graph capture) ----------------
extern "C" void kernel_launch(void* const* d_in, const int* in_sizes, int n_in,
                              void* d_out, int out_size) {
    const int* desc_tokens = (const int*)d_in[0];
    const int* x_tokens    = (const int*)d_in[1];
    const int* mini_tokens = (const int*)d_in[2];
    const int* src         = (const int*)d_in[3];
    const int* dst         = (const int*)d_in[4];
    const int* mini_src    = (const int*)d_in[5];
    const int* mini_dst    = (const int*)d_in[6];
    const float* desc_table  = (const float*)d_in[9];
    const float* code_table  = (const float*)d_in[10];
    const float* code_table2 = (const float*)d_in[11];
    const float* Wq = (const float*)d_in[12]; const float* bq = (const float*)d_in[13];
    const float* Wk = (const float*)d_in[14]; const float* bk = (const float*)d_in[15];
    const float* Wv = (const float*)d_in[16]; const float* bv = (const float*)d_in[17];
    const float* Wskip = (const float*)d_in[18]; const float* bskip = (const float*)d_in[19];
    const float* W2 = (const float*)d_in[20]; const float* b2 = (const float*)d_in[21];
    const float* W3 = (const float*)d_in[22]; const float* b3 = (const float*)d_in[23];
    const float* Wg = (const float*)d_in[24]; const float* bg = (const float*)d_in[25];
    float* out = (float*)d_out;

    float *p_q, *p_k, *p_v, *p_hidden, *p_hn, *p_stmt, *p_xw1, *p_xw2, *p_fs;
    cudaGetSymbolAddress((void**)&p_q, g_q);
    cudaGetSymbolAddress((void**)&p_k, g_k);
    cudaGetSymbolAddress((void**)&p_v, g_v);
    cudaGetSymbolAddress((void**)&p_hidden, g_hidden);
    cudaGetSymbolAddress((void**)&p_hn, g_hn);
    cudaGetSymbolAddress((void**)&p_stmt, g_stmt);
    cudaGetSymbolAddress((void**)&p_xw1, g_xw1);
    cudaGetSymbolAddress((void**)&p_xw2, g_xw2);
    cudaGetSymbolAddress((void**)&p_fs, g_fs);

    __half *p_mini_h, *p_mfn_h, *p_gc1_h, *p_w2t, *p_w3t;
    cudaGetSymbolAddress((void**)&p_mini_h, g_mini_h);
    cudaGetSymbolAddress((void**)&p_mfn_h, g_mfn_h);
    cudaGetSymbolAddress((void**)&p_gc1_h, g_gc1_h);
    cudaGetSymbolAddress((void**)&p_w2t, g_w2t);
    cudaGetSymbolAddress((void**)&p_w3t, g_w3t);

    int *p_deg_m, *p_off_m, *p_pos_m, *p_csr_m, *p_bsum_m;
    int *p_deg_o, *p_off_o, *p_pos_o, *p_csr_o, *p_bsum_o;
    cudaGetSymbolAddress((void**)&p_deg_m, g_deg_m);
    cudaGetSymbolAddress((void**)&p_off_m, g_off_m);
    cudaGetSymbolAddress((void**)&p_pos_m, g_pos_m);
    cudaGetSymbolAddress((void**)&p_csr_m, g_csr_m);
    cudaGetSymbolAddress((void**)&p_bsum_m, g_bsum_m);
    cudaGetSymbolAddress((void**)&p_deg_o, g_deg_o);
    cudaGetSymbolAddress((void**)&p_off_o, g_off_o);
    cudaGetSymbolAddress((void**)&p_pos_o, g_pos_o);
    cudaGetSymbolAddress((void**)&p_csr_o, g_csr_o);
    cudaGetSymbolAddress((void**)&p_bsum_o, g_bsum_o);

    cudaFuncSetAttribute(f16_gemm_qkvs, cudaFuncAttributeMaxDynamicSharedMemorySize, GEMM_SMEM);
    cudaFuncSetAttribute(f16_gemm, cudaFuncAttributeMaxDynamicSharedMemorySize, GEMM_SMEM);

    static cudaStream_t s1 = nullptr, s2 = nullptr;
    static cudaEvent_t e_root = nullptr, e_csrm = nullptr, e_csro = nullptr,
                       e_ws = nullptr, e_emb2 = nullptr;
    if (!s1) {
        cudaStreamCreateWithFlags(&s1, cudaStreamNonBlocking);
        cudaStreamCreateWithFlags(&s2, cudaStreamNonBlocking);
        cudaEventCreateWithFlags(&e_root, cudaEventDisableTiming);
        cudaEventCreateWithFlags(&e_csrm, cudaEventDisableTiming);
        cudaEventCreateWithFlags(&e_csro, cudaEventDisableTiming);
        cudaEventCreateWithFlags(&e_ws, cudaEventDisableTiming);
        cudaEventCreateWithFlags(&e_emb2, cudaEventDisableTiming);
    }

    cudaEventRecord(e_root, 0);
    cudaStreamWaitEvent(s1, e_root, 0);
    cudaStreamWaitEvent(s2, e_root, 0);

    // ---- s1: CSR builds ----
    zero_deg_kernel<<<(NM_ + 255) / 256, 256, 0, s1>>>();
    count_kernel<<<(EM_ + 255) / 256, 256, 0, s1>>>(mini_dst, p_deg_m, EM_);
    count_kernel<<<(EO_ + 255) / 256, 256, 0, s1>>>(dst, p_deg_o, EO_);
    scan_local_kernel<<<NM_ / 1024, 256, 0, s1>>>(p_deg_m, p_off_m, p_bsum_m);
    scan_bsums_kernel<<<1, 128, 0, s1>>>(p_bsum_m, NM_ / 1024, p_off_m, NM_);
    scan_add_kernel<<<NM_ / 256, 256, 0, s1>>>(p_off_m, p_pos_m, p_bsum_m, NM_);
    scatter_kernel<<<(EM_ + 255) / 256, 256, 0, s1>>>(mini_src, mini_dst, p_pos_m, p_csr_m, EM_);
    cudaEventRecord(e_csrm, s1);
    scan_local_kernel<<<NO_ / 1024, 256, 0, s1>>>(p_deg_o, p_off_o, p_bsum_o);
    scan_bsums_kernel<<<1, 128, 0, s1>>>(p_bsum_o, NO_ / 1024, p_off_o, NO_);
    scan_add_kernel<<<NO_ / 256, 256, 0, s1>>>(p_off_o, p_pos_o, p_bsum_o, NO_);
    dinv_kernel<<<(NO_ + 255) / 256, 256, 0, s1>>>();
    scatter_kernel<<<(EO_ + 255) / 256, 256, 0, s1>>>(src, dst, p_pos_o, p_csr_o, EO_);
    cudaEventRecord(e_csro, s1);

    // ---- s2: weight transposes + secondary embeddings ----
    {
        dim3 g((E_ * E_ + 255) / 256, 4);
        wsplit4_kernel<<<g, 256, 0, s2>>>(Wq, Wk, Wv, Wskip);
    }
    wsplit_kernel<<<(E_ * HID_ + 255) / 256, 256, 0, s2>>>(W2, p_w2t, E_, HID_);
    wsplit_kernel<<<(HID_ * E_ + 255) / 256, 256, 0, s2>>>(W3, p_w3t, HID_, E_);
    cudaEventRecord(e_ws, s2);
    masked_mean4_kernel<<<NO_ / 4, 128, 0, s2>>>(x_tokens, code_table2, p_stmt, LO_);
    masked_mean4_kernel<<<B_ / 4, 128, 0, s2>>>(desc_tokens, desc_table, p_hn, LD_);
    cudaEventRecord(e_emb2, s2);

    // ---- main stream: critical path ----
    masked_mean4_f16_kernel<<<NM_ / 4, 128>>>(mini_tokens, code_table, p_mini_h, LM_);

    cudaStreamWaitEvent(0, e_ws, 0);
    {
        dim3 grid(NM_ / 128, 4);
        f16_gemm_qkvs<<<grid, 256, GEMM_SMEM>>>(p_mini_h,
                                                bq, p_q, bk, p_k, bv, p_v, bskip, p_hidden);
    }

    cudaStreamWaitEvent(0, e_csrm, 0);
    cudaStreamWaitEvent(0, e_emb2, 0);
    attn_gattn8_kernel<<<NO_, 256>>>(Wg, bg);

    {
        dim3 grid(NO_ / 128, HID_ / 128);
        f16_gemm<<<grid, 256, GEMM_SMEM>>>(p_mfn_h, p_w2t, p_xw1, E_, HID_);
    }
    cudaStreamWaitEvent(0, e_csro, 0);
    gcn_gather_f16_kernel<<<NO_ / 8, 256>>>(p_xw1, b2, p_gc1_h, HID_ / 4);

    {
        dim3 grid(NO_ / 128, E_ / 128);
        f16_gemm<<<grid, 256, GEMM_SMEM>>>(p_gc1_h, p_w3t, p_xw2, HID_, E_);
    }
    gcn_gather_kernel<<<NO_ / 8, 256>>>(p_xw2, b3, p_fs, E_ / 4);

    gattn40_cos_kernel<<<B_, E_>>>(Wg, bg, out);
    (void)in_sizes; (void)n_in; (void)out_size;
}

// round 15
// speedup vs baseline: 1.2517x; 1.0081x over previous
#include <cuda_runtime.h>
#include <cuda_fp16.h>
#include <cstdint>

#define B_   256
#define LD_  64
#define NO_  10240
#define LO_  32
#define NM_  81920
#define LM_  16
#define EO_  81920
#define EM_  327680
#define E_   128
#define HID_ 256
#define H_   8
#define Dh_  16
#define V_   10000

// ---------------- scratch ----------------
__device__ float g_hn[B_ * E_];
__device__ float g_stmt[NO_ * E_];
__device__ float g_q[NM_ * E_];
__device__ float g_k[NM_ * E_];
__device__ float g_v[NM_ * E_];
__device__ float g_hidden[NM_ * E_];    // skip (QKVS output); read-only in fused attn
__device__ float g_dinv[NO_];
__device__ float g_xw1[NO_ * HID_];
__device__ float g_xw2[NO_ * E_];
__device__ float g_fs[NO_ * E_];

// fp16 operand buffers
__device__ __align__(16) __half g_ct_h[V_ * E_];   // fp16 code_table
__device__ __align__(16) __half g_mini_h[NM_ * E_];
__device__ __align__(16) __half g_mfn_h[NO_ * E_];
__device__ __align__(16) __half g_gc1_h[NO_ * HID_];
__device__ __align__(16) __half g_wtq[E_ * E_];
__device__ __align__(16) __half g_wtk[E_ * E_];
__device__ __align__(16) __half g_wtv[E_ * E_];
__device__ __align__(16) __half g_wts[E_ * E_];
__device__ __align__(16) __half g_w2t[HID_ * E_];
__device__ __align__(16) __half g_w3t[E_ * HID_];

__device__ int g_deg_m[NM_];
__device__ int g_off_m[NM_ + 1];
__device__ int g_pos_m[NM_];
__device__ int g_csr_m[EM_];
__device__ int g_bsum_m[256];
__device__ int g_deg_o[NO_];
__device__ int g_off_o[NO_ + 1];
__device__ int g_pos_o[NO_];
__device__ int g_csr_o[EO_];
__device__ int g_bsum_o[256];

// ---------------- helpers ----------------
__device__ __forceinline__ uint32_t smem_u32(const void* p) {
    uint32_t a;
    asm("{ .reg .u64 t; cvta.to.shared.u64 t, %1; cvt.u32.u64 %0, t; }" : "=r"(a) : "l"(p));
    return a;
}
__device__ __forceinline__ void cp16(uint32_t dst, const void* src) {
    asm volatile("cp.async.cg.shared.global [%0], [%1], 16;" :: "r"(dst), "l"(src));
}
__device__ __forceinline__ void cp_commit() {
    asm volatile("cp.async.commit_group;" ::: "memory");
}
template <int N>
__device__ __forceinline__ void cp_wait() {
    asm volatile("cp.async.wait_group %0;" :: "n"(N) : "memory");
}
__device__ __forceinline__ void mma_f16(float* d, const uint32_t* a, const uint32_t* b) {
    asm volatile(
        "mma.sync.aligned.m16n8k16.row.col.f32.f16.f16.f32 "
        "{%0,%1,%2,%3}, {%4,%5,%6,%7}, {%8,%9}, {%0,%1,%2,%3};"
        : "+f"(d[0]), "+f"(d[1]), "+f"(d[2]), "+f"(d[3])
        : "r"(a[0]), "r"(a[1]), "r"(a[2]), "r"(a[3]), "r"(b[0]), "r"(b[1]));
}

__device__ __forceinline__ void h4_store(__half* dst, size_t base, float4 v) {
    __half2 p0 = __floats2half2_rn(v.x, v.y);
    __half2 p1 = __floats2half2_rn(v.z, v.w);
    uint2 val = {*(uint32_t*)&p0, *(uint32_t*)&p1};
    *(uint2*)(dst + base) = val;
}

// ---------------- table fp32 -> fp16 ----------------
__global__ void table2h_kernel(const float* __restrict__ t, __half* __restrict__ th, int n) {
    int i = blockIdx.x * blockDim.x + threadIdx.x;
    if (i < n) {
        float2 v = ((const float2*)t)[i];
        __half2 h = __floats2half2_rn(v.x, v.y);
        ((__half2*)th)[i] = h;
    }
}

// ---------------- weight transpose (fp16) ----------------
__global__ void wsplit_kernel(const float* __restrict__ W, __half* __restrict__ outh,
                              int K, int N) {
    int i = blockIdx.x * blockDim.x + threadIdx.x;
    if (i >= K * N) return;
    int n = i / K, k = i - n * K;
    outh[i] = __float2half(W[(size_t)k * N + n]);
}

__global__ void wsplit4_kernel(const float* __restrict__ Wq, const float* __restrict__ Wk,
                               const float* __restrict__ Wv, const float* __restrict__ Ws) {
    const float* W; __half* outh;
    switch (blockIdx.y) {
        case 0: W = Wq; outh = g_wtq; break;
        case 1: W = Wk; outh = g_wtk; break;
        case 2: W = Wv; outh = g_wtv; break;
        default: W = Ws; outh = g_wts; break;
    }
    int i = blockIdx.x * blockDim.x + threadIdx.x;
    if (i >= E_ * E_) return;
    int n = i / E_, k = i - n * E_;
    outh[i] = __float2half(W[(size_t)k * E_ + n]);
}

// ---------------- fp16 mma.sync GEMM, cp.async double-buffered --------------------
#define GSTR 40
#define GST_ELEMS (128 * GSTR)
#define STAGE_ELEMS (2 * GST_ELEMS)
#define GEMM_SMEM (2 * STAGE_ELEMS * 2)

__device__ void f16_gemm_body(const __half* __restrict__ A,
                              const __half* __restrict__ Bt,
                              const float* __restrict__ bias, float* __restrict__ C,
                              int row0, int K, int Ntot, int col0) {
    extern __shared__ __align__(16) __half smb[];
    uint32_t sbase = smem_u32(smb);
    int tid = threadIdx.x;
    int wid = tid >> 5, lane = tid & 31;
    int wm = wid >> 2, wn = wid & 3, gr = lane >> 2, tg = lane & 3;

    float acc[4][4][4] = {};
    int nch = K >> 5;

    auto issue = [&](int c) {
        int kt = c << 5;
        uint32_t base = sbase + (uint32_t)(c & 1) * (STAGE_ELEMS * 2);
#pragma unroll
        for (int it = 0; it < 2; it++) {
            int idx = it * 256 + tid;
            int row = idx >> 2, g8 = (idx & 3) * 8;
            size_t goff = (size_t)(row0 + row) * K + kt + g8;
            cp16(base + (uint32_t)(row * GSTR + g8) * 2, A + goff);
        }
#pragma unroll
        for (int it = 0; it < 2; it++) {
            int idx = it * 256 + tid;
            int n = idx >> 2, g8 = (idx & 3) * 8;
            size_t goff = (size_t)(col0 + n) * K + kt + g8;
            cp16(base + (uint32_t)(GST_ELEMS + n * GSTR + g8) * 2, Bt + goff);
        }
        cp_commit();
    };

    issue(0);
    for (int c = 0; c < nch; c++) {
        if (c + 1 < nch) { issue(c + 1); cp_wait<1>(); }
        else             { cp_wait<0>(); }
        __syncthreads();

        const uint32_t* S = reinterpret_cast<const uint32_t*>(smb) + (c & 1) * (STAGE_ELEMS / 2);
        const uint32_t* A32 = S;
        const uint32_t* B32 = S + GST_ELEMS / 2;

#pragma unroll
        for (int ks = 0; ks < 2; ks++) {
            int kb = ks * 8;
            uint32_t af[4][4], bf[4][2];
#pragma unroll
            for (int mt = 0; mt < 4; mt++) {
                int r = wm * 64 + mt * 16 + gr;
                int o = r * (GSTR / 2) + kb + tg;
                af[mt][0] = A32[o];
                af[mt][1] = A32[o + 8 * (GSTR / 2)];
                af[mt][2] = A32[o + 4];
                af[mt][3] = A32[o + 8 * (GSTR / 2) + 4];
            }
#pragma unroll
            for (int nt = 0; nt < 4; nt++) {
                int n = wn * 32 + nt * 8 + gr;
                int o = n * (GSTR / 2) + kb + tg;
                bf[nt][0] = B32[o];
                bf[nt][1] = B32[o + 4];
            }
#pragma unroll
            for (int mt = 0; mt < 4; mt++)
#pragma unroll
                for (int nt = 0; nt < 4; nt++)
                    mma_f16(acc[mt][nt], af[mt], bf[nt]);
        }
        __syncthreads();
    }

#pragma unroll
    for (int mt = 0; mt < 4; mt++) {
#pragma unroll
        for (int nt = 0; nt < 4; nt++) {
            int row = row0 + wm * 64 + mt * 16 + gr;
            int col = col0 + wn * 32 + nt * 8 + 2 * tg;
            float b0 = 0.f, b1 = 0.f;
            if (bias) { b0 = bias[col]; b1 = bias[col + 1]; }
            float2 o0 = {acc[mt][nt][0] + b0, acc[mt][nt][1] + b1};
            float2 o1 = {acc[mt][nt][2] + b0, acc[mt][nt][3] + b1};
            *(float2*)&C[(size_t)row * Ntot + col] = o0;
            *(float2*)&C[(size_t)(row + 8) * Ntot + col] = o1;
        }
    }
}

__global__ __launch_bounds__(256, 2) void f16_gemm_qkvs(
    const __half* __restrict__ A,
    const float* __restrict__ bq, float* __restrict__ Cq,
    const float* __restrict__ bk, float* __restrict__ Ck,
    const float* __restrict__ bv, float* __restrict__ Cv,
    const float* __restrict__ bs, float* __restrict__ Cs) {
    const __half* Bt; const float* bias; float* C;
    switch (blockIdx.y) {
        case 0: Bt = g_wtq; bias = bq; C = Cq; break;
        case 1: Bt = g_wtk; bias = bk; C = Ck; break;
        case 2: Bt = g_wtv; bias = bv; C = Cv; break;
        default: Bt = g_wts; bias = bs; C = Cs; break;
    }
    f16_gemm_body(A, Bt, bias, C, blockIdx.x * 128, E_, E_, 0);
}

__global__ __launch_bounds__(256, 2) void f16_gemm(
    const __half* __restrict__ A, const __half* __restrict__ Bt,
    float* __restrict__ C, int K, int Ntot) {
    f16_gemm_body(A, Bt, nullptr, C, blockIdx.x * 128, K, Ntot, blockIdx.y * 128);
}

// ---------------- CSR build ----------------
__global__ void zero_deg_kernel() {
    int i = blockIdx.x * blockDim.x + threadIdx.x;
    if (i < NM_) g_deg_m[i] = 0;
    if (i < NO_) g_deg_o[i] = 0;
}
__global__ void count_kernel(const int* __restrict__ dst, int* __restrict__ deg, int ne) {
    int e = blockIdx.x * blockDim.x + threadIdx.x;
    if (e < ne) atomicAdd(&deg[dst[e]], 1);
}
__global__ void scan_local_kernel(const int* __restrict__ deg, int* __restrict__ off,
                                  int* __restrict__ bsum) {
    __shared__ int ws[8];
    int tid = threadIdx.x;
    int base = blockIdx.x * 1024 + tid * 4;
    int4 d = *(const int4*)&deg[base];
    int s = d.x + d.y + d.z + d.w;
    int lane = tid & 31, wid = tid >> 5;
    int v = s;
#pragma unroll
    for (int o = 1; o < 32; o <<= 1) {
        int t = __shfl_up_sync(0xffffffffu, v, o);
        if (lane >= o) v += t;
    }
    if (lane == 31) ws[wid] = v;
    __syncthreads();
    if (tid == 0) {
        int run = 0;
#pragma unroll
        for (int w = 0; w < 8; w++) { int t = ws[w]; ws[w] = run; run += t; }
    }
    __syncthreads();
    int excl = v - s + ws[wid];
    int4 o4;
    o4.x = excl;
    o4.y = excl + d.x;
    o4.z = o4.y + d.y;
    o4.w = o4.z + d.z;
    *(int4*)&off[base] = o4;
    if (tid == 255) bsum[blockIdx.x] = excl + s;
}
__global__ void scan_bsums_kernel(int* __restrict__ bsum, int nb, int* __restrict__ off, int n) {
    __shared__ int sh[128];
    int tid = threadIdx.x;
    int val = (tid < nb) ? bsum[tid] : 0;
    sh[tid] = val;
    __syncthreads();
    int acc = val;
    for (int o = 1; o < 128; o <<= 1) {
        int t = (tid >= o) ? sh[tid - o] : 0;
        __syncthreads();
        acc += t;
        sh[tid] = acc;
        __syncthreads();
    }
    if (tid < nb) bsum[tid] = acc - val;
    if (tid == 127) off[n] = sh[127];
}
__global__ void scan_add_kernel(int* __restrict__ off, int* __restrict__ pos,
                                const int* __restrict__ bsum, int n) {
    int i = blockIdx.x * blockDim.x + threadIdx.x;
    if (i < n) {
        int v = off[i] + bsum[i >> 10];
        off[i] = v;
        pos[i] = v;
    }
}
__global__ void scatter_kernel(const int* __restrict__ src, const int* __restrict__ dst,
                               int* __restrict__ pos, int* __restrict__ csr, int ne) {
    int e = blockIdx.x * blockDim.x + threadIdx.x;
    if (e < ne) {
        int t = dst[e];
        int slot = atomicAdd(&pos[t], 1);
        csr[slot] = src[e];
    }
}
__global__ void dinv_kernel() {
    int i = blockIdx.x * blockDim.x + threadIdx.x;
    if (i < NO_) g_dinv[i] = rsqrtf((float)(g_deg_o[i] + 1));
}

// ---------------- masked mean (fp32 table, fp32 out) ----------------
__global__ void masked_mean4_kernel(const int* __restrict__ tok,
                                    const float* __restrict__ table,
                                    float* __restrict__ out, int L) {
    __shared__ int ts[4][64];
    int warp = threadIdx.x >> 5, lane = threadIdx.x & 31;
    int n = blockIdx.x * 4 + warp;
    for (int j = lane; j < L; j += 32) ts[warp][j] = tok[n * L + j];
    __syncwarp();
    const float4* t4 = (const float4*)table;
    float4 acc = {0.f, 0.f, 0.f, 0.f};
    int cnt = 0;
    for (int j = 0; j < L; j++) {
        int t = ts[warp][j];
        if (t != 0) {
            float4 e = t4[(size_t)t * 32 + lane];
            acc.x += e.x; acc.y += e.y; acc.z += e.z; acc.w += e.w;
            cnt++;
        }
    }
    float inv = 1.f / (float)(cnt > 1 ? cnt : 1);
    float4 o = {acc.x * inv, acc.y * inv, acc.z * inv, acc.w * inv};
    ((float4*)out)[(size_t)n * 32 + lane] = o;
}

// ---------------- masked mean (fp16 table, fp16 out) ----------------
__global__ void masked_mean4_f16_kernel(const int* __restrict__ tok,
                                        const __half* __restrict__ table,
                                        __half* __restrict__ outh, int L) {
    __shared__ int ts[4][64];
    int warp = threadIdx.x >> 5, lane = threadIdx.x & 31;
    int n = blockIdx.x * 4 + warp;
    for (int j = lane; j < L; j += 32) ts[warp][j] = tok[n * L + j];
    __syncwarp();
    const uint2* t2 = (const uint2*)table;   // 4 halves per uint2; row = 32 uint2
    float4 acc = {0.f, 0.f, 0.f, 0.f};
    int cnt = 0;
    for (int j = 0; j < L; j++) {
        int t = ts[warp][j];
        if (t != 0) {
            uint2 raw = t2[(size_t)t * 32 + lane];
            __half2 h0 = *(__half2*)&raw.x;
            __half2 h1 = *(__half2*)&raw.y;
            float2 f0 = __half22float2(h0);
            float2 f1 = __half22float2(h1);
            acc.x += f0.x; acc.y += f0.y; acc.z += f1.x; acc.w += f1.y;
            cnt++;
        }
    }
    float inv = 1.f / (float)(cnt > 1 ? cnt : 1);
    float4 o = {acc.x * inv, acc.y * inv, acc.z * inv, acc.w * inv};
    h4_store(outh, ((size_t)n * 32 + lane) * 4, o);
}

// ---------------- fused attn + global-attention-8 + (.,+stmt)*0.5 -----------------
__global__ __launch_bounds__(256) void attn_gattn8_kernel(const float* __restrict__ Wg,
                                                          const float* __restrict__ bg) {
    __shared__ float sh_rows[8][132];
    __shared__ float sh_gate[8];
    int tid = threadIdx.x;
    int warp = tid >> 5, lane = tid & 31;
    int n = blockIdx.x;
    int t = n * 8 + warp;

    const float4* q4 = (const float4*)g_q;
    const float4* k4 = (const float4*)g_k;
    const float4* v4 = (const float4*)g_v;
    float4 qv = q4[(size_t)t * 32 + lane];
    float m = -1e30f, ss = 0.f;
    float4 acc = {0.f, 0.f, 0.f, 0.f};
    int beg = g_off_m[t], end = g_off_m[t + 1];
    for (int i = beg; i < end; i++) {
        int s = g_csr_m[i];
        float4 kv = k4[(size_t)s * 32 + lane];
        float p = qv.x * kv.x + qv.y * kv.y + qv.z * kv.z + qv.w * kv.w;
        p += __shfl_xor_sync(0xffffffffu, p, 1);
        p += __shfl_xor_sync(0xffffffffu, p, 2);
        float sc = p * 0.25f;
        float mn = fmaxf(m, sc);
        float scale = __expf(m - mn);
        float w = __expf(sc - mn);
        float4 vv = v4[(size_t)s * 32 + lane];
        ss = ss * scale + w;
        acc.x = acc.x * scale + w * vv.x;
        acc.y = acc.y * scale + w * vv.y;
        acc.z = acc.z * scale + w * vv.z;
        acc.w = acc.w * scale + w * vv.w;
        m = mn;
    }
    float inv = 1.f / (ss + 1e-16f);
    float4 h = ((const float4*)g_hidden)[(size_t)t * 32 + lane];
    h.x += acc.x * inv; h.y += acc.y * inv;
    h.z += acc.z * inv; h.w += acc.w * inv;

    float4 wg = ((const float4*)Wg)[lane];
    float p = h.x * wg.x + h.y * wg.y + h.z * wg.z + h.w * wg.w;
#pragma unroll
    for (int off = 16; off; off >>= 1) p += __shfl_xor_sync(0xffffffffu, p, off);

    *(float4*)&sh_rows[warp][lane * 4] = h;
    if (lane == 0) sh_gate[warp] = p + bg[0];
    __syncthreads();

    if (tid < E_) {
        float gm = sh_gate[0];
#pragma unroll
        for (int j = 1; j < 8; j++) gm = fmaxf(gm, sh_gate[j]);
        float e[8], s = 0.f;
#pragma unroll
        for (int j = 0; j < 8; j++) { e[j] = __expf(sh_gate[j] - gm); s += e[j]; }
        float is = 1.f / (s + 1e-16f);
        float o = 0.f;
#pragma unroll
        for (int j = 0; j < 8; j++) o += e[j] * is * sh_rows[j][tid];
        float res = (o + g_stmt[(size_t)n * E_ + tid]) * 0.5f;
        g_mfn_h[(size_t)n * E_ + tid] = __float2half(res);
    }
}

// ---------------- GCN gather -> relu + fp16 ----------------
__global__ void gcn_gather_f16_kernel(const float* __restrict__ xw,
                                      const float* __restrict__ bias,
                                      __half* __restrict__ outh, int Mv4) {
    int warp = threadIdx.x >> 5, lane = threadIdx.x & 31;
    int t = blockIdx.x * 8 + warp;
    float di = g_dinv[t];
    int beg = g_off_o[t], end = g_off_o[t + 1];
    const float4* x4 = (const float4*)xw;
    for (int c = lane; c < Mv4; c += 32) {
        float4 a = x4[(size_t)t * Mv4 + c];
        float4 bv = ((const float4*)bias)[c];
        float d2 = di * di;
        float4 acc = {a.x * d2 + bv.x, a.y * d2 + bv.y, a.z * d2 + bv.z, a.w * d2 + bv.w};
        for (int i = beg; i < end; i++) {
            int s = g_csr_o[i];
            float nr = g_dinv[s] * di;
            float4 x = x4[(size_t)s * Mv4 + c];
            acc.x += nr * x.x; acc.y += nr * x.y;
            acc.z += nr * x.z; acc.w += nr * x.w;
        }
        acc.x = fmaxf(acc.x, 0.f); acc.y = fmaxf(acc.y, 0.f);
        acc.z = fmaxf(acc.z, 0.f); acc.w = fmaxf(acc.w, 0.f);
        h4_store(outh, ((size_t)t * Mv4 + c) * 4, acc);
    }
}

// ---------------- GCN gather -> fp32 ----------------
__global__ void gcn_gather_kernel(const float* __restrict__ xw, const float* __restrict__ bias,
                                  float* __restrict__ out, int Mv4) {
    int warp = threadIdx.x >> 5, lane = threadIdx.x & 31;
    int t = blockIdx.x * 8 + warp;
    float di = g_dinv[t];
    int beg = g_off_o[t], end = g_off_o[t + 1];
    const float4* x4 = (const float4*)xw;
    for (int c = lane; c < Mv4; c += 32) {
        float4 a = x4[(size_t)t * Mv4 + c];
        float4 bv = ((const float4*)bias)[c];
        float d2 = di * di;
        float4 acc = {a.x * d2 + bv.x, a.y * d2 + bv.y, a.z * d2 + bv.z, a.w * d2 + bv.w};
        for (int i = beg; i < end; i++) {
            int s = g_csr_o[i];
            float nr = g_dinv[s] * di;
            float4 x = x4[(size_t)s * Mv4 + c];
            acc.x += nr * x.x; acc.y += nr * x.y;
            acc.z += nr * x.z; acc.w += nr * x.w;
        }
        ((float4*)out)[(size_t)t * Mv4 + c] = acc;
    }
}

// ---------------- fused global attention (segments of 40) + cosine ----------------
__global__ void gattn40_cos_kernel(const float* __restrict__ Wg, const float* __restrict__ bg,
                                   float* __restrict__ out) {
    __shared__ float gate[40];
    __shared__ float alpha[40];
    __shared__ float ms[2];
    __shared__ float red[3][4];
    int b = blockIdx.x;
    int tid = threadIdx.x;  // 128
    int warp = tid >> 5, lane = tid & 31;
    float4 wg = ((const float4*)Wg)[lane];
    for (int j = warp; j < 40; j += 4) {
        float4 xv = ((const float4*)g_fs)[(size_t)(b * 40 + j) * 32 + lane];
        float p = xv.x * wg.x + xv.y * wg.y + xv.z * wg.z + xv.w * wg.w;
#pragma unroll
        for (int off = 16; off; off >>= 1) p += __shfl_xor_sync(0xffffffffu, p, off);
        if (lane == 0) gate[j] = p + bg[0];
    }
    __syncthreads();
    if (tid == 0) {
        float m = gate[0];
        for (int j = 1; j < 40; j++) m = fmaxf(m, gate[j]);
        float s = 0.f;
        for (int j = 0; j < 40; j++) s += __expf(gate[j] - m);
        ms[0] = m; ms[1] = s;
    }
    __syncthreads();
    if (tid < 40) alpha[tid] = __expf(gate[tid] - ms[0]) / (ms[1] + 1e-16f);
    __syncthreads();
    float f = 0.f;
    for (int j = 0; j < 40; j++)
        f += alpha[j] * g_fs[(size_t)(b * 40 + j) * E_ + tid];
    float hh = g_hn[(size_t)b * E_ + tid];
    float dt = f * hh, na = f * f, nb = hh * hh;
#pragma unroll
    for (int off = 16; off; off >>= 1) {
        dt += __shfl_xor_sync(0xffffffffu, dt, off);
        na += __shfl_xor_sync(0xffffffffu, na, off);
        nb += __shfl_xor_sync(0xffffffffu, nb, off);
    }
    if (lane == 0) { red[0][warp] = dt; red[1][warp] = na; red[2][warp] = nb; }
    __syncthreads();
    if (tid == 0) {
        float d = red[0][0] + red[0][1] + red[0][2] + red[0][3];
        float a = red[1][0] + red[1][1] + red[1][2] + red[1][3];
        float c = red[2][0] + red[2][1] + red[2][2] + red[2][3];
        out[b] = d / (fmaxf(sqrtf(a), 1e-8f) * fmaxf(sqrtf(c), 1e-8f));
    }
}

// ---------------- launch (stream DAG inside graph capture) ----------------
extern "C" void kernel_launch(void* const* d_in, const int* in_sizes, int n_in,
                              void* d_out, int out_size) {
    const int* desc_tokens = (const int*)d_in[0];
    const int* x_tokens    = (const int*)d_in[1];
    const int* mini_tokens = (const int*)d_in[2];
    const int* src         = (const int*)d_in[3];
    const int* dst         = (const int*)d_in[4];
    const int* mini_src    = (const int*)d_in[5];
    const int* mini_dst    = (const int*)d_in[6];
    const float* desc_table  = (const float*)d_in[9];
    const float* code_table  = (const float*)d_in[10];
    const float* code_table2 = (const float*)d_in[11];
    const float* Wq = (const float*)d_in[12]; const float* bq = (const float*)d_in[13];
    const float* Wk = (const float*)d_in[14]; const float* bk = (const float*)d_in[15];
    const float* Wv = (const float*)d_in[16]; const float* bv = (const float*)d_in[17];
    const float* Wskip = (const float*)d_in[18]; const float* bskip = (const float*)d_in[19];
    const float* W2 = (const float*)d_in[20]; const float* b2 = (const float*)d_in[21];
    const float* W3 = (const float*)d_in[22]; const float* b3 = (const float*)d_in[23];
    const float* Wg = (const float*)d_in[24]; const float* bg = (const float*)d_in[25];
    float* out = (float*)d_out;

    float *p_q, *p_k, *p_v, *p_hidden, *p_hn, *p_stmt, *p_xw1, *p_xw2, *p_fs;
    cudaGetSymbolAddress((void**)&p_q, g_q);
    cudaGetSymbolAddress((void**)&p_k, g_k);
    cudaGetSymbolAddress((void**)&p_v, g_v);
    cudaGetSymbolAddress((void**)&p_hidden, g_hidden);
    cudaGetSymbolAddress((void**)&p_hn, g_hn);
    cudaGetSymbolAddress((void**)&p_stmt, g_stmt);
    cudaGetSymbolAddress((void**)&p_xw1, g_xw1);
    cudaGetSymbolAddress((void**)&p_xw2, g_xw2);
    cudaGetSymbolAddress((void**)&p_fs, g_fs);

    __half *p_ct_h, *p_mini_h, *p_mfn_h, *p_gc1_h, *p_w2t, *p_w3t;
    cudaGetSymbolAddress((void**)&p_ct_h, g_ct_h);
    cudaGetSymbolAddress((void**)&p_mini_h, g_mini_h);
    cudaGetSymbolAddress((void**)&p_mfn_h, g_mfn_h);
    cudaGetSymbolAddress((void**)&p_gc1_h, g_gc1_h);
    cudaGetSymbolAddress((void**)&p_w2t, g_w2t);
    cudaGetSymbolAddress((void**)&p_w3t, g_w3t);

    int *p_deg_m, *p_off_m, *p_pos_m, *p_csr_m, *p_bsum_m;
    int *p_deg_o, *p_off_o, *p_pos_o, *p_csr_o, *p_bsum_o;
    cudaGetSymbolAddress((void**)&p_deg_m, g_deg_m);
    cudaGetSymbolAddress((void**)&p_off_m, g_off_m);
    cudaGetSymbolAddress((void**)&p_pos_m, g_pos_m);
    cudaGetSymbolAddress((void**)&p_csr_m, g_csr_m);
    cudaGetSymbolAddress((void**)&p_bsum_m, g_bsum_m);
    cudaGetSymbolAddress((void**)&p_deg_o, g_deg_o);
    cudaGetSymbolAddress((void**)&p_off_o, g_off_o);
    cudaGetSymbolAddress((void**)&p_pos_o, g_pos_o);
    cudaGetSymbolAddress((void**)&p_csr_o, g_csr_o);
    cudaGetSymbolAddress((void**)&p_bsum_o, g_bsum_o);

    cudaFuncSetAttribute(f16_gemm_qkvs, cudaFuncAttributeMaxDynamicSharedMemorySize, GEMM_SMEM);
    cudaFuncSetAttribute(f16_gemm, cudaFuncAttributeMaxDynamicSharedMemorySize, GEMM_SMEM);

    static cudaStream_t s1 = nullptr, s2 = nullptr;
    static cudaEvent_t e_root = nullptr, e_csrm = nullptr, e_csro = nullptr,
                       e_ws = nullptr, e_emb2 = nullptr;
    if (!s1) {
        cudaStreamCreateWithFlags(&s1, cudaStreamNonBlocking);
        cudaStreamCreateWithFlags(&s2, cudaStreamNonBlocking);
        cudaEventCreateWithFlags(&e_root, cudaEventDisableTiming);
        cudaEventCreateWithFlags(&e_csrm, cudaEventDisableTiming);
        cudaEventCreateWithFlags(&e_csro, cudaEventDisableTiming);
        cudaEventCreateWithFlags(&e_ws, cudaEventDisableTiming);
        cudaEventCreateWithFlags(&e_emb2, cudaEventDisableTiming);
    }

    cudaEventRecord(e_root, 0);
    cudaStreamWaitEvent(s1, e_root, 0);
    cudaStreamWaitEvent(s2, e_root, 0);

    // ---- s1: CSR builds ----
    zero_deg_kernel<<<(NM_ + 255) / 256, 256, 0, s1>>>();
    count_kernel<<<(EM_ + 255) / 256, 256, 0, s1>>>(mini_dst, p_deg_m, EM_);
    count_kernel<<<(EO_ + 255) / 256, 256, 0, s1>>>(dst, p_deg_o, EO_);
    scan_local_kernel<<<NM_ / 1024, 256, 0, s1>>>(p_deg_m, p_off_m, p_bsum_m);
    scan_bsums_kernel<<<1, 128, 0, s1>>>(p_bsum_m, NM_ / 1024, p_off_m, NM_);
    scan_add_kernel<<<NM_ / 256, 256, 0, s1>>>(p_off_m, p_pos_m, p_bsum_m, NM_);
    scatter_kernel<<<(EM_ + 255) / 256, 256, 0, s1>>>(mini_src, mini_dst, p_pos_m, p_csr_m, EM_);
    cudaEventRecord(e_csrm, s1);
    scan_local_kernel<<<NO_ / 1024, 256, 0, s1>>>(p_deg_o, p_off_o, p_bsum_o);
    scan_bsums_kernel<<<1, 128, 0, s1>>>(p_bsum_o, NO_ / 1024, p_off_o, NO_);
    scan_add_kernel<<<NO_ / 256, 256, 0, s1>>>(p_off_o, p_pos_o, p_bsum_o, NO_);
    dinv_kernel<<<(NO_ + 255) / 256, 256, 0, s1>>>();
    scatter_kernel<<<(EO_ + 255) / 256, 256, 0, s1>>>(src, dst, p_pos_o, p_csr_o, EO_);
    cudaEventRecord(e_csro, s1);

    // ---- s2: weight transposes + secondary embeddings ----
    {
        dim3 g((E_ * E_ + 255) / 256, 4);
        wsplit4_kernel<<<g, 256, 0, s2>>>(Wq, Wk, Wv, Wskip);
    }
    wsplit_kernel<<<(E_ * HID_ + 255) / 256, 256, 0, s2>>>(W2, p_w2t, E_, HID_);
    wsplit_kernel<<<(HID_ * E_ + 255) / 256, 256, 0, s2>>>(W3, p_w3t, HID_, E_);
    cudaEventRecord(e_ws, s2);
    masked_mean4_kernel<<<NO_ / 4, 128, 0, s2>>>(x_tokens, code_table2, p_stmt, LO_);
    masked_mean4_kernel<<<B_ / 4, 128, 0, s2>>>(desc_tokens, desc_table, p_hn, LD_);
    cudaEventRecord(e_emb2, s2);

    // ---- main stream: critical path ----
    table2h_kernel<<<(V_ * E_ / 2 + 255) / 256, 256>>>(code_table, p_ct_h, V_ * E_ / 2);
    masked_mean4_f16_kernel<<<NM_ / 4, 128>>>(mini_tokens, p_ct_h, p_mini_h, LM_);

    cudaStreamWaitEvent(0, e_ws, 0);
    {
        dim3 grid(NM_ / 128, 4);
        f16_gemm_qkvs<<<grid, 256, GEMM_SMEM>>>(p_mini_h,
                                                bq, p_q, bk, p_k, bv, p_v, bskip, p_hidden);
    }

    cudaStreamWaitEvent(0, e_csrm, 0);
    cudaStreamWaitEvent(0, e_emb2, 0);
    attn_gattn8_kernel<<<NO_, 256>>>(Wg, bg);

    {
        dim3 grid(NO_ / 128, HID_ / 128);
        f16_gemm<<<grid, 256, GEMM_SMEM>>>(p_mfn_h, p_w2t, p_xw1, E_, HID_);
    }
    cudaStreamWaitEvent(0, e_csro, 0);
    gcn_gather_f16_kernel<<<NO_ / 8, 256>>>(p_xw1, b2, p_gc1_h, HID_ / 4);

    {
        dim3 grid(NO_ / 128, E_ / 128);
        f16_gemm<<<grid, 256, GEMM_SMEM>>>(p_gc1_h, p_w3t, p_xw2, HID_, E_);
    }
    gcn_gather_kernel<<<NO_ / 8, 256>>>(p_xw2, b3, p_fs, E_ / 4);

    gattn40_cos_kernel<<<B_, E_>>>(Wg, bg, out);
    (void)in_sizes; (void)n_in; (void)out_size;
}

// round 16
// speedup vs baseline: 1.3031x; 1.0411x over previous
#include <cuda_runtime.h>
#include <cuda_fp16.h>
#include <cstdint>

#define B_   256
#define LD_  64
#define NO_  10240
#define LO_  32
#define NM_  81920
#define LM_  16
#define EO_  81920
#define EM_  327680
#define E_   128
#define HID_ 256
#define H_   8
#define Dh_  16
#define V_   10000

// ---------------- scratch ----------------
__device__ float g_hn[B_ * E_];
__device__ float g_stmt[NO_ * E_];
__device__ float g_q[NM_ * E_];
__device__ float g_k[NM_ * E_];
__device__ float g_v[NM_ * E_];
__device__ float g_hidden[NM_ * E_];
__device__ float g_dinv[NO_];
__device__ float g_xw1[NO_ * HID_];
__device__ float g_xw2[NO_ * E_];
__device__ float g_fs[NO_ * E_];

// fp16 operand buffers
__device__ __align__(16) __half g_ct_h[V_ * E_];
__device__ __align__(16) __half g_mini_h[NM_ * E_];
__device__ __align__(16) __half g_mfn_h[NO_ * E_];
__device__ __align__(16) __half g_gc1_h[NO_ * HID_];
__device__ __align__(16) __half g_wtq[E_ * E_];
__device__ __align__(16) __half g_wtk[E_ * E_];
__device__ __align__(16) __half g_wtv[E_ * E_];
__device__ __align__(16) __half g_wts[E_ * E_];
__device__ __align__(16) __half g_w2t[HID_ * E_];
__device__ __align__(16) __half g_w3t[E_ * HID_];

__device__ int g_deg_m[NM_];
__device__ int g_off_m[NM_ + 1];
__device__ int g_pos_m[NM_];
__device__ int g_csr_m[EM_];
__device__ int g_bsum_m[256];
__device__ int g_deg_o[NO_];
__device__ int g_off_o[NO_ + 1];
__device__ int g_pos_o[NO_];
__device__ int g_csr_o[EO_];
__device__ int g_bsum_o[256];

// ---------------- helpers ----------------
__device__ __forceinline__ uint32_t smem_u32(const void* p) {
    uint32_t a;
    asm("{ .reg .u64 t; cvta.to.shared.u64 t, %1; cvt.u32.u64 %0, t; }" : "=r"(a) : "l"(p));
    return a;
}
__device__ __forceinline__ void cp16(uint32_t dst, const void* src) {
    asm volatile("cp.async.cg.shared.global [%0], [%1], 16;" :: "r"(dst), "l"(src));
}
__device__ __forceinline__ void cp_commit() {
    asm volatile("cp.async.commit_group;" ::: "memory");
}
template <int N>
__device__ __forceinline__ void cp_wait() {
    asm volatile("cp.async.wait_group %0;" :: "n"(N) : "memory");
}
__device__ __forceinline__ void mma_f16(float* d, const uint32_t* a, const uint32_t* b) {
    asm volatile(
        "mma.sync.aligned.m16n8k16.row.col.f32.f16.f16.f32 "
        "{%0,%1,%2,%3}, {%4,%5,%6,%7}, {%8,%9}, {%0,%1,%2,%3};"
        : "+f"(d[0]), "+f"(d[1]), "+f"(d[2]), "+f"(d[3])
        : "r"(a[0]), "r"(a[1]), "r"(a[2]), "r"(a[3]), "r"(b[0]), "r"(b[1]));
}

__device__ __forceinline__ void h4_store(__half* dst, size_t base, float4 v) {
    __half2 p0 = __floats2half2_rn(v.x, v.y);
    __half2 p1 = __floats2half2_rn(v.z, v.w);
    uint2 val = {*(uint32_t*)&p0, *(uint32_t*)&p1};
    *(uint2*)(dst + base) = val;
}

// ---------------- table fp32 -> fp16 ----------------
__global__ void table2h_kernel(const float* __restrict__ t, __half* __restrict__ th, int n) {
    int i = blockIdx.x * blockDim.x + threadIdx.x;
    if (i < n) {
        float2 v = ((const float2*)t)[i];
        __half2 h = __floats2half2_rn(v.x, v.y);
        ((__half2*)th)[i] = h;
    }
}

// ---------------- weight transpose (fp16) ----------------
__global__ void wsplit_kernel(const float* __restrict__ W, __half* __restrict__ outh,
                              int K, int N) {
    int i = blockIdx.x * blockDim.x + threadIdx.x;
    if (i >= K * N) return;
    int n = i / K, k = i - n * K;
    outh[i] = __float2half(W[(size_t)k * N + n]);
}

__global__ void wsplit4_kernel(const float* __restrict__ Wq, const float* __restrict__ Wk,
                               const float* __restrict__ Wv, const float* __restrict__ Ws) {
    const float* W; __half* outh;
    switch (blockIdx.y) {
        case 0: W = Wq; outh = g_wtq; break;
        case 1: W = Wk; outh = g_wtk; break;
        case 2: W = Wv; outh = g_wtv; break;
        default: W = Ws; outh = g_wts; break;
    }
    int i = blockIdx.x * blockDim.x + threadIdx.x;
    if (i >= E_ * E_) return;
    int n = i / E_, k = i - n * E_;
    outh[i] = __float2half(W[(size_t)k * E_ + n]);
}

// ---------------- fp16 mma.sync GEMM, cp.async double-buffered --------------------
#define GSTR 40
#define GST_ELEMS (128 * GSTR)
#define STAGE_ELEMS (2 * GST_ELEMS)
#define GEMM_SMEM (2 * STAGE_ELEMS * 2)

__device__ void f16_gemm_body(const __half* __restrict__ A,
                              const __half* __restrict__ Bt,
                              const float* __restrict__ bias, float* __restrict__ C,
                              int row0, int K, int Ntot, int col0) {
    extern __shared__ __align__(16) __half smb[];
    uint32_t sbase = smem_u32(smb);
    int tid = threadIdx.x;
    int wid = tid >> 5, lane = tid & 31;
    int wm = wid >> 2, wn = wid & 3, gr = lane >> 2, tg = lane & 3;

    float acc[4][4][4] = {};
    int nch = K >> 5;

    auto issue = [&](int c) {
        int kt = c << 5;
        uint32_t base = sbase + (uint32_t)(c & 1) * (STAGE_ELEMS * 2);
#pragma unroll
        for (int it = 0; it < 2; it++) {
            int idx = it * 256 + tid;
            int row = idx >> 2, g8 = (idx & 3) * 8;
            size_t goff = (size_t)(row0 + row) * K + kt + g8;
            cp16(base + (uint32_t)(row * GSTR + g8) * 2, A + goff);
        }
#pragma unroll
        for (int it = 0; it < 2; it++) {
            int idx = it * 256 + tid;
            int n = idx >> 2, g8 = (idx & 3) * 8;
            size_t goff = (size_t)(col0 + n) * K + kt + g8;
            cp16(base + (uint32_t)(GST_ELEMS + n * GSTR + g8) * 2, Bt + goff);
        }
        cp_commit();
    };

    issue(0);
    for (int c = 0; c < nch; c++) {
        if (c + 1 < nch) { issue(c + 1); cp_wait<1>(); }
        else             { cp_wait<0>(); }
        __syncthreads();

        const uint32_t* S = reinterpret_cast<const uint32_t*>(smb) + (c & 1) * (STAGE_ELEMS / 2);
        const uint32_t* A32 = S;
        const uint32_t* B32 = S + GST_ELEMS / 2;

#pragma unroll
        for (int ks = 0; ks < 2; ks++) {
            int kb = ks * 8;
            uint32_t af[4][4], bf[4][2];
#pragma unroll
            for (int mt = 0; mt < 4; mt++) {
                int r = wm * 64 + mt * 16 + gr;
                int o = r * (GSTR / 2) + kb + tg;
                af[mt][0] = A32[o];
                af[mt][1] = A32[o + 8 * (GSTR / 2)];
                af[mt][2] = A32[o + 4];
                af[mt][3] = A32[o + 8 * (GSTR / 2) + 4];
            }
#pragma unroll
            for (int nt = 0; nt < 4; nt++) {
                int n = wn * 32 + nt * 8 + gr;
                int o = n * (GSTR / 2) + kb + tg;
                bf[nt][0] = B32[o];
                bf[nt][1] = B32[o + 4];
            }
#pragma unroll
            for (int mt = 0; mt < 4; mt++)
#pragma unroll
                for (int nt = 0; nt < 4; nt++)
                    mma_f16(acc[mt][nt], af[mt], bf[nt]);
        }
        __syncthreads();
    }

#pragma unroll
    for (int mt = 0; mt < 4; mt++) {
#pragma unroll
        for (int nt = 0; nt < 4; nt++) {
            int row = row0 + wm * 64 + mt * 16 + gr;
            int col = col0 + wn * 32 + nt * 8 + 2 * tg;
            float b0 = 0.f, b1 = 0.f;
            if (bias) { b0 = bias[col]; b1 = bias[col + 1]; }
            float2 o0 = {acc[mt][nt][0] + b0, acc[mt][nt][1] + b1};
            float2 o1 = {acc[mt][nt][2] + b0, acc[mt][nt][3] + b1};
            *(float2*)&C[(size_t)row * Ntot + col] = o0;
            *(float2*)&C[(size_t)(row + 8) * Ntot + col] = o1;
        }
    }
}

__global__ __launch_bounds__(256, 2) void f16_gemm_qkvs(
    const __half* __restrict__ A,
    const float* __restrict__ bq, float* __restrict__ Cq,
    const float* __restrict__ bk, float* __restrict__ Ck,
    const float* __restrict__ bv, float* __restrict__ Cv,
    const float* __restrict__ bs, float* __restrict__ Cs) {
    const __half* Bt; const float* bias; float* C;
    switch (blockIdx.y) {
        case 0: Bt = g_wtq; bias = bq; C = Cq; break;
        case 1: Bt = g_wtk; bias = bk; C = Ck; break;
        case 2: Bt = g_wtv; bias = bv; C = Cv; break;
        default: Bt = g_wts; bias = bs; C = Cs; break;
    }
    f16_gemm_body(A, Bt, bias, C, blockIdx.x * 128, E_, E_, 0);
}

__global__ __launch_bounds__(256, 2) void f16_gemm(
    const __half* __restrict__ A, const __half* __restrict__ Bt,
    float* __restrict__ C, int K, int Ntot) {
    f16_gemm_body(A, Bt, nullptr, C, blockIdx.x * 128, K, Ntot, blockIdx.y * 128);
}

// ---------------- CSR build ----------------
__global__ void zero_deg_kernel() {
    int i = blockIdx.x * blockDim.x + threadIdx.x;
    if (i < NM_) g_deg_m[i] = 0;
    if (i < NO_) g_deg_o[i] = 0;
}
__global__ void count_kernel(const int* __restrict__ dst, int* __restrict__ deg, int ne) {
    int e = blockIdx.x * blockDim.x + threadIdx.x;
    if (e < ne) atomicAdd(&deg[dst[e]], 1);
}
__global__ void scan_local_kernel(const int* __restrict__ deg, int* __restrict__ off,
                                  int* __restrict__ bsum) {
    __shared__ int ws[8];
    int tid = threadIdx.x;
    int base = blockIdx.x * 1024 + tid * 4;
    int4 d = *(const int4*)&deg[base];
    int s = d.x + d.y + d.z + d.w;
    int lane = tid & 31, wid = tid >> 5;
    int v = s;
#pragma unroll
    for (int o = 1; o < 32; o <<= 1) {
        int t = __shfl_up_sync(0xffffffffu, v, o);
        if (lane >= o) v += t;
    }
    if (lane == 31) ws[wid] = v;
    __syncthreads();
    if (tid == 0) {
        int run = 0;
#pragma unroll
        for (int w = 0; w < 8; w++) { int t = ws[w]; ws[w] = run; run += t; }
    }
    __syncthreads();
    int excl = v - s + ws[wid];
    int4 o4;
    o4.x = excl;
    o4.y = excl + d.x;
    o4.z = o4.y + d.y;
    o4.w = o4.z + d.z;
    *(int4*)&off[base] = o4;
    if (tid == 255) bsum[blockIdx.x] = excl + s;
}
__global__ void scan_bsums_kernel(int* __restrict__ bsum, int nb, int* __restrict__ off, int n) {
    __shared__ int sh[128];
    int tid = threadIdx.x;
    int val = (tid < nb) ? bsum[tid] : 0;
    sh[tid] = val;
    __syncthreads();
    int acc = val;
    for (int o = 1; o < 128; o <<= 1) {
        int t = (tid >= o) ? sh[tid - o] : 0;
        __syncthreads();
        acc += t;
        sh[tid] = acc;
        __syncthreads();
    }
    if (tid < nb) bsum[tid] = acc - val;
    if (tid == 127) off[n] = sh[127];
}
__global__ void scan_add_kernel(int* __restrict__ off, int* __restrict__ pos,
                                const int* __restrict__ bsum, int n) {
    int i = blockIdx.x * blockDim.x + threadIdx.x;
    if (i < n) {
        int v = off[i] + bsum[i >> 10];
        off[i] = v;
        pos[i] = v;
    }
}
__global__ void scatter_kernel(const int* __restrict__ src, const int* __restrict__ dst,
                               int* __restrict__ pos, int* __restrict__ csr, int ne) {
    int e = blockIdx.x * blockDim.x + threadIdx.x;
    if (e < ne) {
        int t = dst[e];
        int slot = atomicAdd(&pos[t], 1);
        csr[slot] = src[e];
    }
}
__global__ void dinv_kernel() {
    int i = blockIdx.x * blockDim.x + threadIdx.x;
    if (i < NO_) g_dinv[i] = rsqrtf((float)(g_deg_o[i] + 1));
}

// ---------------- masked mean (fp32 table, fp32 out) — branchless ----------------
__global__ void masked_mean4_kernel(const int* __restrict__ tok,
                                    const float* __restrict__ table,
                                    float* __restrict__ out, int L) {
    __shared__ int ts[4][64];
    int warp = threadIdx.x >> 5, lane = threadIdx.x & 31;
    int n = blockIdx.x * 4 + warp;
    for (int j = lane; j < L; j += 32) ts[warp][j] = tok[n * L + j];
    __syncwarp();
    const float4* t4 = (const float4*)table;
    float4 acc = {0.f, 0.f, 0.f, 0.f};
    int cnt = 0;
#pragma unroll 8
    for (int j = 0; j < L; j++) {
        int t = ts[warp][j];
        float4 e = t4[(size_t)t * 32 + lane];   // unconditional (row 0 valid)
        float msk = (t != 0) ? 1.f : 0.f;
        cnt += (t != 0);
        acc.x += msk * e.x; acc.y += msk * e.y;
        acc.z += msk * e.z; acc.w += msk * e.w;
    }
    float inv = 1.f / (float)(cnt > 1 ? cnt : 1);
    float4 o = {acc.x * inv, acc.y * inv, acc.z * inv, acc.w * inv};
    ((float4*)out)[(size_t)n * 32 + lane] = o;
}

// ---------------- masked mean (fp16 table, fp16 out) — branchless, L=16 -----------
__global__ void masked_mean4_f16_kernel(const int* __restrict__ tok,
                                        const __half* __restrict__ table,
                                        __half* __restrict__ outh) {
    __shared__ int ts[4][16];
    int warp = threadIdx.x >> 5, lane = threadIdx.x & 31;
    int n = blockIdx.x * 4 + warp;
    if (lane < 16) ts[warp][lane] = tok[n * LM_ + lane];
    __syncwarp();
    const uint2* t2 = (const uint2*)table;
    int t[16];
#pragma unroll
    for (int j = 0; j < 16; j++) t[j] = ts[warp][j];
    uint2 raw[16];
#pragma unroll
    for (int j = 0; j < 16; j++)
        raw[j] = t2[(size_t)t[j] * 32 + lane];   // 16 independent loads in flight
    float4 acc = {0.f, 0.f, 0.f, 0.f};
    int cnt = 0;
#pragma unroll
    for (int j = 0; j < 16; j++) {
        float msk = (t[j] != 0) ? 1.f : 0.f;
        cnt += (t[j] != 0);
        __half2 h0 = *(__half2*)&raw[j].x;
        __half2 h1 = *(__half2*)&raw[j].y;
        float2 f0 = __half22float2(h0);
        float2 f1 = __half22float2(h1);
        acc.x += msk * f0.x; acc.y += msk * f0.y;
        acc.z += msk * f1.x; acc.w += msk * f1.y;
    }
    float inv = 1.f / (float)(cnt > 1 ? cnt : 1);
    float4 o = {acc.x * inv, acc.y * inv, acc.z * inv, acc.w * inv};
    h4_store(outh, ((size_t)n * 32 + lane) * 4, o);
}

// ---------------- fused attn + global-attention-8 + (.,+stmt)*0.5 -----------------
__global__ __launch_bounds__(256) void attn_gattn8_kernel(const float* __restrict__ Wg,
                                                          const float* __restrict__ bg) {
    __shared__ float sh_rows[8][132];
    __shared__ float sh_gate[8];
    int tid = threadIdx.x;
    int warp = tid >> 5, lane = tid & 31;
    int n = blockIdx.x;
    int t = n * 8 + warp;

    const float4* q4 = (const float4*)g_q;
    const float4* k4 = (const float4*)g_k;
    const float4* v4 = (const float4*)g_v;
    float4 qv = q4[(size_t)t * 32 + lane];
    float m = -1e30f, ss = 0.f;
    float4 acc = {0.f, 0.f, 0.f, 0.f};
    int beg = g_off_m[t], end = g_off_m[t + 1];
    for (int i = beg; i < end; i++) {
        int s = g_csr_m[i];
        float4 kv = k4[(size_t)s * 32 + lane];
        float p = qv.x * kv.x + qv.y * kv.y + qv.z * kv.z + qv.w * kv.w;
        p += __shfl_xor_sync(0xffffffffu, p, 1);
        p += __shfl_xor_sync(0xffffffffu, p, 2);
        float sc = p * 0.25f;
        float mn = fmaxf(m, sc);
        float scale = __expf(m - mn);
        float w = __expf(sc - mn);
        float4 vv = v4[(size_t)s * 32 + lane];
        ss = ss * scale + w;
        acc.x = acc.x * scale + w * vv.x;
        acc.y = acc.y * scale + w * vv.y;
        acc.z = acc.z * scale + w * vv.z;
        acc.w = acc.w * scale + w * vv.w;
        m = mn;
    }
    float inv = 1.f / (ss + 1e-16f);
    float4 h = ((const float4*)g_hidden)[(size_t)t * 32 + lane];
    h.x += acc.x * inv; h.y += acc.y * inv;
    h.z += acc.z * inv; h.w += acc.w * inv;

    float4 wg = ((const float4*)Wg)[lane];
    float p = h.x * wg.x + h.y * wg.y + h.z * wg.z + h.w * wg.w;
#pragma unroll
    for (int off = 16; off; off >>= 1) p += __shfl_xor_sync(0xffffffffu, p, off);

    *(float4*)&sh_rows[warp][lane * 4] = h;
    if (lane == 0) sh_gate[warp] = p + bg[0];
    __syncthreads();

    if (tid < E_) {
        float gm = sh_gate[0];
#pragma unroll
        for (int j = 1; j < 8; j++) gm = fmaxf(gm, sh_gate[j]);
        float e[8], s = 0.f;
#pragma unroll
        for (int j = 0; j < 8; j++) { e[j] = __expf(sh_gate[j] - gm); s += e[j]; }
        float is = 1.f / (s + 1e-16f);
        float o = 0.f;
#pragma unroll
        for (int j = 0; j < 8; j++) o += e[j] * is * sh_rows[j][tid];
        float res = (o + g_stmt[(size_t)n * E_ + tid]) * 0.5f;
        g_mfn_h[(size_t)n * E_ + tid] = __float2half(res);
    }
}

// ---------------- GCN gather -> relu + fp16 ----------------
__global__ void gcn_gather_f16_kernel(const float* __restrict__ xw,
                                      const float* __restrict__ bias,
                                      __half* __restrict__ outh, int Mv4) {
    int warp = threadIdx.x >> 5, lane = threadIdx.x & 31;
    int t = blockIdx.x * 8 + warp;
    float di = g_dinv[t];
    int beg = g_off_o[t], end = g_off_o[t + 1];
    const float4* x4 = (const float4*)xw;
    for (int c = lane; c < Mv4; c += 32) {
        float4 a = x4[(size_t)t * Mv4 + c];
        float4 bv = ((const float4*)bias)[c];
        float d2 = di * di;
        float4 acc = {a.x * d2 + bv.x, a.y * d2 + bv.y, a.z * d2 + bv.z, a.w * d2 + bv.w};
        for (int i = beg; i < end; i++) {
            int s = g_csr_o[i];
            float nr = g_dinv[s] * di;
            float4 x = x4[(size_t)s * Mv4 + c];
            acc.x += nr * x.x; acc.y += nr * x.y;
            acc.z += nr * x.z; acc.w += nr * x.w;
        }
        acc.x = fmaxf(acc.x, 0.f); acc.y = fmaxf(acc.y, 0.f);
        acc.z = fmaxf(acc.z, 0.f); acc.w = fmaxf(acc.w, 0.f);
        h4_store(outh, ((size_t)t * Mv4 + c) * 4, acc);
    }
}

// ---------------- GCN gather -> fp32 ----------------
__global__ void gcn_gather_kernel(const float* __restrict__ xw, const float* __restrict__ bias,
                                  float* __restrict__ out, int Mv4) {
    int warp = threadIdx.x >> 5, lane = threadIdx.x & 31;
    int t = blockIdx.x * 8 + warp;
    float di = g_dinv[t];
    int beg = g_off_o[t], end = g_off_o[t + 1];
    const float4* x4 = (const float4*)xw;
    for (int c = lane; c < Mv4; c += 32) {
        float4 a = x4[(size_t)t * Mv4 + c];
        float4 bv = ((const float4*)bias)[c];
        float d2 = di * di;
        float4 acc = {a.x * d2 + bv.x, a.y * d2 + bv.y, a.z * d2 + bv.z, a.w * d2 + bv.w};
        for (int i = beg; i < end; i++) {
            int s = g_csr_o[i];
            float nr = g_dinv[s] * di;
            float4 x = x4[(size_t)s * Mv4 + c];
            acc.x += nr * x.x; acc.y += nr * x.y;
            acc.z += nr * x.z; acc.w += nr * x.w;
        }
        ((float4*)out)[(size_t)t * Mv4 + c] = acc;
    }
}

// ---------------- fused global attention (segments of 40) + cosine ----------------
__global__ void gattn40_cos_kernel(const float* __restrict__ Wg, const float* __restrict__ bg,
                                   float* __restrict__ out) {
    __shared__ float gate[40];
    __shared__ float alpha[40];
    __shared__ float ms[2];
    __shared__ float red[3][4];
    int b = blockIdx.x;
    int tid = threadIdx.x;
    int warp = tid >> 5, lane = tid & 31;
    float4 wg = ((const float4*)Wg)[lane];
    for (int j = warp; j < 40; j += 4) {
        float4 xv = ((const float4*)g_fs)[(size_t)(b * 40 + j) * 32 + lane];
        float p = xv.x * wg.x + xv.y * wg.y + xv.z * wg.z + xv.w * wg.w;
#pragma unroll
        for (int off = 16; off; off >>= 1) p += __shfl_xor_sync(0xffffffffu, p, off);
        if (lane == 0) gate[j] = p + bg[0];
    }
    __syncthreads();
    if (tid == 0) {
        float m = gate[0];
        for (int j = 1; j < 40; j++) m = fmaxf(m, gate[j]);
        float s = 0.f;
        for (int j = 0; j < 40; j++) s += __expf(gate[j] - m);
        ms[0] = m; ms[1] = s;
    }
    __syncthreads();
    if (tid < 40) alpha[tid] = __expf(gate[tid] - ms[0]) / (ms[1] + 1e-16f);
    __syncthreads();
    float f = 0.f;
    for (int j = 0; j < 40; j++)
        f += alpha[j] * g_fs[(size_t)(b * 40 + j) * E_ + tid];
    float hh = g_hn[(size_t)b * E_ + tid];
    float dt = f * hh, na = f * f, nb = hh * hh;
#pragma unroll
    for (int off = 16; off; off >>= 1) {
        dt += __shfl_xor_sync(0xffffffffu, dt, off);
        na += __shfl_xor_sync(0xffffffffu, na, off);
        nb += __shfl_xor_sync(0xffffffffu, nb, off);
    }
    if (lane == 0) { red[0][warp] = dt; red[1][warp] = na; red[2][warp] = nb; }
    __syncthreads();
    if (tid == 0) {
        float d = red[0][0] + red[0][1] + red[0][2] + red[0][3];
        float a = red[1][0] + red[1][1] + red[1][2] + red[1][3];
        float c = red[2][0] + red[2][1] + red[2][2] + red[2][3];
        out[b] = d / (fmaxf(sqrtf(a), 1e-8f) * fmaxf(sqrtf(c), 1e-8f));
    }
}

// ---------------- launch (stream DAG inside graph capture) ----------------
extern "C" void kernel_launch(void* const* d_in, const int* in_sizes, int n_in,
                              void* d_out, int out_size) {
    const int* desc_tokens = (const int*)d_in[0];
    const int* x_tokens    = (const int*)d_in[1];
    const int* mini_tokens = (const int*)d_in[2];
    const int* src         = (const int*)d_in[3];
    const int* dst         = (const int*)d_in[4];
    const int* mini_src    = (const int*)d_in[5];
    const int* mini_dst    = (const int*)d_in[6];
    const float* desc_table  = (const float*)d_in[9];
    const float* code_table  = (const float*)d_in[10];
    const float* code_table2 = (const float*)d_in[11];
    const float* Wq = (const float*)d_in[12]; const float* bq = (const float*)d_in[13];
    const float* Wk = (const float*)d_in[14]; const float* bk = (const float*)d_in[15];
    const float* Wv = (const float*)d_in[16]; const float* bv = (const float*)d_in[17];
    const float* Wskip = (const float*)d_in[18]; const float* bskip = (const float*)d_in[19];
    const float* W2 = (const float*)d_in[20]; const float* b2 = (const float*)d_in[21];
    const float* W3 = (const float*)d_in[22]; const float* b3 = (const float*)d_in[23];
    const float* Wg = (const float*)d_in[24]; const float* bg = (const float*)d_in[25];
    float* out = (float*)d_out;

    float *p_q, *p_k, *p_v, *p_hidden, *p_hn, *p_stmt, *p_xw1, *p_xw2, *p_fs;
    cudaGetSymbolAddress((void**)&p_q, g_q);
    cudaGetSymbolAddress((void**)&p_k, g_k);
    cudaGetSymbolAddress((void**)&p_v, g_v);
    cudaGetSymbolAddress((void**)&p_hidden, g_hidden);
    cudaGetSymbolAddress((void**)&p_hn, g_hn);
    cudaGetSymbolAddress((void**)&p_stmt, g_stmt);
    cudaGetSymbolAddress((void**)&p_xw1, g_xw1);
    cudaGetSymbolAddress((void**)&p_xw2, g_xw2);
    cudaGetSymbolAddress((void**)&p_fs, g_fs);

    __half *p_ct_h, *p_mini_h, *p_mfn_h, *p_gc1_h, *p_w2t, *p_w3t;
    cudaGetSymbolAddress((void**)&p_ct_h, g_ct_h);
    cudaGetSymbolAddress((void**)&p_mini_h, g_mini_h);
    cudaGetSymbolAddress((void**)&p_mfn_h, g_mfn_h);
    cudaGetSymbolAddress((void**)&p_gc1_h, g_gc1_h);
    cudaGetSymbolAddress((void**)&p_w2t, g_w2t);
    cudaGetSymbolAddress((void**)&p_w3t, g_w3t);

    int *p_deg_m, *p_off_m, *p_pos_m, *p_csr_m, *p_bsum_m;
    int *p_deg_o, *p_off_o, *p_pos_o, *p_csr_o, *p_bsum_o;
    cudaGetSymbolAddress((void**)&p_deg_m, g_deg_m);
    cudaGetSymbolAddress((void**)&p_off_m, g_off_m);
    cudaGetSymbolAddress((void**)&p_pos_m, g_pos_m);
    cudaGetSymbolAddress((void**)&p_csr_m, g_csr_m);
    cudaGetSymbolAddress((void**)&p_bsum_m, g_bsum_m);
    cudaGetSymbolAddress((void**)&p_deg_o, g_deg_o);
    cudaGetSymbolAddress((void**)&p_off_o, g_off_o);
    cudaGetSymbolAddress((void**)&p_pos_o, g_pos_o);
    cudaGetSymbolAddress((void**)&p_csr_o, g_csr_o);
    cudaGetSymbolAddress((void**)&p_bsum_o, g_bsum_o);

    cudaFuncSetAttribute(f16_gemm_qkvs, cudaFuncAttributeMaxDynamicSharedMemorySize, GEMM_SMEM);
    cudaFuncSetAttribute(f16_gemm, cudaFuncAttributeMaxDynamicSharedMemorySize, GEMM_SMEM);

    static cudaStream_t s1 = nullptr, s2 = nullptr;
    static cudaEvent_t e_root = nullptr, e_csrm = nullptr, e_csro = nullptr,
                       e_ws = nullptr, e_emb2 = nullptr;
    if (!s1) {
        cudaStreamCreateWithFlags(&s1, cudaStreamNonBlocking);
        cudaStreamCreateWithFlags(&s2, cudaStreamNonBlocking);
        cudaEventCreateWithFlags(&e_root, cudaEventDisableTiming);
        cudaEventCreateWithFlags(&e_csrm, cudaEventDisableTiming);
        cudaEventCreateWithFlags(&e_csro, cudaEventDisableTiming);
        cudaEventCreateWithFlags(&e_ws, cudaEventDisableTiming);
        cudaEventCreateWithFlags(&e_emb2, cudaEventDisableTiming);
    }

    cudaEventRecord(e_root, 0);
    cudaStreamWaitEvent(s1, e_root, 0);
    cudaStreamWaitEvent(s2, e_root, 0);

    // ---- s1: CSR builds ----
    zero_deg_kernel<<<(NM_ + 255) / 256, 256, 0, s1>>>();
    count_kernel<<<(EM_ + 255) / 256, 256, 0, s1>>>(mini_dst, p_deg_m, EM_);
    count_kernel<<<(EO_ + 255) / 256, 256, 0, s1>>>(dst, p_deg_o, EO_);
    scan_local_kernel<<<NM_ / 1024, 256, 0, s1>>>(p_deg_m, p_off_m, p_bsum_m);
    scan_bsums_kernel<<<1, 128, 0, s1>>>(p_bsum_m, NM_ / 1024, p_off_m, NM_);
    scan_add_kernel<<<NM_ / 256, 256, 0, s1>>>(p_off_m, p_pos_m, p_bsum_m, NM_);
    scatter_kernel<<<(EM_ + 255) / 256, 256, 0, s1>>>(mini_src, mini_dst, p_pos_m, p_csr_m, EM_);
    cudaEventRecord(e_csrm, s1);
    scan_local_kernel<<<NO_ / 1024, 256, 0, s1>>>(p_deg_o, p_off_o, p_bsum_o);
    scan_bsums_kernel<<<1, 128, 0, s1>>>(p_bsum_o, NO_ / 1024, p_off_o, NO_);
    scan_add_kernel<<<NO_ / 256, 256, 0, s1>>>(p_off_o, p_pos_o, p_bsum_o, NO_);
    dinv_kernel<<<(NO_ + 255) / 256, 256, 0, s1>>>();
    scatter_kernel<<<(EO_ + 255) / 256, 256, 0, s1>>>(src, dst, p_pos_o, p_csr_o, EO_);
    cudaEventRecord(e_csro, s1);

    // ---- s2: weight transposes + secondary embeddings ----
    {
        dim3 g((E_ * E_ + 255) / 256, 4);
        wsplit4_kernel<<<g, 256, 0, s2>>>(Wq, Wk, Wv, Wskip);
    }
    wsplit_kernel<<<(E_ * HID_ + 255) / 256, 256, 0, s2>>>(W2, p_w2t, E_, HID_);
    wsplit_kernel<<<(HID_ * E_ + 255) / 256, 256, 0, s2>>>(W3, p_w3t, HID_, E_);
    cudaEventRecord(e_ws, s2);
    masked_mean4_kernel<<<NO_ / 4, 128, 0, s2>>>(x_tokens, code_table2, p_stmt, LO_);
    masked_mean4_kernel<<<B_ / 4, 128, 0, s2>>>(desc_tokens, desc_table, p_hn, LD_);
    cudaEventRecord(e_emb2, s2);

    // ---- main stream: critical path ----
    table2h_kernel<<<(V_ * E_ / 2 + 255) / 256, 256>>>(code_table, p_ct_h, V_ * E_ / 2);
    masked_mean4_f16_kernel<<<NM_ / 4, 128>>>(mini_tokens, p_ct_h, p_mini_h);

    cudaStreamWaitEvent(0, e_ws, 0);
    {
        dim3 grid(NM_ / 128, 4);
        f16_gemm_qkvs<<<grid, 256, GEMM_SMEM>>>(p_mini_h,
                                                bq, p_q, bk, p_k, bv, p_v, bskip, p_hidden);
    }

    cudaStreamWaitEvent(0, e_csrm, 0);
    cudaStreamWaitEvent(0, e_emb2, 0);
    attn_gattn8_kernel<<<NO_, 256>>>(Wg, bg);

    {
        dim3 grid(NO_ / 128, HID_ / 128);
        f16_gemm<<<grid, 256, GEMM_SMEM>>>(p_mfn_h, p_w2t, p_xw1, E_, HID_);
    }
    cudaStreamWaitEvent(0, e_csro, 0);
    gcn_gather_f16_kernel<<<NO_ / 8, 256>>>(p_xw1, b2, p_gc1_h, HID_ / 4);

    {
        dim3 grid(NO_ / 128, E_ / 128);
        f16_gemm<<<grid, 256, GEMM_SMEM>>>(p_gc1_h, p_w3t, p_xw2, HID_, E_);
    }
    gcn_gather_kernel<<<NO_ / 8, 256>>>(p_xw2, b3, p_fs, E_ / 4);

    gattn40_cos_kernel<<<B_, E_>>>(Wg, bg, out);
    (void)in_sizes; (void)n_in; (void)out_size;
}